// round 1
// baseline (speedup 1.0000x reference)
#include <cuda_runtime.h>
#include <math.h>

// ---------------- problem constants ----------------
#define Bn   32
#define Cn   256
#define Hn   28
#define Wn   28
#define Pn   784          // H*W
#define NKn  196          // (H/2)*(W/2)
#define HKn  14
#define CMn  1024         // C * R
#define NH   8
#define DKn  32
#define EPSf 1e-5f

// ---------------- scratch (device globals: allocation-free) ----------------
__device__ float g_x1 [Bn*Cn*Pn];    // after LPU
__device__ float g_lnb[Bn*Cn*Pn];    // layernorm output (reused for ln1 and ln2)
__device__ float g_q  [Bn*Pn*Cn];    // [b, n, 256]
__device__ float g_kv [Bn*Cn*NKn];   // stride-2 dw conv output [b, c, 196]
__device__ float g_k  [Bn*NKn*Cn];   // [b, nk, 256]
__device__ float g_v  [Bn*NKn*Cn];
__device__ float g_tmp[Bn*Pn*Cn];    // attention output [b, n, 256]
__device__ float g_x2 [Bn*Cn*Pn];    // after attention residual (flat reinterpret)
__device__ float g_t1 [Bn*CMn*Pn];   // IRFFN expand
__device__ float g_t2 [Bn*CMn*Pn];   // after dw2

__device__ __forceinline__ float gelu_f(float v) {
    return 0.5f * v * (1.0f + erff(v * 0.7071067811865475f));
}

// ---------------- LPU: depthwise 3x3 pad1 + bias + residual ----------------
__global__ void k_lpu(const float* __restrict__ x, const float* __restrict__ w,
                      const float* __restrict__ bias, float* __restrict__ out) {
    int idx = blockIdx.x * blockDim.x + threadIdx.x;
    if (idx >= Bn * Cn * Pn) return;
    int p  = idx % Pn;
    int bc = idx / Pn;
    int c  = bc % Cn;
    int py = p / Wn, px = p % Wn;
    const float* xin = x + (size_t)bc * Pn;
    const float* wc  = w + c * 9;
    float acc = bias[c];
#pragma unroll
    for (int i = 0; i < 3; i++)
#pragma unroll
        for (int j = 0; j < 3; j++) {
            int yy = py + i - 1, xx = px + j - 1;
            if (yy >= 0 && yy < Hn && xx >= 0 && xx < Wn)
                acc += wc[i * 3 + j] * xin[yy * Wn + xx];
        }
    out[idx] = acc + xin[p];
}

// ---------------- per-sample LayerNorm over C*H*W ----------------
__global__ void k_ln(const float* __restrict__ src, float* __restrict__ dst) {
    int b = blockIdx.x;
    const float* s = src + (size_t)b * Cn * Pn;
    float*       d = dst + (size_t)b * Cn * Pn;
    const int n = Cn * Pn;
    float sum = 0.f, sq = 0.f;
    for (int i = threadIdx.x; i < n; i += blockDim.x) {
        float v = s[i];
        sum += v; sq += v * v;
    }
    __shared__ float r1[1024], r2[1024];
    r1[threadIdx.x] = sum; r2[threadIdx.x] = sq;
    __syncthreads();
    for (int st = blockDim.x / 2; st > 0; st >>= 1) {
        if (threadIdx.x < st) {
            r1[threadIdx.x] += r1[threadIdx.x + st];
            r2[threadIdx.x] += r2[threadIdx.x + st];
        }
        __syncthreads();
    }
    __shared__ float mean_s, rstd_s;
    if (threadIdx.x == 0) {
        float m  = r1[0] / (float)n;
        float vv = r2[0] / (float)n - m * m;
        mean_s = m;
        rstd_s = rsqrtf(vv + EPSf);
    }
    __syncthreads();
    float m = mean_s, r = rstd_s;
    for (int i = threadIdx.x; i < n; i += blockDim.x)
        d[i] = (s[i] - m) * r;
}

// ---------------- KV downsample: depthwise 2x2 stride2 pad0 ----------------
__global__ void k_kvconv(const float* __restrict__ x, const float* __restrict__ w,
                         const float* __restrict__ bias, float* __restrict__ out) {
    int idx = blockIdx.x * blockDim.x + threadIdx.x;
    if (idx >= Bn * Cn * NKn) return;
    int p  = idx % NKn;
    int bc = idx / NKn;
    int c  = bc % Cn;
    int oy = p / HKn, ox = p % HKn;
    const float* xin = x + (size_t)bc * Pn;
    const float* wc  = w + c * 4;
    float acc = bias[c];
#pragma unroll
    for (int i = 0; i < 2; i++)
#pragma unroll
        for (int j = 0; j < 2; j++)
            acc += wc[i * 2 + j] * xin[(2 * oy + i) * Wn + (2 * ox + j)];
    out[idx] = acc;
}

// ------- GEMM variant A: out[b,p,oc] = sum_c X[b,c,p] * W[oc,c] + bias[oc] -------
// (Q/K/V projections; X is channel-major [C, Ppts])
__global__ void k_gemm_proj(const float* __restrict__ X, const float* __restrict__ Wt,
                            const float* __restrict__ bias, float* __restrict__ out,
                            int Ppts, int Cin, int OC) {
    const int BM = 64, BN = 64, BK = 8;
    __shared__ float As[BK][BM];
    __shared__ float Bs[BK][BN + 1];
    int b   = blockIdx.z;
    int p0  = blockIdx.y * BM;
    int oc0 = blockIdx.x * BN;
    const float* Xb = X + (size_t)b * Cin * Ppts;
    int tid = threadIdx.x;
    int tx = tid & 15, ty = tid >> 4;
    float acc[4][4] = {};
    for (int c0 = 0; c0 < Cin; c0 += BK) {
        for (int l = tid; l < BK * BM; l += 256) {
            int k = l / BM, m = l % BM;
            int p = p0 + m;
            As[k][m] = (p < Ppts) ? Xb[(size_t)(c0 + k) * Ppts + p] : 0.f;
        }
        for (int l = tid; l < BK * BN; l += 256) {
            int n = l / BK, k = l % BK;
            Bs[k][n] = Wt[(size_t)(oc0 + n) * Cin + c0 + k];
        }
        __syncthreads();
#pragma unroll
        for (int k = 0; k < BK; k++) {
            float a[4], bb[4];
#pragma unroll
            for (int i = 0; i < 4; i++) a[i]  = As[k][ty * 4 + i];
#pragma unroll
            for (int j = 0; j < 4; j++) bb[j] = Bs[k][tx * 4 + j];
#pragma unroll
            for (int i = 0; i < 4; i++)
#pragma unroll
                for (int j = 0; j < 4; j++) acc[i][j] += a[i] * bb[j];
        }
        __syncthreads();
    }
#pragma unroll
    for (int i = 0; i < 4; i++) {
        int p = p0 + ty * 4 + i;
        if (p >= Ppts) continue;
#pragma unroll
        for (int j = 0; j < 4; j++) {
            int oc = oc0 + tx * 4 + j;
            out[((size_t)b * Ppts + p) * OC + oc] = acc[i][j] + bias[oc];
        }
    }
}

// ------- GEMM variant B: out[b,p,oc] = sum_d T[b,p,d]*W[oc,d] + bias + res -------
// (O-projection; residual fused at the SAME flat offset = the reference's raw
//  reshape(b,c,h,w) reinterpret of a contiguous [b,N,C] tensor)
__global__ void k_gemm_rowA(const float* __restrict__ T, const float* __restrict__ Wt,
                            const float* __restrict__ bias, const float* __restrict__ res,
                            float* __restrict__ out, int Ppts, int Din, int OC) {
    const int BM = 64, BN = 64, BK = 8;
    __shared__ float As[BK][BM + 1];
    __shared__ float Bs[BK][BN + 1];
    int b   = blockIdx.z;
    int p0  = blockIdx.y * BM;
    int oc0 = blockIdx.x * BN;
    const float* Tb = T + (size_t)b * Ppts * Din;
    int tid = threadIdx.x;
    int tx = tid & 15, ty = tid >> 4;
    float acc[4][4] = {};
    for (int c0 = 0; c0 < Din; c0 += BK) {
        for (int l = tid; l < BK * BM; l += 256) {
            int m = l / BK, k = l % BK;
            int p = p0 + m;
            As[k][m] = (p < Ppts) ? Tb[(size_t)p * Din + c0 + k] : 0.f;
        }
        for (int l = tid; l < BK * BN; l += 256) {
            int n = l / BK, k = l % BK;
            Bs[k][n] = Wt[(size_t)(oc0 + n) * Din + c0 + k];
        }
        __syncthreads();
#pragma unroll
        for (int k = 0; k < BK; k++) {
            float a[4], bb[4];
#pragma unroll
            for (int i = 0; i < 4; i++) a[i]  = As[k][ty * 4 + i];
#pragma unroll
            for (int j = 0; j < 4; j++) bb[j] = Bs[k][tx * 4 + j];
#pragma unroll
            for (int i = 0; i < 4; i++)
#pragma unroll
                for (int j = 0; j < 4; j++) acc[i][j] += a[i] * bb[j];
        }
        __syncthreads();
    }
#pragma unroll
    for (int i = 0; i < 4; i++) {
        int p = p0 + ty * 4 + i;
        if (p >= Ppts) continue;
#pragma unroll
        for (int j = 0; j < 4; j++) {
            int oc = oc0 + tx * 4 + j;
            size_t off = ((size_t)b * Ppts + p) * OC + oc;
            out[off] = acc[i][j] + bias[oc] + res[off];
        }
    }
}

// ------- GEMM variant C: out[b,m,p] = BN(sum_c W[m,c]*X[b,c,p] + cb[m]) (+GELU)(+res) -------
// (IRFFN 1x1 convs, channel-major output)
template <bool DO_GELU, bool DO_RES>
__global__ void k_gemm_conv(const float* __restrict__ X, const float* __restrict__ Wt,
                            const float* __restrict__ cb,
                            const float* __restrict__ bng, const float* __restrict__ bnb,
                            const float* __restrict__ bnm, const float* __restrict__ bnv,
                            const float* __restrict__ res, float* __restrict__ out,
                            int M, int Cin, int Ppts) {
    const int BM = 64, BN = 64, BK = 8;
    __shared__ float As[BK][BM + 1];   // weights
    __shared__ float Bs[BK][BN];       // activations
    int b  = blockIdx.z;
    int m0 = blockIdx.y * BM;
    int p0 = blockIdx.x * BN;
    const float* Xb = X + (size_t)b * Cin * Ppts;
    int tid = threadIdx.x;
    int tx = tid & 15, ty = tid >> 4;
    float acc[4][4] = {};
    for (int c0 = 0; c0 < Cin; c0 += BK) {
        for (int l = tid; l < BK * BM; l += 256) {
            int mm = l / BK, k = l % BK;
            As[k][mm] = Wt[(size_t)(m0 + mm) * Cin + c0 + k];
        }
        for (int l = tid; l < BK * BN; l += 256) {
            int k = l / BN, pp = l % BN;
            int p = p0 + pp;
            Bs[k][pp] = (p < Ppts) ? Xb[(size_t)(c0 + k) * Ppts + p] : 0.f;
        }
        __syncthreads();
#pragma unroll
        for (int k = 0; k < BK; k++) {
            float a[4], bb[4];
#pragma unroll
            for (int i = 0; i < 4; i++) a[i]  = As[k][ty * 4 + i];
#pragma unroll
            for (int j = 0; j < 4; j++) bb[j] = Bs[k][tx * 4 + j];
#pragma unroll
            for (int i = 0; i < 4; i++)
#pragma unroll
                for (int j = 0; j < 4; j++) acc[i][j] += a[i] * bb[j];
        }
        __syncthreads();
    }
#pragma unroll
    for (int i = 0; i < 4; i++) {
        int m = m0 + ty * 4 + i;
        float scale = bng[m] * rsqrtf(bnv[m] + EPSf);
        float shift = bnb[m] - bnm[m] * scale;
        float cbm   = cb[m];
#pragma unroll
        for (int j = 0; j < 4; j++) {
            int p = p0 + tx * 4 + j;
            if (p >= Ppts) continue;
            float y = (acc[i][j] + cbm) * scale + shift;
            if (DO_GELU) y = gelu_f(y);
            size_t off = ((size_t)b * M + m) * Ppts + p;
            if (DO_RES) y += res[off];
            out[off] = y;
        }
    }
}

// ---------------- IRFFN depthwise 3x3 + BN + GELU ----------------
__global__ void k_dw2(const float* __restrict__ t1, const float* __restrict__ w,
                      const float* __restrict__ bias,
                      const float* __restrict__ bng, const float* __restrict__ bnb,
                      const float* __restrict__ bnm, const float* __restrict__ bnv,
                      float* __restrict__ out) {
    int idx = blockIdx.x * blockDim.x + threadIdx.x;
    if (idx >= Bn * CMn * Pn) return;
    int p  = idx % Pn;
    int bm = idx / Pn;
    int m  = bm % CMn;
    int py = p / Wn, px = p % Wn;
    const float* xin = t1 + (size_t)bm * Pn;
    const float* wc  = w + m * 9;
    float acc = bias[m];
#pragma unroll
    for (int i = 0; i < 3; i++)
#pragma unroll
        for (int j = 0; j < 3; j++) {
            int yy = py + i - 1, xx = px + j - 1;
            if (yy >= 0 && yy < Hn && xx >= 0 && xx < Wn)
                acc += wc[i * 3 + j] * xin[yy * Wn + xx];
        }
    float scale = bng[m] * rsqrtf(bnv[m] + EPSf);
    float y = (acc - bnm[m]) * scale + bnb[m];
    out[idx] = gelu_f(y);
}

// ---------------- fused attention (online softmax), block = (b, head) ----------------
__global__ void k_attn(const float* __restrict__ q, const float* __restrict__ k,
                       const float* __restrict__ v, const float* __restrict__ pos,
                       float* __restrict__ out) {
    extern __shared__ float sm[];
    float* Ks = sm;                 // [NK][DK]
    float* Vs = sm + NKn * DKn;     // [NK][DK]
    int b = blockIdx.x / NH;
    int h = blockIdx.x % NH;
    const float* kb = k + (size_t)b * NKn * Cn + h * DKn;
    const float* vb = v + (size_t)b * NKn * Cn + h * DKn;
    for (int l = threadIdx.x; l < NKn * DKn; l += blockDim.x) {
        int j = l / DKn, d = l % DKn;
        Ks[j * DKn + d] = kb[(size_t)j * Cn + d];
        Vs[j * DKn + d] = vb[(size_t)j * Cn + d];
    }
    __syncthreads();
    const float scale = 0.17677669529663687f;  // 32^-0.5
    for (int i = threadIdx.x; i < Pn; i += blockDim.x) {
        float qr[DKn];
        const float* qp = q + ((size_t)b * Pn + i) * Cn + h * DKn;
#pragma unroll
        for (int d = 0; d < DKn; d++) qr[d] = qp[d];
        const float* pb = pos + ((size_t)h * Pn + i) * NKn;
        float mmax = -1e30f, lsum = 0.f;
        float o[DKn];
#pragma unroll
        for (int d = 0; d < DKn; d++) o[d] = 0.f;
        for (int j = 0; j < NKn; j++) {
            const float* kj = Ks + j * DKn;
            float s0 = 0.f, s1 = 0.f, s2 = 0.f, s3 = 0.f;
#pragma unroll
            for (int d = 0; d < DKn; d += 4) {
                s0 += qr[d + 0] * kj[d + 0];
                s1 += qr[d + 1] * kj[d + 1];
                s2 += qr[d + 2] * kj[d + 2];
                s3 += qr[d + 3] * kj[d + 3];
            }
            float s = (s0 + s1) + (s2 + s3);
            s = s * scale + pb[j];
            if (s > mmax) {
                float corr = __expf(mmax - s);
                lsum *= corr;
#pragma unroll
                for (int d = 0; d < DKn; d++) o[d] *= corr;
                mmax = s;
            }
            float e = __expf(s - mmax);
            lsum += e;
            const float* vj = Vs + j * DKn;
#pragma unroll
            for (int d = 0; d < DKn; d++) o[d] += e * vj[d];
        }
        float inv = 1.f / lsum;
        float* op = out + ((size_t)b * Pn + i) * Cn + h * DKn;
#pragma unroll
        for (int d = 0; d < DKn; d++) op[d] = o[d] * inv;
    }
}

// ---------------- host launch ----------------
static float* sym_addr(const void* symbol) {
    void* p = nullptr;
    cudaGetSymbolAddress(&p, symbol);
    return (float*)p;
}

extern "C" void kernel_launch(void* const* d_in, const int* in_sizes, int n_in,
                              void* d_out, int out_size) {
    const float* x     = (const float*)d_in[0];
    const float* lpu_w = (const float*)d_in[1];
    const float* lpu_b = (const float*)d_in[2];
    const float* dw_w  = (const float*)d_in[3];
    const float* dw_b  = (const float*)d_in[4];
    const float* wq    = (const float*)d_in[5];
    const float* bq    = (const float*)d_in[6];
    const float* wk    = (const float*)d_in[7];
    const float* bk    = (const float*)d_in[8];
    const float* wv    = (const float*)d_in[9];
    const float* bv    = (const float*)d_in[10];
    const float* wo    = (const float*)d_in[11];
    const float* bo    = (const float*)d_in[12];
    const float* pos_b = (const float*)d_in[13];
    const float* c1_w  = (const float*)d_in[14];
    const float* c1_b  = (const float*)d_in[15];
    const float* bn1_g = (const float*)d_in[16];
    const float* bn1_b = (const float*)d_in[17];
    const float* bn1_m = (const float*)d_in[18];
    const float* bn1_v = (const float*)d_in[19];
    const float* dw2_w = (const float*)d_in[20];
    const float* dw2_b = (const float*)d_in[21];
    const float* bn2_g = (const float*)d_in[22];
    const float* bn2_b = (const float*)d_in[23];
    const float* bn2_m = (const float*)d_in[24];
    const float* bn2_v = (const float*)d_in[25];
    const float* c2_w  = (const float*)d_in[26];
    const float* c2_b  = (const float*)d_in[27];
    const float* bn3_g = (const float*)d_in[28];
    const float* bn3_b = (const float*)d_in[29];
    const float* bn3_m = (const float*)d_in[30];
    const float* bn3_v = (const float*)d_in[31];
    float* out = (float*)d_out;

    float* x1  = sym_addr(g_x1);
    float* lnb = sym_addr(g_lnb);
    float* qb  = sym_addr(g_q);
    float* kvb = sym_addr(g_kv);
    float* kb  = sym_addr(g_k);
    float* vb  = sym_addr(g_v);
    float* tmp = sym_addr(g_tmp);
    float* x2  = sym_addr(g_x2);
    float* t1  = sym_addr(g_t1);
    float* t2  = sym_addr(g_t2);

    // 1. LPU
    k_lpu<<<(Bn * Cn * Pn + 255) / 256, 256>>>(x, lpu_w, lpu_b, x1);
    // 2. LN1
    k_ln<<<Bn, 1024>>>(x1, lnb);
    // 3. KV downsample (on pre-LN x1, per reference)
    k_kvconv<<<(Bn * Cn * NKn + 255) / 256, 256>>>(x1, dw_w, dw_b, kvb);
    // 4-6. Q, K, V projections
    {
        dim3 gq(Cn / 64, (Pn + 63) / 64, Bn);
        k_gemm_proj<<<gq, 256>>>(lnb, wq, bq, qb, Pn, Cn, Cn);
        dim3 gk(Cn / 64, (NKn + 63) / 64, Bn);
        k_gemm_proj<<<gk, 256>>>(kvb, wk, bk, kb, NKn, Cn, Cn);
        k_gemm_proj<<<gk, 256>>>(kvb, wv, bv, vb, NKn, Cn, Cn);
    }
    // 7. fused attention
    {
        int smem = 2 * NKn * DKn * (int)sizeof(float);  // 50176 B
        cudaFuncSetAttribute(k_attn, cudaFuncAttributeMaxDynamicSharedMemorySize, smem);
        k_attn<<<Bn * NH, 256, smem>>>(qb, kb, vb, pos_b, tmp);
    }
    // 8. O projection + residual (flat-reinterpret add)
    {
        dim3 go(Cn / 64, (Pn + 63) / 64, Bn);
        k_gemm_rowA<<<go, 256>>>(tmp, wo, bo, x1, x2, Pn, Cn, Cn);
    }
    // 9. LN2
    k_ln<<<Bn, 1024>>>(x2, lnb);
    // 10. c1 + BN1 + GELU
    {
        dim3 g1((Pn + 63) / 64, CMn / 64, Bn);
        k_gemm_conv<true, false><<<g1, 256>>>(lnb, c1_w, c1_b, bn1_g, bn1_b, bn1_m, bn1_v,
                                              nullptr, t1, CMn, Cn, Pn);
    }
    // 11. dw2 + BN2 + GELU
    k_dw2<<<(Bn * CMn * Pn + 255) / 256, 256>>>(t1, dw2_w, dw2_b, bn2_g, bn2_b, bn2_m, bn2_v, t2);
    // 12. c2 + BN3 + residual -> d_out
    {
        dim3 g2((Pn + 63) / 64, Cn / 64, Bn);
        k_gemm_conv<false, true><<<g2, 256>>>(t2, c2_w, c2_b, bn3_g, bn3_b, bn3_m, bn3_v,
                                              x2, out, Cn, CMn, Pn);
    }
}

// round 2
// speedup vs baseline: 1.5252x; 1.5252x over previous
#include <cuda_runtime.h>
#include <math.h>

// ---------------- problem constants ----------------
#define Bn   32
#define Cn   256
#define Hn   28
#define Wn   28
#define Pn   784          // H*W
#define NKn  196          // (H/2)*(W/2)
#define HKn  14
#define CMn  1024         // C * R
#define NH   8
#define DKn  32
#define EPSf 1e-5f

// ---------------- scratch (device globals: allocation-free) ----------------
__device__ float g_x1  [Bn*Cn*Pn];     // after LPU (channel-major)
__device__ float g_q   [Bn*Pn*Cn];     // [b, n, 256] row-major
__device__ float g_kv  [Bn*Cn*NKn];    // stride-2 dw conv output [b, c, 196]
__device__ float g_k   [Bn*NKn*Cn];    // [b, nk, 256]
__device__ float g_v   [Bn*NKn*Cn];
__device__ float g_tmpT[Bn*Cn*Pn];     // attention output CHANNEL-major [b, d, n]
__device__ float g_x2  [Bn*Cn*Pn];     // after attention residual (flat)
__device__ float g_t1  [Bn*CMn*Pn];    // IRFFN expand (channel-major)
__device__ float g_t2  [Bn*CMn*Pn];    // after dw2
__device__ float g_wqT [Cn*Cn];
__device__ float g_wkT [Cn*Cn];
__device__ float g_wvT [Cn*Cn];
__device__ float g_woT [Cn*Cn];
__device__ float g_c1T [Cn*CMn];
__device__ float g_c2T [CMn*Cn];
__device__ float g_posT[NH*NKn*Pn];    // pos transposed [h][j][i]
__device__ float2 g_part[Bn*8];
__device__ float2 g_mr  [Bn];          // (mean, rstd) per sample

__device__ __forceinline__ float gelu_f(float v) {
    return 0.5f * v * (1.0f + erff(v * 0.7071067811865475f));
}

// ---------------- generic tiled transpose: in[R][C] -> out[C][R], batched z ----------------
__global__ void k_transp(const float* __restrict__ in, float* __restrict__ out,
                         int R, int C) {
    __shared__ float t[32][33];
    size_t boff = (size_t)blockIdx.z * R * C;
    in  += boff;
    out += boff;
    int c0 = blockIdx.x * 32, r0 = blockIdx.y * 32;
#pragma unroll
    for (int q = 0; q < 32; q += 8) {
        int r = r0 + threadIdx.y + q, c = c0 + threadIdx.x;
        if (r < R && c < C) t[threadIdx.y + q][threadIdx.x] = in[(size_t)r * C + c];
    }
    __syncthreads();
#pragma unroll
    for (int q = 0; q < 32; q += 8) {
        int c = c0 + threadIdx.y + q, r = r0 + threadIdx.x;
        if (r < R && c < C) out[(size_t)c * R + r] = t[threadIdx.x][threadIdx.y + q];
    }
}

// ---------------- depthwise 3x3 pad1, one (b,ch) plane per block ----------------
// MODE 0: LPU  -> out = conv + bias + input (residual)
// MODE 1: dw2  -> out = gelu(BN(conv + bias))
template <int MODE>
__global__ void __launch_bounds__(256) k_dwplane(
    const float* __restrict__ X, const float* __restrict__ w,
    const float* __restrict__ bias,
    const float* __restrict__ bng, const float* __restrict__ bnb,
    const float* __restrict__ bnm, const float* __restrict__ bnv,
    float* __restrict__ out, int CH) {
    __shared__ float sp[Pn];
    int bc = blockIdx.x;
    int c  = bc % CH;
    const float* xin = X + (size_t)bc * Pn;
    for (int i = threadIdx.x; i < Pn; i += 256) sp[i] = xin[i];
    float wc[9];
#pragma unroll
    for (int i = 0; i < 9; i++) wc[i] = w[c * 9 + i];
    float bsv = bias[c];
    float scale = 0.f, shift = 0.f;
    if (MODE == 1) {
        scale = bng[c] * rsqrtf(bnv[c] + EPSf);
        shift = bnb[c] - bnm[c] * scale;
    }
    __syncthreads();
    for (int p = threadIdx.x; p < Pn; p += 256) {
        int py = p / Wn, px = p % Wn;
        float acc = bsv;
#pragma unroll
        for (int i = 0; i < 3; i++)
#pragma unroll
            for (int j = 0; j < 3; j++) {
                int yy = py + i - 1, xx = px + j - 1;
                if (yy >= 0 && yy < Hn && xx >= 0 && xx < Wn)
                    acc += wc[i * 3 + j] * sp[yy * Wn + xx];
            }
        float y;
        if (MODE == 0) y = acc + sp[p];
        else           y = gelu_f(acc * scale + shift);
        out[(size_t)bc * Pn + p] = y;
    }
}

// ---------------- LN stats: partial sums then finalize ----------------
__global__ void k_stats_part(const float* __restrict__ src, float2* __restrict__ part) {
    int b = blockIdx.x, ch = blockIdx.y;
    const float4* s = (const float4*)(src + (size_t)b * Cn * Pn + (size_t)ch * (Cn * Pn / 8));
    const int nv = (Cn * Pn / 8) / 4;  // 6272
    float sum = 0.f, sq = 0.f;
    for (int i = threadIdx.x; i < nv; i += 256) {
        float4 v = s[i];
        sum += v.x + v.y + v.z + v.w;
        sq  += v.x * v.x + v.y * v.y + v.z * v.z + v.w * v.w;
    }
    __shared__ float r1[256], r2[256];
    r1[threadIdx.x] = sum; r2[threadIdx.x] = sq;
    __syncthreads();
    for (int st = 128; st > 0; st >>= 1) {
        if (threadIdx.x < st) {
            r1[threadIdx.x] += r1[threadIdx.x + st];
            r2[threadIdx.x] += r2[threadIdx.x + st];
        }
        __syncthreads();
    }
    if (threadIdx.x == 0) part[b * 8 + ch] = make_float2(r1[0], r2[0]);
}

__global__ void k_stats_fin(const float2* __restrict__ part, float2* __restrict__ mr) {
    int t = threadIdx.x;  // 256 threads = 32 b * 8 chunks
    float2 p = part[t];
#pragma unroll
    for (int o = 4; o >= 1; o >>= 1) {
        p.x += __shfl_down_sync(0xffffffffu, p.x, o, 8);
        p.y += __shfl_down_sync(0xffffffffu, p.y, o, 8);
    }
    if ((t & 7) == 0) {
        const float n = (float)(Cn * Pn);
        float m  = p.x / n;
        float vv = p.y / n - m * m;
        mr[t >> 3] = make_float2(m, rsqrtf(vv + EPSf));
    }
}

// ---------------- KV downsample: depthwise 2x2 stride2 pad0 ----------------
__global__ void k_kvconv(const float* __restrict__ x, const float* __restrict__ w,
                         const float* __restrict__ bias, float* __restrict__ out) {
    int idx = blockIdx.x * blockDim.x + threadIdx.x;
    if (idx >= Bn * Cn * NKn) return;
    int p  = idx % NKn;
    int bc = idx / NKn;
    int c  = bc % Cn;
    int oy = p / HKn, ox = p % HKn;
    const float* xin = x + (size_t)bc * Pn;
    const float* wc  = w + c * 4;
    float acc = bias[c];
    acc += wc[0] * xin[(2 * oy) * Wn + 2 * ox];
    acc += wc[1] * xin[(2 * oy) * Wn + 2 * ox + 1];
    acc += wc[2] * xin[(2 * oy + 1) * Wn + 2 * ox];
    acc += wc[3] * xin[(2 * oy + 1) * Wn + 2 * ox + 1];
    out[idx] = acc;
}

// ======================= 128x128x8 double-buffered SGEMM cores =======================
// Variant PROJ: out[b][p][oc] = sum_k (X[b][k][p] (-m)*r) * WT[k][oc] + bias[oc] (+ res)
template <bool LNA, bool RES>
__global__ void __launch_bounds__(256, 2) k_proj128(
    const float* __restrict__ X, const float* __restrict__ WT,
    const float* __restrict__ bias, const float2* __restrict__ mr,
    const float* __restrict__ res, float* __restrict__ out,
    int Ppts, int K, int OC) {
    __shared__ float As[2][8][128];
    __shared__ float Bs[2][8][128];
    const int b  = blockIdx.z;
    const int p0 = blockIdx.y * 128;
    const int n0 = blockIdx.x * 128;
    const float* Xb = X + (size_t)b * K * Ppts;
    float mean = 0.f, rstd = 1.f;
    if (LNA) { float2 v = mr[b]; mean = v.x; rstd = v.y; }
    const int tid = threadIdx.x;
    const int ka = tid >> 5;
    const int ma = (tid & 31) * 4;
    const int tx = tid & 15, ty = tid >> 4;

    float acc[8][8];
#pragma unroll
    for (int i = 0; i < 8; i++)
#pragma unroll
        for (int j = 0; j < 8; j++) acc[i][j] = 0.f;

    const int T = K >> 3;
    float4 pa, pb;
    {
        int p = p0 + ma;
        pa = make_float4(0.f, 0.f, 0.f, 0.f);
        if (p < Ppts) pa = *(const float4*)(Xb + (size_t)ka * Ppts + p);
        if (LNA) {
            pa.x = (pa.x - mean) * rstd; pa.y = (pa.y - mean) * rstd;
            pa.z = (pa.z - mean) * rstd; pa.w = (pa.w - mean) * rstd;
        }
        pb = *(const float4*)(WT + (size_t)ka * OC + n0 + ma);
    }
    *(float4*)&As[0][ka][ma] = pa;
    *(float4*)&Bs[0][ka][ma] = pb;
    __syncthreads();
    int s = 0;
    for (int t = 0; t < T; t++) {
        if (t + 1 < T) {
            int c0 = (t + 1) << 3;
            int p = p0 + ma;
            pa = make_float4(0.f, 0.f, 0.f, 0.f);
            if (p < Ppts) pa = *(const float4*)(Xb + (size_t)(c0 + ka) * Ppts + p);
            if (LNA) {
                pa.x = (pa.x - mean) * rstd; pa.y = (pa.y - mean) * rstd;
                pa.z = (pa.z - mean) * rstd; pa.w = (pa.w - mean) * rstd;
            }
            pb = *(const float4*)(WT + (size_t)(c0 + ka) * OC + n0 + ma);
        }
#pragma unroll
        for (int kk = 0; kk < 8; kk++) {
            float4 a0 = *(const float4*)&As[s][kk][ty * 4];
            float4 a1 = *(const float4*)&As[s][kk][64 + ty * 4];
            float4 b0 = *(const float4*)&Bs[s][kk][tx * 4];
            float4 b1 = *(const float4*)&Bs[s][kk][64 + tx * 4];
            float ar[8] = {a0.x, a0.y, a0.z, a0.w, a1.x, a1.y, a1.z, a1.w};
            float br[8] = {b0.x, b0.y, b0.z, b0.w, b1.x, b1.y, b1.z, b1.w};
#pragma unroll
            for (int i = 0; i < 8; i++)
#pragma unroll
                for (int j = 0; j < 8; j++) acc[i][j] += ar[i] * br[j];
        }
        if (t + 1 < T) {
            s ^= 1;
            *(float4*)&As[s][ka][ma] = pa;
            *(float4*)&Bs[s][ka][ma] = pb;
            __syncthreads();
        }
    }
    float4 bias0 = *(const float4*)(bias + n0 + tx * 4);
    float4 bias1 = *(const float4*)(bias + n0 + 64 + tx * 4);
#pragma unroll
    for (int i = 0; i < 8; i++) {
        int p = p0 + (i < 4 ? ty * 4 + i : 64 + ty * 4 + (i - 4));
        if (p >= Ppts) continue;
        size_t off = ((size_t)b * Ppts + p) * OC + n0;
        float4 r0 = make_float4(acc[i][0] + bias0.x, acc[i][1] + bias0.y,
                                acc[i][2] + bias0.z, acc[i][3] + bias0.w);
        float4 r1 = make_float4(acc[i][4] + bias1.x, acc[i][5] + bias1.y,
                                acc[i][6] + bias1.z, acc[i][7] + bias1.w);
        if (RES) {
            float4 q0 = *(const float4*)(res + off + tx * 4);
            float4 q1 = *(const float4*)(res + off + 64 + tx * 4);
            r0.x += q0.x; r0.y += q0.y; r0.z += q0.z; r0.w += q0.w;
            r1.x += q1.x; r1.y += q1.y; r1.z += q1.z; r1.w += q1.w;
        }
        *(float4*)(out + off + tx * 4)      = r0;
        *(float4*)(out + off + 64 + tx * 4) = r1;
    }
}

// Variant CONV: out[b][m][p] = BN(sum_k WT[k][m] * (X[b][k][p] (-mean)*rstd) + cb[m]) (+GELU)(+res)
template <bool LNB, bool GELU, bool RES>
__global__ void __launch_bounds__(256, 2) k_conv128(
    const float* __restrict__ X, const float* __restrict__ WT,
    const float* __restrict__ cb,
    const float* __restrict__ bng, const float* __restrict__ bnb,
    const float* __restrict__ bnm, const float* __restrict__ bnv,
    const float2* __restrict__ mr, const float* __restrict__ res,
    float* __restrict__ out, int M, int K, int Ppts) {
    __shared__ float As[2][8][128];
    __shared__ float Bs[2][8][128];
    const int b  = blockIdx.z;
    const int m0 = blockIdx.y * 128;
    const int p0 = blockIdx.x * 128;
    const float* Xb = X + (size_t)b * K * Ppts;
    float mean = 0.f, rstd = 1.f;
    if (LNB) { float2 v = mr[b]; mean = v.x; rstd = v.y; }
    const int tid = threadIdx.x;
    const int ka = tid >> 5;
    const int ma = (tid & 31) * 4;
    const int tx = tid & 15, ty = tid >> 4;

    float acc[8][8];
#pragma unroll
    for (int i = 0; i < 8; i++)
#pragma unroll
        for (int j = 0; j < 8; j++) acc[i][j] = 0.f;

    const int T = K >> 3;
    float4 pa, pb;
    {
        pa = *(const float4*)(WT + (size_t)ka * M + m0 + ma);
        int p = p0 + ma;
        pb = make_float4(0.f, 0.f, 0.f, 0.f);
        if (p < Ppts) pb = *(const float4*)(Xb + (size_t)ka * Ppts + p);
        if (LNB) {
            pb.x = (pb.x - mean) * rstd; pb.y = (pb.y - mean) * rstd;
            pb.z = (pb.z - mean) * rstd; pb.w = (pb.w - mean) * rstd;
        }
    }
    *(float4*)&As[0][ka][ma] = pa;
    *(float4*)&Bs[0][ka][ma] = pb;
    __syncthreads();
    int s = 0;
    for (int t = 0; t < T; t++) {
        if (t + 1 < T) {
            int c0 = (t + 1) << 3;
            pa = *(const float4*)(WT + (size_t)(c0 + ka) * M + m0 + ma);
            int p = p0 + ma;
            pb = make_float4(0.f, 0.f, 0.f, 0.f);
            if (p < Ppts) pb = *(const float4*)(Xb + (size_t)(c0 + ka) * Ppts + p);
            if (LNB) {
                pb.x = (pb.x - mean) * rstd; pb.y = (pb.y - mean) * rstd;
                pb.z = (pb.z - mean) * rstd; pb.w = (pb.w - mean) * rstd;
            }
        }
#pragma unroll
        for (int kk = 0; kk < 8; kk++) {
            float4 a0 = *(const float4*)&As[s][kk][ty * 4];
            float4 a1 = *(const float4*)&As[s][kk][64 + ty * 4];
            float4 b0 = *(const float4*)&Bs[s][kk][tx * 4];
            float4 b1 = *(const float4*)&Bs[s][kk][64 + tx * 4];
            float ar[8] = {a0.x, a0.y, a0.z, a0.w, a1.x, a1.y, a1.z, a1.w};
            float br[8] = {b0.x, b0.y, b0.z, b0.w, b1.x, b1.y, b1.z, b1.w};
#pragma unroll
            for (int i = 0; i < 8; i++)
#pragma unroll
                for (int j = 0; j < 8; j++) acc[i][j] += ar[i] * br[j];
        }
        if (t + 1 < T) {
            s ^= 1;
            *(float4*)&As[s][ka][ma] = pa;
            *(float4*)&Bs[s][ka][ma] = pb;
            __syncthreads();
        }
    }
#pragma unroll
    for (int i = 0; i < 8; i++) {
        int m = m0 + (i < 4 ? ty * 4 + i : 64 + ty * 4 + (i - 4));
        float scale = bng[m] * rsqrtf(bnv[m] + EPSf);
        float shift = bnb[m] - bnm[m] * scale;
        float cbm   = cb[m];
        size_t rowoff = ((size_t)b * M + m) * Ppts;
        int pA = p0 + tx * 4, pB = p0 + 64 + tx * 4;
        if (pA < Ppts) {
            float4 r;
            r.x = (acc[i][0] + cbm) * scale + shift;
            r.y = (acc[i][1] + cbm) * scale + shift;
            r.z = (acc[i][2] + cbm) * scale + shift;
            r.w = (acc[i][3] + cbm) * scale + shift;
            if (GELU) { r.x = gelu_f(r.x); r.y = gelu_f(r.y); r.z = gelu_f(r.z); r.w = gelu_f(r.w); }
            if (RES) {
                float4 q = *(const float4*)(res + rowoff + pA);
                r.x += q.x; r.y += q.y; r.z += q.z; r.w += q.w;
            }
            *(float4*)(out + rowoff + pA) = r;
        }
        if (pB < Ppts) {
            float4 r;
            r.x = (acc[i][4] + cbm) * scale + shift;
            r.y = (acc[i][5] + cbm) * scale + shift;
            r.z = (acc[i][6] + cbm) * scale + shift;
            r.w = (acc[i][7] + cbm) * scale + shift;
            if (GELU) { r.x = gelu_f(r.x); r.y = gelu_f(r.y); r.z = gelu_f(r.z); r.w = gelu_f(r.w); }
            if (RES) {
                float4 q = *(const float4*)(res + rowoff + pB);
                r.x += q.x; r.y += q.y; r.z += q.z; r.w += q.w;
            }
            *(float4*)(out + rowoff + pB) = r;
        }
    }
}

// ---------------- fused attention, block = (b, head), coalesced pos, channel-major out ----------------
__global__ void __launch_bounds__(256) k_attn(
    const float* __restrict__ q, const float* __restrict__ k,
    const float* __restrict__ v, const float* __restrict__ posT,
    float* __restrict__ outT) {
    extern __shared__ float sm[];
    float* Ks = sm;                 // [196][32]
    float* Vs = sm + NKn * DKn;     // [196][32]
    int b = blockIdx.x >> 3;
    int h = blockIdx.x & 7;
    for (int l = threadIdx.x; l < NKn * 8; l += 256) {
        int j = l >> 3, qv = l & 7;
        size_t src = ((size_t)(b * NKn + j)) * Cn + h * DKn + qv * 4;
        ((float4*)Ks)[l] = *(const float4*)(k + src);
        ((float4*)Vs)[l] = *(const float4*)(v + src);
    }
    __syncthreads();
    const float scale = 0.17677669529663687f;  // 32^-0.5
    for (int i = threadIdx.x; i < Pn; i += 256) {
        float4 qr[8];
        const float4* qp = (const float4*)(q + ((size_t)b * Pn + i) * Cn + h * DKn);
#pragma unroll
        for (int qv = 0; qv < 8; qv++) qr[qv] = qp[qv];
        const float* pt = posT + (size_t)h * NKn * Pn + i;
        float mmax = -1e30f, lsum = 0.f;
        float4 o[8];
#pragma unroll
        for (int qv = 0; qv < 8; qv++) o[qv] = make_float4(0.f, 0.f, 0.f, 0.f);
        for (int j = 0; j < NKn; j++) {
            const float4* k4 = (const float4*)(Ks + j * DKn);
            float s = 0.f;
#pragma unroll
            for (int qv = 0; qv < 8; qv++) {
                float4 kk = k4[qv];
                s += qr[qv].x * kk.x + qr[qv].y * kk.y + qr[qv].z * kk.z + qr[qv].w * kk.w;
            }
            s = s * scale + pt[j * Pn];
            if (s > mmax) {
                float corr = __expf(mmax - s);
                lsum *= corr;
#pragma unroll
                for (int qv = 0; qv < 8; qv++) {
                    o[qv].x *= corr; o[qv].y *= corr; o[qv].z *= corr; o[qv].w *= corr;
                }
                mmax = s;
            }
            float e = __expf(s - mmax);
            lsum += e;
            const float4* v4 = (const float4*)(Vs + j * DKn);
#pragma unroll
            for (int qv = 0; qv < 8; qv++) {
                float4 vv = v4[qv];
                o[qv].x += e * vv.x; o[qv].y += e * vv.y;
                o[qv].z += e * vv.z; o[qv].w += e * vv.w;
            }
        }
        float inv = 1.f / lsum;
        size_t base = ((size_t)(b * Cn + h * DKn)) * Pn + i;
#pragma unroll
        for (int qv = 0; qv < 8; qv++) {
            outT[base + (size_t)(qv * 4 + 0) * Pn] = o[qv].x * inv;
            outT[base + (size_t)(qv * 4 + 1) * Pn] = o[qv].y * inv;
            outT[base + (size_t)(qv * 4 + 2) * Pn] = o[qv].z * inv;
            outT[base + (size_t)(qv * 4 + 3) * Pn] = o[qv].w * inv;
        }
    }
}

// ---------------- host launch ----------------
static void* sym_addr(const void* symbol) {
    void* p = nullptr;
    cudaGetSymbolAddress(&p, symbol);
    return p;
}

extern "C" void kernel_launch(void* const* d_in, const int* in_sizes, int n_in,
                              void* d_out, int out_size) {
    const float* x     = (const float*)d_in[0];
    const float* lpu_w = (const float*)d_in[1];
    const float* lpu_b = (const float*)d_in[2];
    const float* dw_w  = (const float*)d_in[3];
    const float* dw_b  = (const float*)d_in[4];
    const float* wq    = (const float*)d_in[5];
    const float* bq    = (const float*)d_in[6];
    const float* wk    = (const float*)d_in[7];
    const float* bk    = (const float*)d_in[8];
    const float* wv    = (const float*)d_in[9];
    const float* bv    = (const float*)d_in[10];
    const float* wo    = (const float*)d_in[11];
    const float* bo    = (const float*)d_in[12];
    const float* pos_b = (const float*)d_in[13];
    const float* c1_w  = (const float*)d_in[14];
    const float* c1_b  = (const float*)d_in[15];
    const float* bn1_g = (const float*)d_in[16];
    const float* bn1_b = (const float*)d_in[17];
    const float* bn1_m = (const float*)d_in[18];
    const float* bn1_v = (const float*)d_in[19];
    const float* dw2_w = (const float*)d_in[20];
    const float* dw2_b = (const float*)d_in[21];
    const float* bn2_g = (const float*)d_in[22];
    const float* bn2_b = (const float*)d_in[23];
    const float* bn2_m = (const float*)d_in[24];
    const float* bn2_v = (const float*)d_in[25];
    const float* c2_w  = (const float*)d_in[26];
    const float* c2_b  = (const float*)d_in[27];
    const float* bn3_g = (const float*)d_in[28];
    const float* bn3_b = (const float*)d_in[29];
    const float* bn3_m = (const float*)d_in[30];
    const float* bn3_v = (const float*)d_in[31];
    float* out = (float*)d_out;

    float*  x1   = (float*)sym_addr(g_x1);
    float*  qb   = (float*)sym_addr(g_q);
    float*  kvb  = (float*)sym_addr(g_kv);
    float*  kb   = (float*)sym_addr(g_k);
    float*  vb   = (float*)sym_addr(g_v);
    float*  tmpT = (float*)sym_addr(g_tmpT);
    float*  x2   = (float*)sym_addr(g_x2);
    float*  t1   = (float*)sym_addr(g_t1);
    float*  t2   = (float*)sym_addr(g_t2);
    float*  wqT  = (float*)sym_addr(g_wqT);
    float*  wkT  = (float*)sym_addr(g_wkT);
    float*  wvT  = (float*)sym_addr(g_wvT);
    float*  woT  = (float*)sym_addr(g_woT);
    float*  c1T  = (float*)sym_addr(g_c1T);
    float*  c2T  = (float*)sym_addr(g_c2T);
    float*  posT = (float*)sym_addr(g_posT);
    float2* part = (float2*)sym_addr(g_part);
    float2* mr   = (float2*)sym_addr(g_mr);

    dim3 tb(32, 8);
    // weight / pos transposes (cheap, once per launch)
    k_transp<<<dim3(8, 8, 1),  tb>>>(wq,   wqT, Cn, Cn);
    k_transp<<<dim3(8, 8, 1),  tb>>>(wk,   wkT, Cn, Cn);
    k_transp<<<dim3(8, 8, 1),  tb>>>(wv,   wvT, Cn, Cn);
    k_transp<<<dim3(8, 8, 1),  tb>>>(wo,   woT, Cn, Cn);
    k_transp<<<dim3(8, 32, 1), tb>>>(c1_w, c1T, CMn, Cn);
    k_transp<<<dim3(32, 8, 1), tb>>>(c2_w, c2T, Cn, CMn);
    k_transp<<<dim3(7, 25, 8), tb>>>(pos_b, posT, Pn, NKn);

    // 1. LPU
    k_dwplane<0><<<Bn * Cn, 256>>>(x, lpu_w, lpu_b, nullptr, nullptr, nullptr, nullptr, x1, Cn);
    // 2. LN1 stats
    k_stats_part<<<dim3(Bn, 8), 256>>>(x1, part);
    k_stats_fin<<<1, 256>>>(part, mr);
    // 3. KV downsample (on pre-LN x1)
    k_kvconv<<<(Bn * Cn * NKn + 255) / 256, 256>>>(x1, dw_w, dw_b, kvb);
    // 4-6. Q (LN fused), K, V projections
    k_proj128<true,  false><<<dim3(2, 7, Bn), 256>>>(x1,  wqT, bq, mr, nullptr, qb, Pn,  Cn, Cn);
    k_proj128<false, false><<<dim3(2, 2, Bn), 256>>>(kvb, wkT, bk, nullptr, nullptr, kb, NKn, Cn, Cn);
    k_proj128<false, false><<<dim3(2, 2, Bn), 256>>>(kvb, wvT, bv, nullptr, nullptr, vb, NKn, Cn, Cn);
    // 7. fused attention -> channel-major tmpT
    {
        int smem = 2 * NKn * DKn * (int)sizeof(float);  // 50176
        cudaFuncSetAttribute(k_attn, cudaFuncAttributeMaxDynamicSharedMemorySize, smem);
        k_attn<<<Bn * NH, 256, smem>>>(qb, kb, vb, posT, tmpT);
    }
    // 8. O projection + residual (flat-reinterpret add) -> x2
    k_proj128<false, true><<<dim3(2, 7, Bn), 256>>>(tmpT, woT, bo, nullptr, x1, x2, Pn, Cn, Cn);
    // 9. LN2 stats
    k_stats_part<<<dim3(Bn, 8), 256>>>(x2, part);
    k_stats_fin<<<1, 256>>>(part, mr);
    // 10. c1 + BN1 + GELU (LN fused on input)
    k_conv128<true, true, false><<<dim3(7, 8, Bn), 256>>>(
        x2, c1T, c1_b, bn1_g, bn1_b, bn1_m, bn1_v, mr, nullptr, t1, CMn, Cn, Pn);
    // 11. dw2 + BN2 + GELU
    k_dwplane<1><<<Bn * CMn, 256>>>(t1, dw2_w, dw2_b, bn2_g, bn2_b, bn2_m, bn2_v, t2, CMn);
    // 12. c2 + BN3 + residual -> d_out
    k_conv128<false, false, true><<<dim3(7, 2, Bn), 256>>>(
        t2, c2T, c2_b, bn3_g, bn3_b, bn3_m, bn3_v, nullptr, x2, out, Cn, CMn, Pn);
}

// round 4
// speedup vs baseline: 2.2547x; 1.4783x over previous
#include <cuda_runtime.h>
#include <math.h>
#include <stdint.h>

// ---------------- problem constants ----------------
#define Bn   32
#define Cn   256
#define Hn   28
#define Wn   28
#define Pn   784          // H*W
#define NKn  196          // (H/2)*(W/2)
#define HKn  14
#define CMn  1024         // C * R
#define NH   8
#define DKn  32
#define EPSf 1e-5f

// ---------------- scratch (device globals: allocation-free) ----------------
__device__ float g_x1  [Bn*Cn*Pn];     // after LPU (channel-major)
__device__ float g_xrow[Bn*Pn*Cn];     // LN(x1) row-major [p][c]
__device__ float g_q   [Bn*Pn*Cn];     // Q row-major [p][oc]
__device__ float g_kv  [Bn*Cn*NKn];    // stride-2 dw conv out [c][196]
__device__ float g_k   [Bn*NKn*Cn];    // [nk][256] row-major
__device__ float g_v   [Bn*NKn*Cn];
__device__ float g_att [Bn*Pn*Cn];     // attention out row-major [p][d]
__device__ float g_x2  [Bn*Cn*Pn];     // after attn residual (flat)
__device__ float g_x2r [Bn*Pn*Cn];     // LN(x2) row-major
__device__ float g_t1  [Bn*CMn*Pn];    // IRFFN expand (channel-major)
__device__ float g_t2  [Bn*CMn*Pn];    // after dw2 (channel-major)
__device__ float g_t2T [Bn*Pn*CMn];    // t2 row-major [p][m]
__device__ float g_wkT [Cn*Cn];
__device__ float g_wvT [Cn*Cn];
__device__ float g_posT[NH*NKn*Pn];    // pos transposed [h][j][i]
__device__ float2 g_part[Bn*8];
__device__ float2 g_mr  [Bn];          // (mean, rstd) per sample

__device__ __forceinline__ float gelu_f(float v) {
    return 0.5f * v * (1.0f + erff(v * 0.7071067811865475f));
}
__device__ __forceinline__ uint32_t f2tf32(float f) {
    uint32_t r;
    asm("cvt.rna.tf32.f32 %0, %1;" : "=r"(r) : "f"(f));
    return r;
}
__device__ __forceinline__ void mma_tf32(float* c, const uint32_t* a, const uint32_t* b) {
    asm volatile(
        "mma.sync.aligned.m16n8k8.row.col.f32.tf32.tf32.f32 "
        "{%0,%1,%2,%3}, {%4,%5,%6,%7}, {%8,%9}, {%0,%1,%2,%3};"
        : "+f"(c[0]), "+f"(c[1]), "+f"(c[2]), "+f"(c[3])
        : "r"(a[0]), "r"(a[1]), "r"(a[2]), "r"(a[3]), "r"(b[0]), "r"(b[1]));
}

// ====================== tf32 mma.sync GEMM ======================
// D[m][p] = sum_k W[m][k] * X[p][k]   (per batch, X row-major [784][K])
// MODE 0 (Q):  out[p*M+m] = D + bias[m]
// MODE 1 (O):  out[p*M+m] = D + bias[m] + res[p*M+m]      (flat-reinterpret residual)
// MODE 2 (c1): out[m*784+p] = gelu(BN(D + bias[m]))
// MODE 3 (c2): out[m*784+p] = BN(D + bias[m]) + res[m*784+p]
#define MKC 32
#define ASTR 36                 // smem row stride (floats), conflict-free fragments
#define SMEM_MMA (128*132*4)    // 67584 B staging (>= 2*128*36*4 = 36864 operands)

template <int MODE>
__global__ void __launch_bounds__(256) k_mma(
    const float* __restrict__ W, const float* __restrict__ X,
    const float* __restrict__ bias,
    const float* __restrict__ bng, const float* __restrict__ bnb,
    const float* __restrict__ bnm, const float* __restrict__ bnv,
    const float* __restrict__ res, float* __restrict__ out,
    int M, int K) {
    extern __shared__ float sm[];
    float* As = sm;               // [128][36] (m, k)
    float* Bs = sm + 128 * ASTR;  // [128][36] (p, k)
    const int tid  = threadIdx.x;
    const int warp = tid >> 5, lane = tid & 31;
    const int gid = lane >> 2, tq = lane & 3;
    const int wm = (warp & 1) * 64;
    const int wn = (warp >> 1) * 32;
    const int b  = blockIdx.z;
    const int m0 = blockIdx.y * 128;
    const int n0 = blockIdx.x * 128;
    const float* Xb = X + (size_t)b * Pn * K;

    float acc[4][4][4];
#pragma unroll
    for (int i = 0; i < 4; i++)
#pragma unroll
        for (int j = 0; j < 4; j++)
#pragma unroll
            for (int r = 0; r < 4; r++) acc[i][j][r] = 0.f;

    const int lrow = tid >> 3;       // 0..31 step: 4 rows covered per 256 thr pass
    const int lf4  = (tid & 7) * 4;  // k offset within chunk
    uint4 pa[4], pb[4];

    const int T = K / MKC;
    // prologue load chunk 0
#pragma unroll
    for (int i = 0; i < 4; i++) {
        int row = lrow + i * 32;
        float4 a = *(const float4*)(W + (size_t)(m0 + row) * K + lf4);
        pa[i] = make_uint4(f2tf32(a.x), f2tf32(a.y), f2tf32(a.z), f2tf32(a.w));
        float4 bx = make_float4(0.f, 0.f, 0.f, 0.f);
        if (n0 + row < Pn) bx = *(const float4*)(Xb + (size_t)(n0 + row) * K + lf4);
        pb[i] = make_uint4(f2tf32(bx.x), f2tf32(bx.y), f2tf32(bx.z), f2tf32(bx.w));
    }
#pragma unroll
    for (int i = 0; i < 4; i++) {
        int row = lrow + i * 32;
        *(uint4*)&As[row * ASTR + lf4] = pa[i];
        *(uint4*)&Bs[row * ASTR + lf4] = pb[i];
    }
    __syncthreads();

    for (int t = 0; t < T; t++) {
        if (t + 1 < T) {
            int kc0 = (t + 1) * MKC;
#pragma unroll
            for (int i = 0; i < 4; i++) {
                int row = lrow + i * 32;
                float4 a = *(const float4*)(W + (size_t)(m0 + row) * K + kc0 + lf4);
                pa[i] = make_uint4(f2tf32(a.x), f2tf32(a.y), f2tf32(a.z), f2tf32(a.w));
                float4 bx = make_float4(0.f, 0.f, 0.f, 0.f);
                if (n0 + row < Pn) bx = *(const float4*)(Xb + (size_t)(n0 + row) * K + kc0 + lf4);
                pb[i] = make_uint4(f2tf32(bx.x), f2tf32(bx.y), f2tf32(bx.z), f2tf32(bx.w));
            }
        }
#pragma unroll
        for (int ks = 0; ks < 4; ks++) {
            const int k0 = ks * 8;
            uint32_t af[4][4], bf[4][2];
#pragma unroll
            for (int i = 0; i < 4; i++) {
                const float* ap = As + (wm + i * 16 + gid) * ASTR + k0 + tq;
                af[i][0] = __float_as_uint(ap[0]);
                af[i][1] = __float_as_uint(ap[8 * ASTR]);
                af[i][2] = __float_as_uint(ap[4]);
                af[i][3] = __float_as_uint(ap[8 * ASTR + 4]);
            }
#pragma unroll
            for (int j = 0; j < 4; j++) {
                const float* bp = Bs + (wn + j * 8 + gid) * ASTR + k0 + tq;
                bf[j][0] = __float_as_uint(bp[0]);
                bf[j][1] = __float_as_uint(bp[4]);
            }
#pragma unroll
            for (int i = 0; i < 4; i++)
#pragma unroll
                for (int j = 0; j < 4; j++) mma_tf32(acc[i][j], af[i], bf[j]);
        }
        if (t + 1 < T) {
            __syncthreads();
#pragma unroll
            for (int i = 0; i < 4; i++) {
                int row = lrow + i * 32;
                *(uint4*)&As[row * ASTR + lf4] = pa[i];
                *(uint4*)&Bs[row * ASTR + lf4] = pb[i];
            }
            __syncthreads();
        }
    }

    // stage D tile in smem
    __syncthreads();
    float* sD = sm;  // stride 132
#pragma unroll
    for (int i = 0; i < 4; i++) {
        int mrow = wm + i * 16 + gid;
#pragma unroll
        for (int j = 0; j < 4; j++) {
            int pcol = wn + j * 8 + 2 * tq;
            if (MODE <= 1) {
                sD[pcol * 132 + mrow]           = acc[i][j][0];
                sD[(pcol + 1) * 132 + mrow]     = acc[i][j][1];
                sD[pcol * 132 + mrow + 8]       = acc[i][j][2];
                sD[(pcol + 1) * 132 + mrow + 8] = acc[i][j][3];
            } else {
                sD[mrow * 132 + pcol]           = acc[i][j][0];
                sD[mrow * 132 + pcol + 1]       = acc[i][j][1];
                sD[(mrow + 8) * 132 + pcol]     = acc[i][j][2];
                sD[(mrow + 8) * 132 + pcol + 1] = acc[i][j][3];
            }
        }
    }
    __syncthreads();

    float* outb = out + (size_t)b * (size_t)M * Pn;
    const float* resb = (MODE == 1 || MODE == 3) ? res + (size_t)b * (size_t)M * Pn : nullptr;

    if (MODE <= 1) {
        // row-major out[p*M + m], coalesced float4 along m
        for (int l = tid; l < 128 * 32; l += 256) {
            int pl = l >> 5, mq = (l & 31) * 4;
            int p = n0 + pl;
            if (p >= Pn) continue;
            float4 v = *(float4*)&sD[pl * 132 + mq];
            float4 bb = *(const float4*)(bias + m0 + mq);
            v.x += bb.x; v.y += bb.y; v.z += bb.z; v.w += bb.w;
            size_t off = (size_t)p * M + m0 + mq;
            if (MODE == 1) {
                float4 rr = *(const float4*)(resb + off);
                v.x += rr.x; v.y += rr.y; v.z += rr.z; v.w += rr.w;
            }
            *(float4*)(outb + off) = v;
        }
    } else {
        // channel-major out[m*784 + p], coalesced float4 along p
        for (int l = tid; l < 128 * 32; l += 256) {
            int ml = l >> 5, pq = (l & 31) * 4;
            int m = m0 + ml;
            int p = n0 + pq;
            if (p >= Pn) continue;
            float scale = bng[m] * rsqrtf(bnv[m] + EPSf);
            float shift = bnb[m] - bnm[m] * scale + bias[m] * scale;
            float4 v = *(float4*)&sD[ml * 132 + pq];
            v.x = v.x * scale + shift; v.y = v.y * scale + shift;
            v.z = v.z * scale + shift; v.w = v.w * scale + shift;
            if (MODE == 2) { v.x = gelu_f(v.x); v.y = gelu_f(v.y); v.z = gelu_f(v.z); v.w = gelu_f(v.w); }
            size_t off = (size_t)m * Pn + p;
            if (MODE == 3) {
                float4 rr = *(const float4*)(resb + off);
                v.x += rr.x; v.y += rr.y; v.z += rr.z; v.w += rr.w;
            }
            *(float4*)(outb + off) = v;
        }
    }
}

// ---------------- generic tiled transpose: in[R][C] -> out[C][R], batched z ----------------
__global__ void k_transp(const float* __restrict__ in, float* __restrict__ out,
                         int R, int C) {
    __shared__ float t[32][33];
    size_t boff = (size_t)blockIdx.z * R * C;
    in  += boff;
    out += boff;
    int c0 = blockIdx.x * 32, r0 = blockIdx.y * 32;
#pragma unroll
    for (int q = 0; q < 32; q += 8) {
        int r = r0 + threadIdx.y + q, c = c0 + threadIdx.x;
        if (r < R && c < C) t[threadIdx.y + q][threadIdx.x] = in[(size_t)r * C + c];
    }
    __syncthreads();
#pragma unroll
    for (int q = 0; q < 32; q += 8) {
        int c = c0 + threadIdx.y + q, r = r0 + threadIdx.x;
        if (r < R && c < C) out[(size_t)c * R + r] = t[threadIdx.x][threadIdx.y + q];
    }
}

// --------- transpose + LayerNorm: chan [256][784] -> row [784][256], per batch ---------
__global__ void k_trln(const float* __restrict__ src, const float2* __restrict__ mr,
                       float* __restrict__ dst) {
    __shared__ float t[32][33];
    int b = blockIdx.z;
    float2 s = mr[b];
    src += (size_t)b * Cn * Pn;
    dst += (size_t)b * Cn * Pn;
    int p0 = blockIdx.x * 32, c0 = blockIdx.y * 32;
#pragma unroll
    for (int q = 0; q < 32; q += 8) {
        int c = c0 + threadIdx.y + q, p = p0 + threadIdx.x;
        if (p < Pn)
            t[threadIdx.y + q][threadIdx.x] = (src[(size_t)c * Pn + p] - s.x) * s.y;
    }
    __syncthreads();
#pragma unroll
    for (int q = 0; q < 32; q += 8) {
        int p = p0 + threadIdx.y + q, c = c0 + threadIdx.x;
        if (p < Pn) dst[(size_t)p * Cn + c] = t[threadIdx.x][threadIdx.y + q];
    }
}

// ---------------- depthwise 3x3 pad1, one (b,ch) plane per block ----------------
template <int MODE>
__global__ void __launch_bounds__(256) k_dwplane(
    const float* __restrict__ X, const float* __restrict__ w,
    const float* __restrict__ bias,
    const float* __restrict__ bng, const float* __restrict__ bnb,
    const float* __restrict__ bnm, const float* __restrict__ bnv,
    float* __restrict__ out, int CH) {
    __shared__ float sp[Pn];
    int bc = blockIdx.x;
    int c  = bc % CH;
    const float* xin = X + (size_t)bc * Pn;
    for (int i = threadIdx.x; i < Pn; i += 256) sp[i] = xin[i];
    float wc[9];
#pragma unroll
    for (int i = 0; i < 9; i++) wc[i] = w[c * 9 + i];
    float bsv = bias[c];
    float scale = 0.f, shift = 0.f;
    if (MODE == 1) {
        scale = bng[c] * rsqrtf(bnv[c] + EPSf);
        shift = bnb[c] - bnm[c] * scale;
    }
    __syncthreads();
    for (int p = threadIdx.x; p < Pn; p += 256) {
        int py = p / Wn, px = p % Wn;
        float acc = bsv;
#pragma unroll
        for (int i = 0; i < 3; i++)
#pragma unroll
            for (int j = 0; j < 3; j++) {
                int yy = py + i - 1, xx = px + j - 1;
                if (yy >= 0 && yy < Hn && xx >= 0 && xx < Wn)
                    acc += wc[i * 3 + j] * sp[yy * Wn + xx];
            }
        float y;
        if (MODE == 0) y = acc + sp[p];
        else           y = gelu_f(acc * scale + shift);
        out[(size_t)bc * Pn + p] = y;
    }
}

// ---------------- LN stats ----------------
__global__ void k_stats_part(const float* __restrict__ src, float2* __restrict__ part) {
    int b = blockIdx.x, ch = blockIdx.y;
    const float4* s = (const float4*)(src + (size_t)b * Cn * Pn + (size_t)ch * (Cn * Pn / 8));
    const int nv = (Cn * Pn / 8) / 4;
    float sum = 0.f, sq = 0.f;
    for (int i = threadIdx.x; i < nv; i += 256) {
        float4 v = s[i];
        sum += v.x + v.y + v.z + v.w;
        sq  += v.x * v.x + v.y * v.y + v.z * v.z + v.w * v.w;
    }
    __shared__ float r1[256], r2[256];
    r1[threadIdx.x] = sum; r2[threadIdx.x] = sq;
    __syncthreads();
    for (int st = 128; st > 0; st >>= 1) {
        if (threadIdx.x < st) {
            r1[threadIdx.x] += r1[threadIdx.x + st];
            r2[threadIdx.x] += r2[threadIdx.x + st];
        }
        __syncthreads();
    }
    if (threadIdx.x == 0) part[b * 8 + ch] = make_float2(r1[0], r2[0]);
}

__global__ void k_stats_fin(const float2* __restrict__ part, float2* __restrict__ mr) {
    int t = threadIdx.x;
    float2 p = part[t];
#pragma unroll
    for (int o = 4; o >= 1; o >>= 1) {
        p.x += __shfl_down_sync(0xffffffffu, p.x, o, 8);
        p.y += __shfl_down_sync(0xffffffffu, p.y, o, 8);
    }
    if ((t & 7) == 0) {
        const float n = (float)(Cn * Pn);
        float m  = p.x / n;
        float vv = p.y / n - m * m;
        mr[t >> 3] = make_float2(m, rsqrtf(vv + EPSf));
    }
}

// ---------------- KV downsample: depthwise 2x2 stride2 ----------------
__global__ void k_kvconv(const float* __restrict__ x, const float* __restrict__ w,
                         const float* __restrict__ bias, float* __restrict__ out) {
    int idx = blockIdx.x * blockDim.x + threadIdx.x;
    if (idx >= Bn * Cn * NKn) return;
    int p  = idx % NKn;
    int bc = idx / NKn;
    int c  = bc % Cn;
    int oy = p / HKn, ox = p % HKn;
    const float* xin = x + (size_t)bc * Pn;
    const float* wc  = w + c * 4;
    float acc = bias[c];
    acc += wc[0] * xin[(2 * oy) * Wn + 2 * ox];
    acc += wc[1] * xin[(2 * oy) * Wn + 2 * ox + 1];
    acc += wc[2] * xin[(2 * oy + 1) * Wn + 2 * ox];
    acc += wc[3] * xin[(2 * oy + 1) * Wn + 2 * ox + 1];
    out[idx] = acc;
}

// ---------------- FFMA 128x128 GEMM for K/V projections (small) ----------------
__global__ void __launch_bounds__(256, 2) k_proj128(
    const float* __restrict__ X, const float* __restrict__ WT,
    const float* __restrict__ bias, float* __restrict__ out,
    int Ppts, int K, int OC) {
    __shared__ float As[2][8][128];
    __shared__ float Bs[2][8][128];
    const int b  = blockIdx.z;
    const int p0 = blockIdx.y * 128;
    const int n0 = blockIdx.x * 128;
    const float* Xb = X + (size_t)b * K * Ppts;
    const int tid = threadIdx.x;
    const int ka = tid >> 5;
    const int ma = (tid & 31) * 4;
    const int tx = tid & 15, ty = tid >> 4;
    float acc[8][8];
#pragma unroll
    for (int i = 0; i < 8; i++)
#pragma unroll
        for (int j = 0; j < 8; j++) acc[i][j] = 0.f;
    const int T = K >> 3;
    float4 pa, pb;
    {
        int p = p0 + ma;
        pa = make_float4(0.f, 0.f, 0.f, 0.f);
        if (p < Ppts) pa = *(const float4*)(Xb + (size_t)ka * Ppts + p);
        pb = *(const float4*)(WT + (size_t)ka * OC + n0 + ma);
    }
    *(float4*)&As[0][ka][ma] = pa;
    *(float4*)&Bs[0][ka][ma] = pb;
    __syncthreads();
    int s = 0;
    for (int t = 0; t < T; t++) {
        if (t + 1 < T) {
            int c0 = (t + 1) << 3;
            int p = p0 + ma;
            pa = make_float4(0.f, 0.f, 0.f, 0.f);
            if (p < Ppts) pa = *(const float4*)(Xb + (size_t)(c0 + ka) * Ppts + p);
            pb = *(const float4*)(WT + (size_t)(c0 + ka) * OC + n0 + ma);
        }
#pragma unroll
        for (int kk = 0; kk < 8; kk++) {
            float4 a0 = *(const float4*)&As[s][kk][ty * 4];
            float4 a1 = *(const float4*)&As[s][kk][64 + ty * 4];
            float4 b0 = *(const float4*)&Bs[s][kk][tx * 4];
            float4 b1 = *(const float4*)&Bs[s][kk][64 + tx * 4];
            float ar[8] = {a0.x, a0.y, a0.z, a0.w, a1.x, a1.y, a1.z, a1.w};
            float br[8] = {b0.x, b0.y, b0.z, b0.w, b1.x, b1.y, b1.z, b1.w};
#pragma unroll
            for (int i = 0; i < 8; i++)
#pragma unroll
                for (int j = 0; j < 8; j++) acc[i][j] += ar[i] * br[j];
        }
        if (t + 1 < T) {
            s ^= 1;
            *(float4*)&As[s][ka][ma] = pa;
            *(float4*)&Bs[s][ka][ma] = pb;
            __syncthreads();
        }
    }
    float4 bias0 = *(const float4*)(bias + n0 + tx * 4);
    float4 bias1 = *(const float4*)(bias + n0 + 64 + tx * 4);
#pragma unroll
    for (int i = 0; i < 8; i++) {
        int p = p0 + (i < 4 ? ty * 4 + i : 64 + ty * 4 + (i - 4));
        if (p >= Ppts) continue;
        size_t off = ((size_t)b * Ppts + p) * OC + n0;
        float4 r0 = make_float4(acc[i][0] + bias0.x, acc[i][1] + bias0.y,
                                acc[i][2] + bias0.z, acc[i][3] + bias0.w);
        float4 r1 = make_float4(acc[i][4] + bias1.x, acc[i][5] + bias1.y,
                                acc[i][6] + bias1.z, acc[i][7] + bias1.w);
        *(float4*)(out + off + tx * 4)      = r0;
        *(float4*)(out + off + 64 + tx * 4) = r1;
    }
}

// ---------------- fused attention (online softmax), row-major q & out ----------------
__global__ void __launch_bounds__(256) k_attn(
    const float* __restrict__ q, const float* __restrict__ k,
    const float* __restrict__ v, const float* __restrict__ posT,
    float* __restrict__ out) {
    extern __shared__ float sm[];
    float* Ks = sm;
    float* Vs = sm + NKn * DKn;
    int b = blockIdx.x >> 3;
    int h = blockIdx.x & 7;
    for (int l = threadIdx.x; l < NKn * 8; l += 256) {
        int j = l >> 3, qv = l & 7;
        size_t src = ((size_t)(b * NKn + j)) * Cn + h * DKn + qv * 4;
        ((float4*)Ks)[l] = *(const float4*)(k + src);
        ((float4*)Vs)[l] = *(const float4*)(v + src);
    }
    __syncthreads();
    const float scale = 0.17677669529663687f;
    for (int i = threadIdx.x; i < Pn; i += 256) {
        float4 qr[8];
        const float4* qp = (const float4*)(q + ((size_t)b * Pn + i) * Cn + h * DKn);
#pragma unroll
        for (int qv = 0; qv < 8; qv++) qr[qv] = qp[qv];
        const float* pt = posT + (size_t)h * NKn * Pn + i;
        float mmax = -1e30f, lsum = 0.f;
        float4 o[8];
#pragma unroll
        for (int qv = 0; qv < 8; qv++) o[qv] = make_float4(0.f, 0.f, 0.f, 0.f);
        for (int j = 0; j < NKn; j++) {
            const float4* k4 = (const float4*)(Ks + j * DKn);
            float s = 0.f;
#pragma unroll
            for (int qv = 0; qv < 8; qv++) {
                float4 kk = k4[qv];
                s += qr[qv].x * kk.x + qr[qv].y * kk.y + qr[qv].z * kk.z + qr[qv].w * kk.w;
            }
            s = s * scale + pt[j * Pn];
            if (s > mmax) {
                float corr = __expf(mmax - s);
                lsum *= corr;
#pragma unroll
                for (int qv = 0; qv < 8; qv++) {
                    o[qv].x *= corr; o[qv].y *= corr; o[qv].z *= corr; o[qv].w *= corr;
                }
                mmax = s;
            }
            float e = __expf(s - mmax);
            lsum += e;
            const float4* v4 = (const float4*)(Vs + j * DKn);
#pragma unroll
            for (int qv = 0; qv < 8; qv++) {
                float4 vv = v4[qv];
                o[qv].x += e * vv.x; o[qv].y += e * vv.y;
                o[qv].z += e * vv.z; o[qv].w += e * vv.w;
            }
        }
        float inv = 1.f / lsum;
        float4* op = (float4*)(out + ((size_t)b * Pn + i) * Cn + h * DKn);
#pragma unroll
        for (int qv = 0; qv < 8; qv++) {
            float4 r = make_float4(o[qv].x * inv, o[qv].y * inv, o[qv].z * inv, o[qv].w * inv);
            op[qv] = r;
        }
    }
}

// ---------------- host launch ----------------
static void* sym_addr(const void* symbol) {
    void* p = nullptr;
    cudaGetSymbolAddress(&p, symbol);
    return p;
}

extern "C" void kernel_launch(void* const* d_in, const int* in_sizes, int n_in,
                              void* d_out, int out_size) {
    const float* x     = (const float*)d_in[0];
    const float* lpu_w = (const float*)d_in[1];
    const float* lpu_b = (const float*)d_in[2];
    const float* dw_w  = (const float*)d_in[3];
    const float* dw_b  = (const float*)d_in[4];
    const float* wq    = (const float*)d_in[5];
    const float* bq    = (const float*)d_in[6];
    const float* wk    = (const float*)d_in[7];
    const float* bk    = (const float*)d_in[8];
    const float* wv    = (const float*)d_in[9];
    const float* bv    = (const float*)d_in[10];
    const float* wo    = (const float*)d_in[11];
    const float* bo    = (const float*)d_in[12];
    const float* pos_b = (const float*)d_in[13];
    const float* c1_w  = (const float*)d_in[14];
    const float* c1_b  = (const float*)d_in[15];
    const float* bn1_g = (const float*)d_in[16];
    const float* bn1_b = (const float*)d_in[17];
    const float* bn1_m = (const float*)d_in[18];
    const float* bn1_v = (const float*)d_in[19];
    const float* dw2_w = (const float*)d_in[20];
    const float* dw2_b = (const float*)d_in[21];
    const float* bn2_g = (const float*)d_in[22];
    const float* bn2_b = (const float*)d_in[23];
    const float* bn2_m = (const float*)d_in[24];
    const float* bn2_v = (const float*)d_in[25];
    const float* c2_w  = (const float*)d_in[26];
    const float* c2_b  = (const float*)d_in[27];
    const float* bn3_g = (const float*)d_in[28];
    const float* bn3_b = (const float*)d_in[29];
    const float* bn3_m = (const float*)d_in[30];
    const float* bn3_v = (const float*)d_in[31];
    float* out = (float*)d_out;

    float*  x1   = (float*)sym_addr(g_x1);
    float*  xrow = (float*)sym_addr(g_xrow);
    float*  qb   = (float*)sym_addr(g_q);
    float*  kvb  = (float*)sym_addr(g_kv);
    float*  kb   = (float*)sym_addr(g_k);
    float*  vb   = (float*)sym_addr(g_v);
    float*  attb = (float*)sym_addr(g_att);
    float*  x2   = (float*)sym_addr(g_x2);
    float*  x2r  = (float*)sym_addr(g_x2r);
    float*  t1   = (float*)sym_addr(g_t1);
    float*  t2   = (float*)sym_addr(g_t2);
    float*  t2T  = (float*)sym_addr(g_t2T);
    float*  wkT  = (float*)sym_addr(g_wkT);
    float*  wvT  = (float*)sym_addr(g_wvT);
    float*  posT = (float*)sym_addr(g_posT);
    float2* part = (float2*)sym_addr(g_part);
    float2* mr   = (float2*)sym_addr(g_mr);

    cudaFuncSetAttribute(k_mma<0>, cudaFuncAttributeMaxDynamicSharedMemorySize, SMEM_MMA);
    cudaFuncSetAttribute(k_mma<1>, cudaFuncAttributeMaxDynamicSharedMemorySize, SMEM_MMA);
    cudaFuncSetAttribute(k_mma<2>, cudaFuncAttributeMaxDynamicSharedMemorySize, SMEM_MMA);
    cudaFuncSetAttribute(k_mma<3>, cudaFuncAttributeMaxDynamicSharedMemorySize, SMEM_MMA);
    cudaFuncSetAttribute(k_attn, cudaFuncAttributeMaxDynamicSharedMemorySize,
                         2 * NKn * DKn * (int)sizeof(float));

    dim3 tb(32, 8);
    // weight transposes for FFMA K/V path + pos transpose
    k_transp<<<dim3(8, 8, 1),  tb>>>(wk, wkT, Cn, Cn);
    k_transp<<<dim3(8, 8, 1),  tb>>>(wv, wvT, Cn, Cn);
    k_transp<<<dim3(7, 25, 8), tb>>>(pos_b, posT, Pn, NKn);

    // 1. LPU -> x1 (channel-major)
    k_dwplane<0><<<Bn * Cn, 256>>>(x, lpu_w, lpu_b, nullptr, nullptr, nullptr, nullptr, x1, Cn);
    // 2. LN1 stats
    k_stats_part<<<dim3(Bn, 8), 256>>>(x1, part);
    k_stats_fin<<<1, 256>>>(part, mr);
    // 3. KV downsample (pre-LN x1)
    k_kvconv<<<(Bn * Cn * NKn + 255) / 256, 256>>>(x1, dw_w, dw_b, kvb);
    // 4. LN(x1) -> row-major xrow
    k_trln<<<dim3(25, 8, Bn), tb>>>(x1, mr, xrow);
    // 5. K, V projections (FFMA, small)
    {
        dim3 gk(2, 2, Bn);
        k_proj128<<<gk, 256>>>(kvb, wkT, bk, kb, NKn, Cn, Cn);
        k_proj128<<<gk, 256>>>(kvb, wvT, bv, vb, NKn, Cn, Cn);
    }
    // 6. Q projection (tf32 mma) -> q row-major
    k_mma<0><<<dim3(7, 2, Bn), 256, SMEM_MMA>>>(
        wq, xrow, bq, nullptr, nullptr, nullptr, nullptr, nullptr, qb, Cn, Cn);
    // 7. fused attention -> row-major attb
    k_attn<<<Bn * NH, 256, 2 * NKn * DKn * (int)sizeof(float)>>>(qb, kb, vb, posT, attb);
    // 8. O projection + flat residual (tf32 mma) -> x2
    k_mma<1><<<dim3(7, 2, Bn), 256, SMEM_MMA>>>(
        wo, attb, bo, nullptr, nullptr, nullptr, nullptr, x1, x2, Cn, Cn);
    // 9. LN2 stats + transpose
    k_stats_part<<<dim3(Bn, 8), 256>>>(x2, part);
    k_stats_fin<<<1, 256>>>(part, mr);
    k_trln<<<dim3(25, 8, Bn), tb>>>(x2, mr, x2r);
    // 10. c1 + BN1 + GELU (tf32 mma) -> t1 channel-major
    k_mma<2><<<dim3(7, 8, Bn), 256, SMEM_MMA>>>(
        c1_w, x2r, c1_b, bn1_g, bn1_b, bn1_m, bn1_v, nullptr, t1, CMn, Cn);
    // 11. dw2 + BN2 + GELU -> t2 channel-major
    k_dwplane<1><<<Bn * CMn, 256>>>(t1, dw2_w, dw2_b, bn2_g, bn2_b, bn2_m, bn2_v, t2, CMn);
    // 12. transpose t2 -> t2T row-major [p][m]
    k_transp<<<dim3(25, 32, Bn), tb>>>(t2, t2T, CMn, Pn);
    // 13. c2 + BN3 + channel-major residual (tf32 mma) -> d_out
    k_mma<3><<<dim3(7, 2, Bn), 256, SMEM_MMA>>>(
        c2_w, t2T, c2_b, bn3_g, bn3_b, bn3_m, bn3_v, x2, out, Cn, CMn);
}

// round 5
// speedup vs baseline: 2.4112x; 1.0694x over previous
#include <cuda_runtime.h>
#include <math.h>
#include <stdint.h>

// ---------------- problem constants ----------------
#define Bn   32
#define Cn   256
#define Hn   28
#define Wn   28
#define Pn   784          // H*W
#define NKn  196          // (H/2)*(W/2)
#define HKn  14
#define CMn  1024         // C * R
#define NH   8
#define DKn  32
#define EPSf 1e-5f

// ---------------- scratch (device globals: allocation-free) ----------------
__device__ float g_x1  [Bn*Cn*Pn];     // after LPU (channel-major)
__device__ float g_q   [Bn*Pn*Cn];     // Q row-major [p][oc]
__device__ float g_kv  [Bn*Cn*NKn];    // stride-2 dw conv out [c][196]
__device__ float g_k   [Bn*NKn*Cn];    // [nk][256] row-major
__device__ float g_v   [Bn*NKn*Cn];
__device__ float g_attT[Bn*Cn*Pn];     // attention out CHANNEL-major [d][p]
__device__ float g_x2  [Bn*Cn*Pn];     // after attn residual (flat)
__device__ float g_t1  [Bn*CMn*Pn];    // IRFFN expand (channel-major)
__device__ float g_t2  [Bn*CMn*Pn];    // after dw2 (channel-major)
__device__ float g_wqT [Cn*Cn];        // [k][m]
__device__ float g_wkT [Cn*Cn];
__device__ float g_wvT [Cn*Cn];
__device__ float g_woT [Cn*Cn];
__device__ float g_c1T [Cn*CMn];       // [256][1024]
__device__ float g_c2T [CMn*Cn];       // [1024][256]
__device__ float g_posT[NH*NKn*Pn];    // pos transposed [h][j][i]
__device__ float2 g_part[Bn*8];
__device__ float2 g_mr  [Bn];          // (mean, rstd) per sample

__device__ __forceinline__ float gelu_f(float v) {
    return 0.5f * v * (1.0f + erff(v * 0.7071067811865475f));
}
__device__ __forceinline__ uint32_t f2tf32(float f) {
    uint32_t r;
    asm("cvt.rna.tf32.f32 %0, %1;" : "=r"(r) : "f"(f));
    return r;
}
__device__ __forceinline__ void mma_tf32(float* c, const uint32_t* a, const uint32_t* b) {
    asm volatile(
        "mma.sync.aligned.m16n8k8.row.col.f32.tf32.tf32.f32 "
        "{%0,%1,%2,%3}, {%4,%5,%6,%7}, {%8,%9}, {%0,%1,%2,%3};"
        : "+f"(c[0]), "+f"(c[1]), "+f"(c[2]), "+f"(c[3])
        : "r"(a[0]), "r"(a[1]), "r"(a[2]), "r"(a[3]), "r"(b[0]), "r"(b[1]));
}

// ====================== tf32 mma.sync GEMM, k-major smem ======================
// D[m][p] = sum_k WT[k][m] * X[k][p]  (X channel-major per batch, batch stride K*P)
// MODE 0: out[p*M+m] = D + bias[m]
// MODE 1: out[p*M+m] = D + bias[m] + res[p*M+m]      (flat-reinterpret residual)
// MODE 2: out[m*P+p] = gelu(BN(D + bias[m]))
// MODE 3: out[m*P+p] = BN(D + bias[m]) + res[m*P+p]
// LNB: scale X by (v - mean)*rstd from mr[b]
#define KSTR 132
#define SMEM_MMA (2*32*KSTR*4)   // 33792 B (operands; epilogue reuses same region)

template <int MODE, bool LNB>
__global__ void __launch_bounds__(256, 2) k_mma(
    const float* __restrict__ WT, const float* __restrict__ X,
    const float* __restrict__ bias,
    const float* __restrict__ bng, const float* __restrict__ bnb,
    const float* __restrict__ bnm, const float* __restrict__ bnv,
    const float2* __restrict__ mr, const float* __restrict__ res,
    float* __restrict__ out, int M, int K, int P) {
    extern __shared__ float sm[];
    float* As = sm;              // [32][KSTR]  (k, m)
    float* Bs = sm + 32 * KSTR;  // [32][KSTR]  (k, p)
    const int tid  = threadIdx.x;
    const int warp = tid >> 5, lane = tid & 31;
    const int gid = lane >> 2, tq = lane & 3;
    const int wm = (warp & 1) * 64;
    const int wn = (warp >> 1) * 32;
    const int b  = blockIdx.z;
    const int m0 = blockIdx.y * 128;
    const int n0 = blockIdx.x * 128;
    const float* Xb = X + (size_t)b * K * P;
    float mean = 0.f, rstd = 1.f;
    if (LNB) { float2 v = mr[b]; mean = v.x; rstd = v.y; }

    float acc[4][4][4];
#pragma unroll
    for (int i = 0; i < 4; i++)
#pragma unroll
        for (int j = 0; j < 4; j++)
#pragma unroll
            for (int r = 0; r < 4; r++) acc[i][j][r] = 0.f;

    const int mq = lane * 4;  // column offset within 128-wide tile (m or p)
    uint4 ra[4], rb[4];
    const int T = K >> 5;     // chunks of 32

    // prologue: load chunk 0 into registers
#pragma unroll
    for (int i = 0; i < 4; i++) {
        int k = warp + i * 8;
        float4 a = *(const float4*)(WT + (size_t)k * M + m0 + mq);
        ra[i] = make_uint4(f2tf32(a.x), f2tf32(a.y), f2tf32(a.z), f2tf32(a.w));
        float4 bx = make_float4(0.f, 0.f, 0.f, 0.f);
        if (n0 + mq < P) bx = *(const float4*)(Xb + (size_t)k * P + n0 + mq);
        if (LNB) {
            bx.x = (bx.x - mean) * rstd; bx.y = (bx.y - mean) * rstd;
            bx.z = (bx.z - mean) * rstd; bx.w = (bx.w - mean) * rstd;
        }
        rb[i] = make_uint4(f2tf32(bx.x), f2tf32(bx.y), f2tf32(bx.z), f2tf32(bx.w));
    }
#pragma unroll
    for (int i = 0; i < 4; i++) {
        int k = warp + i * 8;
        *(uint4*)&As[k * KSTR + mq] = ra[i];
        *(uint4*)&Bs[k * KSTR + mq] = rb[i];
    }
    __syncthreads();

    for (int t = 0; t < T; t++) {
        if (t + 1 < T) {
            int kc0 = (t + 1) << 5;
#pragma unroll
            for (int i = 0; i < 4; i++) {
                int k = kc0 + warp + i * 8;
                float4 a = *(const float4*)(WT + (size_t)k * M + m0 + mq);
                ra[i] = make_uint4(f2tf32(a.x), f2tf32(a.y), f2tf32(a.z), f2tf32(a.w));
                float4 bx = make_float4(0.f, 0.f, 0.f, 0.f);
                if (n0 + mq < P) bx = *(const float4*)(Xb + (size_t)k * P + n0 + mq);
                if (LNB) {
                    bx.x = (bx.x - mean) * rstd; bx.y = (bx.y - mean) * rstd;
                    bx.z = (bx.z - mean) * rstd; bx.w = (bx.w - mean) * rstd;
                }
                rb[i] = make_uint4(f2tf32(bx.x), f2tf32(bx.y), f2tf32(bx.z), f2tf32(bx.w));
            }
        }
#pragma unroll
        for (int ks = 0; ks < 4; ks++) {
            const int k0 = ks * 8;
            uint32_t af[4][4], bf[4][2];
#pragma unroll
            for (int i = 0; i < 4; i++) {
                int m = wm + i * 16 + gid;
                af[i][0] = __float_as_uint(As[(k0 + tq) * KSTR + m]);
                af[i][1] = __float_as_uint(As[(k0 + tq) * KSTR + m + 8]);
                af[i][2] = __float_as_uint(As[(k0 + tq + 4) * KSTR + m]);
                af[i][3] = __float_as_uint(As[(k0 + tq + 4) * KSTR + m + 8]);
            }
#pragma unroll
            for (int j = 0; j < 4; j++) {
                int p = wn + j * 8 + gid;
                bf[j][0] = __float_as_uint(Bs[(k0 + tq) * KSTR + p]);
                bf[j][1] = __float_as_uint(Bs[(k0 + tq + 4) * KSTR + p]);
            }
#pragma unroll
            for (int i = 0; i < 4; i++)
#pragma unroll
                for (int j = 0; j < 4; j++) mma_tf32(acc[i][j], af[i], bf[j]);
        }
        if (t + 1 < T) {
            __syncthreads();
#pragma unroll
            for (int i = 0; i < 4; i++) {
                int k = warp + i * 8;
                *(uint4*)&As[k * KSTR + mq] = ra[i];
                *(uint4*)&Bs[k * KSTR + mq] = rb[i];
            }
            __syncthreads();
        }
    }

    // ---- epilogue: two 64-row passes staged through smem (reuses operand smem) ----
    float* sD = sm;  // [64][132]
    float* outb = out + (size_t)b * (size_t)M * P;
    const float* resb = (MODE == 1 || MODE == 3) ? res + (size_t)b * (size_t)M * P : nullptr;

#pragma unroll
    for (int pass = 0; pass < 2; pass++) {
        __syncthreads();
        if (MODE <= 1) {
            if ((wn >> 6) == pass) {
#pragma unroll
                for (int i = 0; i < 4; i++) {
                    int mrow = wm + i * 16 + gid;
#pragma unroll
                    for (int j = 0; j < 4; j++) {
                        int pc = (wn & 63) + j * 8 + 2 * tq;
                        sD[pc * KSTR + mrow]           = acc[i][j][0];
                        sD[(pc + 1) * KSTR + mrow]     = acc[i][j][1];
                        sD[pc * KSTR + mrow + 8]       = acc[i][j][2];
                        sD[(pc + 1) * KSTR + mrow + 8] = acc[i][j][3];
                    }
                }
            }
        } else {
            if ((wm >> 6) == pass) {
#pragma unroll
                for (int i = 0; i < 4; i++) {
                    int ml = (wm & 63) + i * 16 + gid;
#pragma unroll
                    for (int j = 0; j < 4; j++) {
                        int pc = wn + j * 8 + 2 * tq;
                        sD[ml * KSTR + pc]           = acc[i][j][0];
                        sD[ml * KSTR + pc + 1]       = acc[i][j][1];
                        sD[(ml + 8) * KSTR + pc]     = acc[i][j][2];
                        sD[(ml + 8) * KSTR + pc + 1] = acc[i][j][3];
                    }
                }
            }
        }
        __syncthreads();
        if (MODE <= 1) {
            for (int l = tid; l < 64 * 32; l += 256) {
                int rl = l >> 5, cq = (l & 31) * 4;
                int p = n0 + pass * 64 + rl;
                if (p >= P) continue;
                float4 v = *(float4*)&sD[rl * KSTR + cq];
                float4 bb = *(const float4*)(bias + m0 + cq);
                v.x += bb.x; v.y += bb.y; v.z += bb.z; v.w += bb.w;
                size_t off = (size_t)p * M + m0 + cq;
                if (MODE == 1) {
                    float4 rr = *(const float4*)(resb + off);
                    v.x += rr.x; v.y += rr.y; v.z += rr.z; v.w += rr.w;
                }
                *(float4*)(outb + off) = v;
            }
        } else {
            for (int l = tid; l < 64 * 32; l += 256) {
                int rl = l >> 5, cq = (l & 31) * 4;
                int m = m0 + pass * 64 + rl;
                int p = n0 + cq;
                if (p >= P) continue;
                float scale = bng[m] * rsqrtf(bnv[m] + EPSf);
                float shift = bnb[m] - bnm[m] * scale + bias[m] * scale;
                float4 v = *(float4*)&sD[rl * KSTR + cq];
                v.x = v.x * scale + shift; v.y = v.y * scale + shift;
                v.z = v.z * scale + shift; v.w = v.w * scale + shift;
                if (MODE == 2) { v.x = gelu_f(v.x); v.y = gelu_f(v.y); v.z = gelu_f(v.z); v.w = gelu_f(v.w); }
                size_t off = (size_t)m * P + p;
                if (MODE == 3) {
                    float4 rr = *(const float4*)(resb + off);
                    v.x += rr.x; v.y += rr.y; v.z += rr.z; v.w += rr.w;
                }
                *(float4*)(outb + off) = v;
            }
        }
    }
}

// ---------------- generic tiled transpose: in[R][C] -> out[C][R], batched z ----------------
__global__ void k_transp(const float* __restrict__ in, float* __restrict__ out,
                         int R, int C) {
    __shared__ float t[32][33];
    size_t boff = (size_t)blockIdx.z * R * C;
    in  += boff;
    out += boff;
    int c0 = blockIdx.x * 32, r0 = blockIdx.y * 32;
#pragma unroll
    for (int q = 0; q < 32; q += 8) {
        int r = r0 + threadIdx.y + q, c = c0 + threadIdx.x;
        if (r < R && c < C) t[threadIdx.y + q][threadIdx.x] = in[(size_t)r * C + c];
    }
    __syncthreads();
#pragma unroll
    for (int q = 0; q < 32; q += 8) {
        int c = c0 + threadIdx.y + q, r = r0 + threadIdx.x;
        if (r < R && c < C) out[(size_t)c * R + r] = t[threadIdx.x][threadIdx.y + q];
    }
}

// ---------------- depthwise 3x3 pad1, one (b,ch) plane per block ----------------
template <int MODE>
__global__ void __launch_bounds__(256) k_dwplane(
    const float* __restrict__ X, const float* __restrict__ w,
    const float* __restrict__ bias,
    const float* __restrict__ bng, const float* __restrict__ bnb,
    const float* __restrict__ bnm, const float* __restrict__ bnv,
    float* __restrict__ out, int CH) {
    __shared__ float sp[Pn];
    int bc = blockIdx.x;
    int c  = bc % CH;
    const float* xin = X + (size_t)bc * Pn;
    for (int i = threadIdx.x; i < Pn; i += 256) sp[i] = xin[i];
    float wc[9];
#pragma unroll
    for (int i = 0; i < 9; i++) wc[i] = w[c * 9 + i];
    float bsv = bias[c];
    float scale = 0.f, shift = 0.f;
    if (MODE == 1) {
        scale = bng[c] * rsqrtf(bnv[c] + EPSf);
        shift = bnb[c] - bnm[c] * scale;
    }
    __syncthreads();
    for (int p = threadIdx.x; p < Pn; p += 256) {
        int py = p / Wn, px = p % Wn;
        float acc = bsv;
#pragma unroll
        for (int i = 0; i < 3; i++)
#pragma unroll
            for (int j = 0; j < 3; j++) {
                int yy = py + i - 1, xx = px + j - 1;
                if (yy >= 0 && yy < Hn && xx >= 0 && xx < Wn)
                    acc += wc[i * 3 + j] * sp[yy * Wn + xx];
            }
        float y;
        if (MODE == 0) y = acc + sp[p];
        else           y = gelu_f(acc * scale + shift);
        out[(size_t)bc * Pn + p] = y;
    }
}

// ---------------- LN stats ----------------
__global__ void k_stats_part(const float* __restrict__ src, float2* __restrict__ part) {
    int b = blockIdx.x, ch = blockIdx.y;
    const float4* s = (const float4*)(src + (size_t)b * Cn * Pn + (size_t)ch * (Cn * Pn / 8));
    const int nv = (Cn * Pn / 8) / 4;
    float sum = 0.f, sq = 0.f;
    for (int i = threadIdx.x; i < nv; i += 256) {
        float4 v = s[i];
        sum += v.x + v.y + v.z + v.w;
        sq  += v.x * v.x + v.y * v.y + v.z * v.z + v.w * v.w;
    }
    __shared__ float r1[256], r2[256];
    r1[threadIdx.x] = sum; r2[threadIdx.x] = sq;
    __syncthreads();
    for (int st = 128; st > 0; st >>= 1) {
        if (threadIdx.x < st) {
            r1[threadIdx.x] += r1[threadIdx.x + st];
            r2[threadIdx.x] += r2[threadIdx.x + st];
        }
        __syncthreads();
    }
    if (threadIdx.x == 0) part[b * 8 + ch] = make_float2(r1[0], r2[0]);
}

__global__ void k_stats_fin(const float2* __restrict__ part, float2* __restrict__ mr) {
    int t = threadIdx.x;
    float2 p = part[t];
#pragma unroll
    for (int o = 4; o >= 1; o >>= 1) {
        p.x += __shfl_down_sync(0xffffffffu, p.x, o, 8);
        p.y += __shfl_down_sync(0xffffffffu, p.y, o, 8);
    }
    if ((t & 7) == 0) {
        const float n = (float)(Cn * Pn);
        float m  = p.x / n;
        float vv = p.y / n - m * m;
        mr[t >> 3] = make_float2(m, rsqrtf(vv + EPSf));
    }
}

// ---------------- KV downsample: depthwise 2x2 stride2 ----------------
__global__ void k_kvconv(const float* __restrict__ x, const float* __restrict__ w,
                         const float* __restrict__ bias, float* __restrict__ out) {
    int idx = blockIdx.x * blockDim.x + threadIdx.x;
    if (idx >= Bn * Cn * NKn) return;
    int p  = idx % NKn;
    int bc = idx / NKn;
    int c  = bc % Cn;
    int oy = p / HKn, ox = p % HKn;
    const float* xin = x + (size_t)bc * Pn;
    const float* wc  = w + c * 4;
    float acc = bias[c];
    acc += wc[0] * xin[(2 * oy) * Wn + 2 * ox];
    acc += wc[1] * xin[(2 * oy) * Wn + 2 * ox + 1];
    acc += wc[2] * xin[(2 * oy + 1) * Wn + 2 * ox];
    acc += wc[3] * xin[(2 * oy + 1) * Wn + 2 * ox + 1];
    out[idx] = acc;
}

// ---------------- fused attention (online softmax), row-major q, channel-major out ----------------
__global__ void __launch_bounds__(256) k_attn(
    const float* __restrict__ q, const float* __restrict__ k,
    const float* __restrict__ v, const float* __restrict__ posT,
    float* __restrict__ outT) {
    extern __shared__ float sm[];
    float* Ks = sm;
    float* Vs = sm + NKn * DKn;
    int b = blockIdx.x >> 3;
    int h = blockIdx.x & 7;
    for (int l = threadIdx.x; l < NKn * 8; l += 256) {
        int j = l >> 3, qv = l & 7;
        size_t src = ((size_t)(b * NKn + j)) * Cn + h * DKn + qv * 4;
        ((float4*)Ks)[l] = *(const float4*)(k + src);
        ((float4*)Vs)[l] = *(const float4*)(v + src);
    }
    __syncthreads();
    const float scale = 0.17677669529663687f;
    for (int i = threadIdx.x; i < Pn; i += 256) {
        float4 qr[8];
        const float4* qp = (const float4*)(q + ((size_t)b * Pn + i) * Cn + h * DKn);
#pragma unroll
        for (int qv = 0; qv < 8; qv++) qr[qv] = qp[qv];
        const float* pt = posT + (size_t)h * NKn * Pn + i;
        float mmax = -1e30f, lsum = 0.f;
        float4 o[8];
#pragma unroll
        for (int qv = 0; qv < 8; qv++) o[qv] = make_float4(0.f, 0.f, 0.f, 0.f);
        for (int j = 0; j < NKn; j++) {
            const float4* k4 = (const float4*)(Ks + j * DKn);
            float s = 0.f;
#pragma unroll
            for (int qv = 0; qv < 8; qv++) {
                float4 kk = k4[qv];
                s += qr[qv].x * kk.x + qr[qv].y * kk.y + qr[qv].z * kk.z + qr[qv].w * kk.w;
            }
            s = s * scale + pt[j * Pn];
            if (s > mmax) {
                float corr = __expf(mmax - s);
                lsum *= corr;
#pragma unroll
                for (int qv = 0; qv < 8; qv++) {
                    o[qv].x *= corr; o[qv].y *= corr; o[qv].z *= corr; o[qv].w *= corr;
                }
                mmax = s;
            }
            float e = __expf(s - mmax);
            lsum += e;
            const float4* v4 = (const float4*)(Vs + j * DKn);
#pragma unroll
            for (int qv = 0; qv < 8; qv++) {
                float4 vv = v4[qv];
                o[qv].x += e * vv.x; o[qv].y += e * vv.y;
                o[qv].z += e * vv.z; o[qv].w += e * vv.w;
            }
        }
        float inv = 1.f / lsum;
        size_t base = ((size_t)(b * Cn + h * DKn)) * Pn + i;
#pragma unroll
        for (int qv = 0; qv < 8; qv++) {
            outT[base + (size_t)(qv * 4 + 0) * Pn] = o[qv].x * inv;
            outT[base + (size_t)(qv * 4 + 1) * Pn] = o[qv].y * inv;
            outT[base + (size_t)(qv * 4 + 2) * Pn] = o[qv].z * inv;
            outT[base + (size_t)(qv * 4 + 3) * Pn] = o[qv].w * inv;
        }
    }
}

// ---------------- host launch ----------------
static void* sym_addr(const void* symbol) {
    void* p = nullptr;
    cudaGetSymbolAddress(&p, symbol);
    return p;
}

extern "C" void kernel_launch(void* const* d_in, const int* in_sizes, int n_in,
                              void* d_out, int out_size) {
    const float* x     = (const float*)d_in[0];
    const float* lpu_w = (const float*)d_in[1];
    const float* lpu_b = (const float*)d_in[2];
    const float* dw_w  = (const float*)d_in[3];
    const float* dw_b  = (const float*)d_in[4];
    const float* wq    = (const float*)d_in[5];
    const float* bq    = (const float*)d_in[6];
    const float* wk    = (const float*)d_in[7];
    const float* bk    = (const float*)d_in[8];
    const float* wv    = (const float*)d_in[9];
    const float* bv    = (const float*)d_in[10];
    const float* wo    = (const float*)d_in[11];
    const float* bo    = (const float*)d_in[12];
    const float* pos_b = (const float*)d_in[13];
    const float* c1_w  = (const float*)d_in[14];
    const float* c1_b  = (const float*)d_in[15];
    const float* bn1_g = (const float*)d_in[16];
    const float* bn1_b = (const float*)d_in[17];
    const float* bn1_m = (const float*)d_in[18];
    const float* bn1_v = (const float*)d_in[19];
    const float* dw2_w = (const float*)d_in[20];
    const float* dw2_b = (const float*)d_in[21];
    const float* bn2_g = (const float*)d_in[22];
    const float* bn2_b = (const float*)d_in[23];
    const float* bn2_m = (const float*)d_in[24];
    const float* bn2_v = (const float*)d_in[25];
    const float* c2_w  = (const float*)d_in[26];
    const float* c2_b  = (const float*)d_in[27];
    const float* bn3_g = (const float*)d_in[28];
    const float* bn3_b = (const float*)d_in[29];
    const float* bn3_m = (const float*)d_in[30];
    const float* bn3_v = (const float*)d_in[31];
    float* out = (float*)d_out;

    float*  x1   = (float*)sym_addr(g_x1);
    float*  qb   = (float*)sym_addr(g_q);
    float*  kvb  = (float*)sym_addr(g_kv);
    float*  kb   = (float*)sym_addr(g_k);
    float*  vb   = (float*)sym_addr(g_v);
    float*  attT = (float*)sym_addr(g_attT);
    float*  x2   = (float*)sym_addr(g_x2);
    float*  t1   = (float*)sym_addr(g_t1);
    float*  t2   = (float*)sym_addr(g_t2);
    float*  wqT  = (float*)sym_addr(g_wqT);
    float*  wkT  = (float*)sym_addr(g_wkT);
    float*  wvT  = (float*)sym_addr(g_wvT);
    float*  woT  = (float*)sym_addr(g_woT);
    float*  c1T  = (float*)sym_addr(g_c1T);
    float*  c2T  = (float*)sym_addr(g_c2T);
    float*  posT = (float*)sym_addr(g_posT);
    float2* part = (float2*)sym_addr(g_part);
    float2* mr   = (float2*)sym_addr(g_mr);

    cudaFuncSetAttribute(k_attn, cudaFuncAttributeMaxDynamicSharedMemorySize,
                         2 * NKn * DKn * (int)sizeof(float));

    dim3 tb(32, 8);
    // weight transposes -> [k][m] layout; pos transpose
    k_transp<<<dim3(8, 8, 1),   tb>>>(wq,   wqT, Cn, Cn);
    k_transp<<<dim3(8, 8, 1),   tb>>>(wk,   wkT, Cn, Cn);
    k_transp<<<dim3(8, 8, 1),   tb>>>(wv,   wvT, Cn, Cn);
    k_transp<<<dim3(8, 8, 1),   tb>>>(wo,   woT, Cn, Cn);
    k_transp<<<dim3(8, 32, 1),  tb>>>(c1_w, c1T, CMn, Cn);
    k_transp<<<dim3(32, 8, 1),  tb>>>(c2_w, c2T, Cn, CMn);
    k_transp<<<dim3(7, 25, 8),  tb>>>(pos_b, posT, Pn, NKn);

    // 1. LPU -> x1 (channel-major)
    k_dwplane<0><<<Bn * Cn, 256>>>(x, lpu_w, lpu_b, nullptr, nullptr, nullptr, nullptr, x1, Cn);
    // 2. LN1 stats
    k_stats_part<<<dim3(Bn, 8), 256>>>(x1, part);
    k_stats_fin<<<1, 256>>>(part, mr);
    // 3. KV downsample (pre-LN x1)
    k_kvconv<<<(Bn * Cn * NKn + 255) / 256, 256>>>(x1, dw_w, dw_b, kvb);
    // 4. Q projection (LN fused in B-load) -> q row-major
    k_mma<0, true><<<dim3(7, 2, Bn), 256, SMEM_MMA>>>(
        wqT, x1, bq, nullptr, nullptr, nullptr, nullptr, mr, nullptr, qb, Cn, Cn, Pn);
    // 5. K, V projections (same mma kernel, P=196)
    k_mma<0, false><<<dim3(2, 2, Bn), 256, SMEM_MMA>>>(
        wkT, kvb, bk, nullptr, nullptr, nullptr, nullptr, nullptr, nullptr, kb, Cn, Cn, NKn);
    k_mma<0, false><<<dim3(2, 2, Bn), 256, SMEM_MMA>>>(
        wvT, kvb, bv, nullptr, nullptr, nullptr, nullptr, nullptr, nullptr, vb, Cn, Cn, NKn);
    // 6. fused attention -> channel-major attT
    k_attn<<<Bn * NH, 256, 2 * NKn * DKn * (int)sizeof(float)>>>(qb, kb, vb, posT, attT);
    // 7. O projection + flat residual -> x2
    k_mma<1, false><<<dim3(7, 2, Bn), 256, SMEM_MMA>>>(
        woT, attT, bo, nullptr, nullptr, nullptr, nullptr, nullptr, x1, x2, Cn, Cn, Pn);
    // 8. LN2 stats
    k_stats_part<<<dim3(Bn, 8), 256>>>(x2, part);
    k_stats_fin<<<1, 256>>>(part, mr);
    // 9. c1 + BN1 + GELU (LN fused in B-load) -> t1 channel-major
    k_mma<2, true><<<dim3(7, 8, Bn), 256, SMEM_MMA>>>(
        c1T, x2, c1_b, bn1_g, bn1_b, bn1_m, bn1_v, mr, nullptr, t1, CMn, Cn, Pn);
    // 10. dw2 + BN2 + GELU -> t2 channel-major
    k_dwplane<1><<<Bn * CMn, 256>>>(t1, dw2_w, dw2_b, bn2_g, bn2_b, bn2_m, bn2_v, t2, CMn);
    // 11. c2 + BN3 + channel-major residual -> d_out
    k_mma<3, false><<<dim3(7, 2, Bn), 256, SMEM_MMA>>>(
        c2T, t2, c2_b, bn3_g, bn3_b, bn3_m, bn3_v, nullptr, x2, out, Cn, CMn, Pn);
}

// round 6
// speedup vs baseline: 2.8078x; 1.1645x over previous
#include <cuda_runtime.h>
#include <cuda_fp16.h>
#include <math.h>
#include <stdint.h>

// ---------------- problem constants ----------------
#define Bn   32
#define Cn   256
#define Hn   28
#define Wn   28
#define Pn   784          // H*W
#define NKn  196          // (H/2)*(W/2)
#define HKn  14
#define CMn  1024         // C * R
#define NH   8
#define DKn  32
#define EPSf 1e-5f

// ---------------- scratch (device globals: allocation-free) ----------------
__device__ float g_x1  [Bn*Cn*Pn];     // after LPU (channel-major)
__device__ float g_q   [Bn*Pn*Cn];     // Q row-major [p][oc]
__device__ float g_kv  [Bn*Cn*NKn];    // stride-2 dw conv out [c][196]
__device__ float g_k   [Bn*NKn*Cn];    // [nk][256] row-major
__device__ float g_v   [Bn*NKn*Cn];
__device__ float g_attT[Bn*Cn*Pn];     // attention out CHANNEL-major [d][p]
__device__ float g_x2  [Bn*Cn*Pn];     // after attn residual (flat)
__device__ float g_t1  [Bn*CMn*Pn];    // IRFFN expand (channel-major)
__device__ float g_t2  [Bn*CMn*Pn];    // after dw2 (channel-major)
__device__ float g_wqT [Cn*Cn];        // [k][m]
__device__ float g_wkT [Cn*Cn];
__device__ float g_wvT [Cn*Cn];
__device__ float g_woT [Cn*Cn];
__device__ float g_c1T [Cn*CMn];       // [256][1024]
__device__ float g_c2T [CMn*Cn];       // [1024][256]
__device__ float g_posT[NH*NKn*Pn];    // pos transposed [h][j][i]
__device__ float2 g_part[Bn*8];
__device__ float2 g_mr  [Bn];          // (mean, rstd) per sample

__device__ __forceinline__ float gelu_f(float v) {
    return 0.5f * v * (1.0f + erff(v * 0.7071067811865475f));
}
__device__ __forceinline__ void mma_f16(float* c, const uint32_t* a, const uint32_t* b) {
    asm volatile(
        "mma.sync.aligned.m16n8k16.row.col.f32.f16.f16.f32 "
        "{%0,%1,%2,%3}, {%4,%5,%6,%7}, {%8,%9}, {%0,%1,%2,%3};"
        : "+f"(c[0]), "+f"(c[1]), "+f"(c[2]), "+f"(c[3])
        : "r"(a[0]), "r"(a[1]), "r"(a[2]), "r"(a[3]), "r"(b[0]), "r"(b[1]));
}
__device__ __forceinline__ uint32_t packh2(float lo, float hi) {
    __half2 h = __floats2half2_rn(lo, hi);
    return *(uint32_t*)&h;
}

// ====================== fp16 mma.sync GEMM, k-paired-half2 smem ======================
// D[m][p] = sum_k WT[k][m] * X[k][p]  (X channel-major per batch, batch stride K*P)
// MODE 0: out[p*M+m] = D + bias[m]
// MODE 1: out[p*M+m] = D + bias[m] + res[p*M+m]      (flat-reinterpret residual)
// MODE 2: out[m*P+p] = gelu(BN(D + bias[m]))
// MODE 3: out[m*P+p] = BN(D + bias[m]) + res[m*P+p]
// LNB: scale X by (v - mean)*rstd from mr[b]
#define H2STR 136                // half2 row stride: 136 mod 32 == 8 -> conflict-free frags
#define KSTR  132                // epilogue float stride
#define SMEM_MMA (64*KSTR*4)     // 33792 B (epilogue dominates; operands use 17408 B)

template <int MODE, bool LNB>
__global__ void __launch_bounds__(256, 2) k_mma(
    const float* __restrict__ WT, const float* __restrict__ X,
    const float* __restrict__ bias,
    const float* __restrict__ bng, const float* __restrict__ bnb,
    const float* __restrict__ bnm, const float* __restrict__ bnv,
    const float2* __restrict__ mr, const float* __restrict__ res,
    float* __restrict__ out, int M, int K, int P) {
    extern __shared__ float sm[];
    __half2* As2 = (__half2*)sm;             // [16][H2STR]: (k-pair, m)
    __half2* Bs2 = As2 + 16 * H2STR;         // [16][H2STR]: (k-pair, p)
    const int tid  = threadIdx.x;
    const int warp = tid >> 5, lane = tid & 31;
    const int gid = lane >> 2, tq = lane & 3;
    const int wm = (warp & 1) * 64;
    const int wn = (warp >> 1) * 32;
    const int b  = blockIdx.z;
    const int m0 = blockIdx.y * 128;
    const int n0 = blockIdx.x * 128;
    const float* Xb = X + (size_t)b * K * P;
    float mean = 0.f, rstd = 1.f;
    if (LNB) { float2 v = mr[b]; mean = v.x; rstd = v.y; }

    float acc[4][4][4];
#pragma unroll
    for (int i = 0; i < 4; i++)
#pragma unroll
        for (int j = 0; j < 4; j++)
#pragma unroll
            for (int r = 0; r < 4; r++) acc[i][j][r] = 0.f;

    const int kk = tid >> 4;         // 0..15 : half2 row (= k pair)
    const int mq = (tid & 15) * 8;   // 0..120 : column start (8 cols per thread)
    uint4 pa0, pa1, pb0, pb1;
    const int T = K >> 5;            // chunks of 32 k

    // ---- chunk loader into registers ----
    auto load_chunk = [&](int kc0) {
        const float* wr0 = WT + (size_t)(kc0 + 2 * kk) * M + m0 + mq;
        const float* wr1 = wr0 + M;
        float4 a0 = *(const float4*)wr0;
        float4 a1 = *(const float4*)(wr0 + 4);
        float4 a2 = *(const float4*)wr1;
        float4 a3 = *(const float4*)(wr1 + 4);
        pa0 = make_uint4(packh2(a0.x, a2.x), packh2(a0.y, a2.y),
                         packh2(a0.z, a2.z), packh2(a0.w, a2.w));
        pa1 = make_uint4(packh2(a1.x, a3.x), packh2(a1.y, a3.y),
                         packh2(a1.z, a3.z), packh2(a1.w, a3.w));
        const float* xr0 = Xb + (size_t)(kc0 + 2 * kk) * P + n0 + mq;
        const float* xr1 = xr0 + P;
        float4 b0 = make_float4(0.f,0.f,0.f,0.f), b1 = b0, b2 = b0, b3 = b0;
        if (n0 + mq + 4 <= P)  { b0 = *(const float4*)xr0; b2 = *(const float4*)xr1; }
        if (n0 + mq + 8 <= P)  { b1 = *(const float4*)(xr0 + 4); b3 = *(const float4*)(xr1 + 4); }
        if (LNB) {
            b0.x=(b0.x-mean)*rstd; b0.y=(b0.y-mean)*rstd; b0.z=(b0.z-mean)*rstd; b0.w=(b0.w-mean)*rstd;
            b1.x=(b1.x-mean)*rstd; b1.y=(b1.y-mean)*rstd; b1.z=(b1.z-mean)*rstd; b1.w=(b1.w-mean)*rstd;
            b2.x=(b2.x-mean)*rstd; b2.y=(b2.y-mean)*rstd; b2.z=(b2.z-mean)*rstd; b2.w=(b2.w-mean)*rstd;
            b3.x=(b3.x-mean)*rstd; b3.y=(b3.y-mean)*rstd; b3.z=(b3.z-mean)*rstd; b3.w=(b3.w-mean)*rstd;
        }
        pb0 = make_uint4(packh2(b0.x, b2.x), packh2(b0.y, b2.y),
                         packh2(b0.z, b2.z), packh2(b0.w, b2.w));
        pb1 = make_uint4(packh2(b1.x, b3.x), packh2(b1.y, b3.y),
                         packh2(b1.z, b3.z), packh2(b1.w, b3.w));
    };
    auto store_chunk = [&]() {
        *(uint4*)&As2[kk * H2STR + mq]     = pa0;
        *(uint4*)&As2[kk * H2STR + mq + 4] = pa1;
        *(uint4*)&Bs2[kk * H2STR + mq]     = pb0;
        *(uint4*)&Bs2[kk * H2STR + mq + 4] = pb1;
    };

    load_chunk(0);
    store_chunk();
    __syncthreads();

    for (int t = 0; t < T; t++) {
        if (t + 1 < T) load_chunk((t + 1) << 5);
#pragma unroll
        for (int ks = 0; ks < 2; ks++) {
            const int r0 = ks * 8;
            uint32_t af[4][4], bf[4][2];
#pragma unroll
            for (int i = 0; i < 4; i++) {
                int m = wm + i * 16 + gid;
                af[i][0] = *(uint32_t*)&As2[(r0 + tq) * H2STR + m];
                af[i][1] = *(uint32_t*)&As2[(r0 + tq) * H2STR + m + 8];
                af[i][2] = *(uint32_t*)&As2[(r0 + tq + 4) * H2STR + m];
                af[i][3] = *(uint32_t*)&As2[(r0 + tq + 4) * H2STR + m + 8];
            }
#pragma unroll
            for (int j = 0; j < 4; j++) {
                int p = wn + j * 8 + gid;
                bf[j][0] = *(uint32_t*)&Bs2[(r0 + tq) * H2STR + p];
                bf[j][1] = *(uint32_t*)&Bs2[(r0 + tq + 4) * H2STR + p];
            }
#pragma unroll
            for (int i = 0; i < 4; i++)
#pragma unroll
                for (int j = 0; j < 4; j++) mma_f16(acc[i][j], af[i], bf[j]);
        }
        if (t + 1 < T) {
            __syncthreads();
            store_chunk();
            __syncthreads();
        }
    }

    // ---- epilogue: two 64-row passes staged through smem ----
    float* sD = sm;  // [64][KSTR]
    float* outb = out + (size_t)b * (size_t)M * P;
    const float* resb = (MODE == 1 || MODE == 3) ? res + (size_t)b * (size_t)M * P : nullptr;

#pragma unroll
    for (int pass = 0; pass < 2; pass++) {
        __syncthreads();
        if (MODE <= 1) {
            if ((wn >> 6) == pass) {
#pragma unroll
                for (int i = 0; i < 4; i++) {
                    int mrow = wm + i * 16 + gid;
#pragma unroll
                    for (int j = 0; j < 4; j++) {
                        int pc = (wn & 63) + j * 8 + 2 * tq;
                        sD[pc * KSTR + mrow]           = acc[i][j][0];
                        sD[(pc + 1) * KSTR + mrow]     = acc[i][j][1];
                        sD[pc * KSTR + mrow + 8]       = acc[i][j][2];
                        sD[(pc + 1) * KSTR + mrow + 8] = acc[i][j][3];
                    }
                }
            }
        } else {
            if ((wm >> 6) == pass) {
#pragma unroll
                for (int i = 0; i < 4; i++) {
                    int ml = (wm & 63) + i * 16 + gid;
#pragma unroll
                    for (int j = 0; j < 4; j++) {
                        int pc = wn + j * 8 + 2 * tq;
                        sD[ml * KSTR + pc]           = acc[i][j][0];
                        sD[ml * KSTR + pc + 1]       = acc[i][j][1];
                        sD[(ml + 8) * KSTR + pc]     = acc[i][j][2];
                        sD[(ml + 8) * KSTR + pc + 1] = acc[i][j][3];
                    }
                }
            }
        }
        __syncthreads();
        if (MODE <= 1) {
            for (int l = tid; l < 64 * 32; l += 256) {
                int rl = l >> 5, cq = (l & 31) * 4;
                int p = n0 + pass * 64 + rl;
                if (p >= P) continue;
                float4 v = *(float4*)&sD[rl * KSTR + cq];
                float4 bb = *(const float4*)(bias + m0 + cq);
                v.x += bb.x; v.y += bb.y; v.z += bb.z; v.w += bb.w;
                size_t off = (size_t)p * M + m0 + cq;
                if (MODE == 1) {
                    float4 rr = *(const float4*)(resb + off);
                    v.x += rr.x; v.y += rr.y; v.z += rr.z; v.w += rr.w;
                }
                *(float4*)(outb + off) = v;
            }
        } else {
            for (int l = tid; l < 64 * 32; l += 256) {
                int rl = l >> 5, cq = (l & 31) * 4;
                int m = m0 + pass * 64 + rl;
                int p = n0 + cq;
                if (p >= P) continue;
                float scale = bng[m] * rsqrtf(bnv[m] + EPSf);
                float shift = bnb[m] - bnm[m] * scale + bias[m] * scale;
                float4 v = *(float4*)&sD[rl * KSTR + cq];
                v.x = v.x * scale + shift; v.y = v.y * scale + shift;
                v.z = v.z * scale + shift; v.w = v.w * scale + shift;
                if (MODE == 2) { v.x = gelu_f(v.x); v.y = gelu_f(v.y); v.z = gelu_f(v.z); v.w = gelu_f(v.w); }
                size_t off = (size_t)m * P + p;
                if (MODE == 3) {
                    float4 rr = *(const float4*)(resb + off);
                    v.x += rr.x; v.y += rr.y; v.z += rr.z; v.w += rr.w;
                }
                *(float4*)(outb + off) = v;
            }
        }
    }
}

// ---------------- generic tiled transpose: in[R][C] -> out[C][R], batched z ----------------
__global__ void k_transp(const float* __restrict__ in, float* __restrict__ out,
                         int R, int C) {
    __shared__ float t[32][33];
    size_t boff = (size_t)blockIdx.z * R * C;
    in  += boff;
    out += boff;
    int c0 = blockIdx.x * 32, r0 = blockIdx.y * 32;
#pragma unroll
    for (int q = 0; q < 32; q += 8) {
        int r = r0 + threadIdx.y + q, c = c0 + threadIdx.x;
        if (r < R && c < C) t[threadIdx.y + q][threadIdx.x] = in[(size_t)r * C + c];
    }
    __syncthreads();
#pragma unroll
    for (int q = 0; q < 32; q += 8) {
        int c = c0 + threadIdx.y + q, r = r0 + threadIdx.x;
        if (r < R && c < C) out[(size_t)c * R + r] = t[threadIdx.x][threadIdx.y + q];
    }
}

// ---- merged 4x 256x256 transpose (wq, wk, wv, wo) ----
__global__ void k_transp4(const float* __restrict__ p0, const float* __restrict__ p1,
                          const float* __restrict__ p2, const float* __restrict__ p3,
                          float* __restrict__ o0, float* __restrict__ o1,
                          float* __restrict__ o2, float* __restrict__ o3) {
    __shared__ float t[32][33];
    const float* in  = (blockIdx.z == 0) ? p0 : (blockIdx.z == 1) ? p1 : (blockIdx.z == 2) ? p2 : p3;
    float*       out = (blockIdx.z == 0) ? o0 : (blockIdx.z == 1) ? o1 : (blockIdx.z == 2) ? o2 : o3;
    int c0 = blockIdx.x * 32, r0 = blockIdx.y * 32;
#pragma unroll
    for (int q = 0; q < 32; q += 8)
        t[threadIdx.y + q][threadIdx.x] = in[(size_t)(r0 + threadIdx.y + q) * Cn + c0 + threadIdx.x];
    __syncthreads();
#pragma unroll
    for (int q = 0; q < 32; q += 8)
        out[(size_t)(c0 + threadIdx.y + q) * Cn + r0 + threadIdx.x] = t[threadIdx.x][threadIdx.y + q];
}

// ---------------- depthwise 3x3 pad1, padded-smem plane (no bounds predicates) ----------------
// MODE 0: LPU  -> out = conv + bias + input
// MODE 1: dw2  -> out = gelu(BN(conv + bias))
template <int MODE>
__global__ void __launch_bounds__(256) k_dwplane(
    const float* __restrict__ X, const float* __restrict__ w,
    const float* __restrict__ bias,
    const float* __restrict__ bng, const float* __restrict__ bnb,
    const float* __restrict__ bnm, const float* __restrict__ bnv,
    float* __restrict__ out, int CH) {
    __shared__ float sp[30 * 30];
    int bc = blockIdx.x;
    int c  = bc % CH;
    const float* xin = X + (size_t)bc * Pn;
    for (int i = threadIdx.x; i < 900; i += 256) sp[i] = 0.f;
    float wc[9];
#pragma unroll
    for (int i = 0; i < 9; i++) wc[i] = w[c * 9 + i];
    float bsv = bias[c];
    float scale = 0.f, shift = 0.f;
    if (MODE == 1) {
        scale = bng[c] * rsqrtf(bnv[c] + EPSf);
        shift = bnb[c] - bnm[c] * scale;
    }
    __syncthreads();
    for (int i = threadIdx.x; i < Pn; i += 256) {
        int py = i / Wn, px = i - py * Wn;
        sp[(py + 1) * 30 + px + 1] = xin[i];
    }
    __syncthreads();
    for (int p = threadIdx.x; p < Pn; p += 256) {
        int py = p / Wn, px = p - py * Wn;
        const float* s0 = sp + py * 30 + px;
        float acc = bsv;
        acc += wc[0] * s0[0]  + wc[1] * s0[1]  + wc[2] * s0[2];
        acc += wc[3] * s0[30] + wc[4] * s0[31] + wc[5] * s0[32];
        acc += wc[6] * s0[60] + wc[7] * s0[61] + wc[8] * s0[62];
        float y;
        if (MODE == 0) y = acc + s0[31];
        else           y = gelu_f(acc * scale + shift);
        out[(size_t)bc * Pn + p] = y;
    }
}

// ---------------- LN stats ----------------
__global__ void k_stats_part(const float* __restrict__ src, float2* __restrict__ part) {
    int b = blockIdx.x, ch = blockIdx.y;
    const float4* s = (const float4*)(src + (size_t)b * Cn * Pn + (size_t)ch * (Cn * Pn / 8));
    const int nv = (Cn * Pn / 8) / 4;
    float sum = 0.f, sq = 0.f;
    for (int i = threadIdx.x; i < nv; i += 256) {
        float4 v = s[i];
        sum += v.x + v.y + v.z + v.w;
        sq  += v.x * v.x + v.y * v.y + v.z * v.z + v.w * v.w;
    }
    __shared__ float r1[256], r2[256];
    r1[threadIdx.x] = sum; r2[threadIdx.x] = sq;
    __syncthreads();
    for (int st = 128; st > 0; st >>= 1) {
        if (threadIdx.x < st) {
            r1[threadIdx.x] += r1[threadIdx.x + st];
            r2[threadIdx.x] += r2[threadIdx.x + st];
        }
        __syncthreads();
    }
    if (threadIdx.x == 0) part[b * 8 + ch] = make_float2(r1[0], r2[0]);
}

__global__ void k_stats_fin(const float2* __restrict__ part, float2* __restrict__ mr) {
    int t = threadIdx.x;
    float2 p = part[t];
#pragma unroll
    for (int o = 4; o >= 1; o >>= 1) {
        p.x += __shfl_down_sync(0xffffffffu, p.x, o, 8);
        p.y += __shfl_down_sync(0xffffffffu, p.y, o, 8);
    }
    if ((t & 7) == 0) {
        const float n = (float)(Cn * Pn);
        float m  = p.x / n;
        float vv = p.y / n - m * m;
        mr[t >> 3] = make_float2(m, rsqrtf(vv + EPSf));
    }
}

// ---------------- KV downsample: depthwise 2x2 stride2 ----------------
__global__ void k_kvconv(const float* __restrict__ x, const float* __restrict__ w,
                         const float* __restrict__ bias, float* __restrict__ out) {
    int idx = blockIdx.x * blockDim.x + threadIdx.x;
    if (idx >= Bn * Cn * NKn) return;
    int p  = idx % NKn;
    int bc = idx / NKn;
    int c  = bc % Cn;
    int oy = p / HKn, ox = p % HKn;
    const float* xin = x + (size_t)bc * Pn;
    const float* wc  = w + c * 4;
    float acc = bias[c];
    acc += wc[0] * xin[(2 * oy) * Wn + 2 * ox];
    acc += wc[1] * xin[(2 * oy) * Wn + 2 * ox + 1];
    acc += wc[2] * xin[(2 * oy + 1) * Wn + 2 * ox];
    acc += wc[3] * xin[(2 * oy + 1) * Wn + 2 * ox + 1];
    out[idx] = acc;
}

// ---------------- fused attention (online softmax), row-major q, channel-major out ----------------
__global__ void __launch_bounds__(256) k_attn(
    const float* __restrict__ q, const float* __restrict__ k,
    const float* __restrict__ v, const float* __restrict__ posT,
    float* __restrict__ outT) {
    extern __shared__ float sm[];
    float* Ks = sm;
    float* Vs = sm + NKn * DKn;
    int b = blockIdx.x >> 3;
    int h = blockIdx.x & 7;
    for (int l = threadIdx.x; l < NKn * 8; l += 256) {
        int j = l >> 3, qv = l & 7;
        size_t src = ((size_t)(b * NKn + j)) * Cn + h * DKn + qv * 4;
        ((float4*)Ks)[l] = *(const float4*)(k + src);
        ((float4*)Vs)[l] = *(const float4*)(v + src);
    }
    __syncthreads();
    const float scale = 0.17677669529663687f;
    for (int i = threadIdx.x; i < Pn; i += 256) {
        float4 qr[8];
        const float4* qp = (const float4*)(q + ((size_t)b * Pn + i) * Cn + h * DKn);
#pragma unroll
        for (int qv = 0; qv < 8; qv++) qr[qv] = qp[qv];
        const float* pt = posT + (size_t)h * NKn * Pn + i;
        float mmax = -1e30f, lsum = 0.f;
        float4 o[8];
#pragma unroll
        for (int qv = 0; qv < 8; qv++) o[qv] = make_float4(0.f, 0.f, 0.f, 0.f);
        for (int j = 0; j < NKn; j++) {
            const float4* k4 = (const float4*)(Ks + j * DKn);
            float s = 0.f;
#pragma unroll
            for (int qv = 0; qv < 8; qv++) {
                float4 kk = k4[qv];
                s += qr[qv].x * kk.x + qr[qv].y * kk.y + qr[qv].z * kk.z + qr[qv].w * kk.w;
            }
            s = s * scale + pt[j * Pn];
            if (s > mmax) {
                float corr = __expf(mmax - s);
                lsum *= corr;
#pragma unroll
                for (int qv = 0; qv < 8; qv++) {
                    o[qv].x *= corr; o[qv].y *= corr; o[qv].z *= corr; o[qv].w *= corr;
                }
                mmax = s;
            }
            float e = __expf(s - mmax);
            lsum += e;
            const float4* v4 = (const float4*)(Vs + j * DKn);
#pragma unroll
            for (int qv = 0; qv < 8; qv++) {
                float4 vv = v4[qv];
                o[qv].x += e * vv.x; o[qv].y += e * vv.y;
                o[qv].z += e * vv.z; o[qv].w += e * vv.w;
            }
        }
        float inv = 1.f / lsum;
        size_t base = ((size_t)(b * Cn + h * DKn)) * Pn + i;
#pragma unroll
        for (int qv = 0; qv < 8; qv++) {
            outT[base + (size_t)(qv * 4 + 0) * Pn] = o[qv].x * inv;
            outT[base + (size_t)(qv * 4 + 1) * Pn] = o[qv].y * inv;
            outT[base + (size_t)(qv * 4 + 2) * Pn] = o[qv].z * inv;
            outT[base + (size_t)(qv * 4 + 3) * Pn] = o[qv].w * inv;
        }
    }
}

// ---------------- host launch ----------------
static void* sym_addr(const void* symbol) {
    void* p = nullptr;
    cudaGetSymbolAddress(&p, symbol);
    return p;
}

extern "C" void kernel_launch(void* const* d_in, const int* in_sizes, int n_in,
                              void* d_out, int out_size) {
    const float* x     = (const float*)d_in[0];
    const float* lpu_w = (const float*)d_in[1];
    const float* lpu_b = (const float*)d_in[2];
    const float* dw_w  = (const float*)d_in[3];
    const float* dw_b  = (const float*)d_in[4];
    const float* wq    = (const float*)d_in[5];
    const float* bq    = (const float*)d_in[6];
    const float* wk    = (const float*)d_in[7];
    const float* bk    = (const float*)d_in[8];
    const float* wv    = (const float*)d_in[9];
    const float* bv    = (const float*)d_in[10];
    const float* wo    = (const float*)d_in[11];
    const float* bo    = (const float*)d_in[12];
    const float* pos_b = (const float*)d_in[13];
    const float* c1_w  = (const float*)d_in[14];
    const float* c1_b  = (const float*)d_in[15];
    const float* bn1_g = (const float*)d_in[16];
    const float* bn1_b = (const float*)d_in[17];
    const float* bn1_m = (const float*)d_in[18];
    const float* bn1_v = (const float*)d_in[19];
    const float* dw2_w = (const float*)d_in[20];
    const float* dw2_b = (const float*)d_in[21];
    const float* bn2_g = (const float*)d_in[22];
    const float* bn2_b = (const float*)d_in[23];
    const float* bn2_m = (const float*)d_in[24];
    const float* bn2_v = (const float*)d_in[25];
    const float* c2_w  = (const float*)d_in[26];
    const float* c2_b  = (const float*)d_in[27];
    const float* bn3_g = (const float*)d_in[28];
    const float* bn3_b = (const float*)d_in[29];
    const float* bn3_m = (const float*)d_in[30];
    const float* bn3_v = (const float*)d_in[31];
    float* out = (float*)d_out;

    float*  x1   = (float*)sym_addr(g_x1);
    float*  qb   = (float*)sym_addr(g_q);
    float*  kvb  = (float*)sym_addr(g_kv);
    float*  kb   = (float*)sym_addr(g_k);
    float*  vb   = (float*)sym_addr(g_v);
    float*  attT = (float*)sym_addr(g_attT);
    float*  x2   = (float*)sym_addr(g_x2);
    float*  t1   = (float*)sym_addr(g_t1);
    float*  t2   = (float*)sym_addr(g_t2);
    float*  wqT  = (float*)sym_addr(g_wqT);
    float*  wkT  = (float*)sym_addr(g_wkT);
    float*  wvT  = (float*)sym_addr(g_wvT);
    float*  woT  = (float*)sym_addr(g_woT);
    float*  c1T  = (float*)sym_addr(g_c1T);
    float*  c2T  = (float*)sym_addr(g_c2T);
    float*  posT = (float*)sym_addr(g_posT);
    float2* part = (float2*)sym_addr(g_part);
    float2* mr   = (float2*)sym_addr(g_mr);

    cudaFuncSetAttribute(k_attn, cudaFuncAttributeMaxDynamicSharedMemorySize,
                         2 * NKn * DKn * (int)sizeof(float));

    dim3 tb(32, 8);
    // weight transposes -> [k][m] layout; pos transpose
    k_transp4<<<dim3(8, 8, 4), tb>>>(wq, wk, wv, wo, wqT, wkT, wvT, woT);
    k_transp<<<dim3(8, 32, 1), tb>>>(c1_w, c1T, CMn, Cn);
    k_transp<<<dim3(32, 8, 1), tb>>>(c2_w, c2T, Cn, CMn);
    k_transp<<<dim3(7, 25, 8), tb>>>(pos_b, posT, Pn, NKn);

    // 1. LPU -> x1 (channel-major)
    k_dwplane<0><<<Bn * Cn, 256>>>(x, lpu_w, lpu_b, nullptr, nullptr, nullptr, nullptr, x1, Cn);
    // 2. LN1 stats
    k_stats_part<<<dim3(Bn, 8), 256>>>(x1, part);
    k_stats_fin<<<1, 256>>>(part, mr);
    // 3. KV downsample (pre-LN x1)
    k_kvconv<<<(Bn * Cn * NKn + 255) / 256, 256>>>(x1, dw_w, dw_b, kvb);
    // 4. Q projection (LN fused in B-load) -> q row-major
    k_mma<0, true><<<dim3(7, 2, Bn), 256, SMEM_MMA>>>(
        wqT, x1, bq, nullptr, nullptr, nullptr, nullptr, mr, nullptr, qb, Cn, Cn, Pn);
    // 5. K, V projections
    k_mma<0, false><<<dim3(2, 2, Bn), 256, SMEM_MMA>>>(
        wkT, kvb, bk, nullptr, nullptr, nullptr, nullptr, nullptr, nullptr, kb, Cn, Cn, NKn);
    k_mma<0, false><<<dim3(2, 2, Bn), 256, SMEM_MMA>>>(
        wvT, kvb, bv, nullptr, nullptr, nullptr, nullptr, nullptr, nullptr, vb, Cn, Cn, NKn);
    // 6. fused attention -> channel-major attT
    k_attn<<<Bn * NH, 256, 2 * NKn * DKn * (int)sizeof(float)>>>(qb, kb, vb, posT, attT);
    // 7. O projection + flat residual -> x2
    k_mma<1, false><<<dim3(7, 2, Bn), 256, SMEM_MMA>>>(
        woT, attT, bo, nullptr, nullptr, nullptr, nullptr, nullptr, x1, x2, Cn, Cn, Pn);
    // 8. LN2 stats
    k_stats_part<<<dim3(Bn, 8), 256>>>(x2, part);
    k_stats_fin<<<1, 256>>>(part, mr);
    // 9. c1 + BN1 + GELU (LN fused in B-load) -> t1 channel-major
    k_mma<2, true><<<dim3(7, 8, Bn), 256, SMEM_MMA>>>(
        c1T, x2, c1_b, bn1_g, bn1_b, bn1_m, bn1_v, mr, nullptr, t1, CMn, Cn, Pn);
    // 10. dw2 + BN2 + GELU -> t2 channel-major
    k_dwplane<1><<<Bn * CMn, 256>>>(t1, dw2_w, dw2_b, bn2_g, bn2_b, bn2_m, bn2_v, t2, CMn);
    // 11. c2 + BN3 + channel-major residual -> d_out
    k_mma<3, false><<<dim3(7, 2, Bn), 256, SMEM_MMA>>>(
        c2T, t2, c2_b, bn3_g, bn3_b, bn3_m, bn3_v, nullptr, x2, out, Cn, CMn, Pn);
}

// round 7
// speedup vs baseline: 3.6669x; 1.3060x over previous
#include <cuda_runtime.h>
#include <cuda_fp16.h>
#include <math.h>
#include <stdint.h>

// ---------------- problem constants ----------------
#define Bn   32
#define Cn   256
#define Hn   28
#define Wn   28
#define Pn   784          // H*W
#define NKn  196          // (H/2)*(W/2)
#define HKn  14
#define CMn  1024         // C * R
#define NH   8
#define DKn  32
#define EPSf 1e-5f

// ---------------- scratch (device globals: allocation-free) ----------------
__device__ float g_x1  [Bn*Cn*Pn];     // after LPU (channel-major)
__device__ float g_q   [Bn*Pn*Cn];     // Q row-major [p][oc]
__device__ float g_kv  [Bn*Cn*NKn];    // stride-2 dw conv out [c][196]
__device__ float g_k   [Bn*NKn*Cn];    // [nk][256] row-major
__device__ float g_v   [Bn*NKn*Cn];
__device__ float g_attT[Bn*Cn*Pn];     // attention out CHANNEL-major [d][p]
__device__ float g_x2  [Bn*Cn*Pn];     // after attn residual (flat)
__device__ float g_t1  [Bn*CMn*Pn];    // IRFFN expand (channel-major)
__device__ float g_t2  [Bn*CMn*Pn];    // after dw2 (channel-major)
__device__ float g_wqT [Cn*Cn];        // [k][m]
__device__ float g_wkT [Cn*Cn];
__device__ float g_wvT [Cn*Cn];
__device__ float g_woT [Cn*Cn];
__device__ float g_c1T [Cn*CMn];       // [256][1024]
__device__ float g_c2T [CMn*Cn];       // [1024][256]
__device__ float2 g_part[Bn*8];
__device__ float2 g_mr  [Bn];          // (mean, rstd) per sample

__device__ __forceinline__ float gelu_f(float v) {
    return 0.5f * v * (1.0f + erff(v * 0.7071067811865475f));
}
__device__ __forceinline__ void mma_f16(float* c, const uint32_t* a, const uint32_t* b) {
    asm volatile(
        "mma.sync.aligned.m16n8k16.row.col.f32.f16.f16.f32 "
        "{%0,%1,%2,%3}, {%4,%5,%6,%7}, {%8,%9}, {%0,%1,%2,%3};"
        : "+f"(c[0]), "+f"(c[1]), "+f"(c[2]), "+f"(c[3])
        : "r"(a[0]), "r"(a[1]), "r"(a[2]), "r"(a[3]), "r"(b[0]), "r"(b[1]));
}
__device__ __forceinline__ uint32_t packh2(float lo, float hi) {
    __half2 h = __floats2half2_rn(lo, hi);
    return *(uint32_t*)&h;
}

// ====================== fp16 mma.sync GEMM, k-paired-half2 smem ======================
// D[m][p] = sum_k WT[k][m] * X[k][p]  (X channel-major per batch, batch stride K*P)
// MODE 0: out[p*M+m] = D + bias[m]
// MODE 1: out[p*M+m] = D + bias[m] + res[p*M+m]      (flat-reinterpret residual)
// MODE 2: out[m*P+p] = gelu(BN(D + bias[m]))
// MODE 3: out[m*P+p] = BN(D + bias[m]) + res[m*P+p]
// LNB: scale X by (v - mean)*rstd from mr[b]
#define H2STR 136                // half2 row stride: 136 mod 32 == 8 -> conflict-free frags
#define KSTR  132                // epilogue float stride
#define SMEM_MMA (64*KSTR*4)     // 33792 B (epilogue dominates; operands use 17408 B)

template <int MODE, bool LNB>
__global__ void __launch_bounds__(256, 2) k_mma(
    const float* __restrict__ WT, const float* __restrict__ X,
    const float* __restrict__ bias,
    const float* __restrict__ bng, const float* __restrict__ bnb,
    const float* __restrict__ bnm, const float* __restrict__ bnv,
    const float2* __restrict__ mr, const float* __restrict__ res,
    float* __restrict__ out, int M, int K, int P) {
    extern __shared__ float sm[];
    __half2* As2 = (__half2*)sm;             // [16][H2STR]: (k-pair, m)
    __half2* Bs2 = As2 + 16 * H2STR;         // [16][H2STR]: (k-pair, p)
    const int tid  = threadIdx.x;
    const int warp = tid >> 5, lane = tid & 31;
    const int gid = lane >> 2, tq = lane & 3;
    const int wm = (warp & 1) * 64;
    const int wn = (warp >> 1) * 32;
    const int b  = blockIdx.z;
    const int m0 = blockIdx.y * 128;
    const int n0 = blockIdx.x * 128;
    const float* Xb = X + (size_t)b * K * P;
    float mean = 0.f, rstd = 1.f;
    if (LNB) { float2 v = mr[b]; mean = v.x; rstd = v.y; }

    float acc[4][4][4];
#pragma unroll
    for (int i = 0; i < 4; i++)
#pragma unroll
        for (int j = 0; j < 4; j++)
#pragma unroll
            for (int r = 0; r < 4; r++) acc[i][j][r] = 0.f;

    const int kk = tid >> 4;         // 0..15 : half2 row (= k pair)
    const int mq = (tid & 15) * 8;   // 0..120 : column start (8 cols per thread)
    uint4 pa0, pa1, pb0, pb1;
    const int T = K >> 5;            // chunks of 32 k

    auto load_chunk = [&](int kc0) {
        const float* wr0 = WT + (size_t)(kc0 + 2 * kk) * M + m0 + mq;
        const float* wr1 = wr0 + M;
        float4 a0 = *(const float4*)wr0;
        float4 a1 = *(const float4*)(wr0 + 4);
        float4 a2 = *(const float4*)wr1;
        float4 a3 = *(const float4*)(wr1 + 4);
        pa0 = make_uint4(packh2(a0.x, a2.x), packh2(a0.y, a2.y),
                         packh2(a0.z, a2.z), packh2(a0.w, a2.w));
        pa1 = make_uint4(packh2(a1.x, a3.x), packh2(a1.y, a3.y),
                         packh2(a1.z, a3.z), packh2(a1.w, a3.w));
        const float* xr0 = Xb + (size_t)(kc0 + 2 * kk) * P + n0 + mq;
        const float* xr1 = xr0 + P;
        float4 b0 = make_float4(0.f,0.f,0.f,0.f), b1 = b0, b2 = b0, b3 = b0;
        if (n0 + mq + 4 <= P)  { b0 = *(const float4*)xr0; b2 = *(const float4*)xr1; }
        if (n0 + mq + 8 <= P)  { b1 = *(const float4*)(xr0 + 4); b3 = *(const float4*)(xr1 + 4); }
        if (LNB) {
            b0.x=(b0.x-mean)*rstd; b0.y=(b0.y-mean)*rstd; b0.z=(b0.z-mean)*rstd; b0.w=(b0.w-mean)*rstd;
            b1.x=(b1.x-mean)*rstd; b1.y=(b1.y-mean)*rstd; b1.z=(b1.z-mean)*rstd; b1.w=(b1.w-mean)*rstd;
            b2.x=(b2.x-mean)*rstd; b2.y=(b2.y-mean)*rstd; b2.z=(b2.z-mean)*rstd; b2.w=(b2.w-mean)*rstd;
            b3.x=(b3.x-mean)*rstd; b3.y=(b3.y-mean)*rstd; b3.z=(b3.z-mean)*rstd; b3.w=(b3.w-mean)*rstd;
        }
        pb0 = make_uint4(packh2(b0.x, b2.x), packh2(b0.y, b2.y),
                         packh2(b0.z, b2.z), packh2(b0.w, b2.w));
        pb1 = make_uint4(packh2(b1.x, b3.x), packh2(b1.y, b3.y),
                         packh2(b1.z, b3.z), packh2(b1.w, b3.w));
    };
    auto store_chunk = [&]() {
        *(uint4*)&As2[kk * H2STR + mq]     = pa0;
        *(uint4*)&As2[kk * H2STR + mq + 4] = pa1;
        *(uint4*)&Bs2[kk * H2STR + mq]     = pb0;
        *(uint4*)&Bs2[kk * H2STR + mq + 4] = pb1;
    };

    load_chunk(0);
    store_chunk();
    __syncthreads();

    for (int t = 0; t < T; t++) {
        if (t + 1 < T) load_chunk((t + 1) << 5);
#pragma unroll
        for (int ks = 0; ks < 2; ks++) {
            const int r0 = ks * 8;
            uint32_t af[4][4], bf[4][2];
#pragma unroll
            for (int i = 0; i < 4; i++) {
                int m = wm + i * 16 + gid;
                af[i][0] = *(uint32_t*)&As2[(r0 + tq) * H2STR + m];
                af[i][1] = *(uint32_t*)&As2[(r0 + tq) * H2STR + m + 8];
                af[i][2] = *(uint32_t*)&As2[(r0 + tq + 4) * H2STR + m];
                af[i][3] = *(uint32_t*)&As2[(r0 + tq + 4) * H2STR + m + 8];
            }
#pragma unroll
            for (int j = 0; j < 4; j++) {
                int p = wn + j * 8 + gid;
                bf[j][0] = *(uint32_t*)&Bs2[(r0 + tq) * H2STR + p];
                bf[j][1] = *(uint32_t*)&Bs2[(r0 + tq + 4) * H2STR + p];
            }
#pragma unroll
            for (int i = 0; i < 4; i++)
#pragma unroll
                for (int j = 0; j < 4; j++) mma_f16(acc[i][j], af[i], bf[j]);
        }
        if (t + 1 < T) {
            __syncthreads();
            store_chunk();
            __syncthreads();
        }
    }

    // ---- epilogue: two 64-row passes staged through smem ----
    float* sD = sm;  // [64][KSTR]
    float* outb = out + (size_t)b * (size_t)M * P;
    const float* resb = (MODE == 1 || MODE == 3) ? res + (size_t)b * (size_t)M * P : nullptr;

#pragma unroll
    for (int pass = 0; pass < 2; pass++) {
        __syncthreads();
        if (MODE <= 1) {
            if ((wn >> 6) == pass) {
#pragma unroll
                for (int i = 0; i < 4; i++) {
                    int mrow = wm + i * 16 + gid;
#pragma unroll
                    for (int j = 0; j < 4; j++) {
                        int pc = (wn & 63) + j * 8 + 2 * tq;
                        sD[pc * KSTR + mrow]           = acc[i][j][0];
                        sD[(pc + 1) * KSTR + mrow]     = acc[i][j][1];
                        sD[pc * KSTR + mrow + 8]       = acc[i][j][2];
                        sD[(pc + 1) * KSTR + mrow + 8] = acc[i][j][3];
                    }
                }
            }
        } else {
            if ((wm >> 6) == pass) {
#pragma unroll
                for (int i = 0; i < 4; i++) {
                    int ml = (wm & 63) + i * 16 + gid;
#pragma unroll
                    for (int j = 0; j < 4; j++) {
                        int pc = wn + j * 8 + 2 * tq;
                        sD[ml * KSTR + pc]           = acc[i][j][0];
                        sD[ml * KSTR + pc + 1]       = acc[i][j][1];
                        sD[(ml + 8) * KSTR + pc]     = acc[i][j][2];
                        sD[(ml + 8) * KSTR + pc + 1] = acc[i][j][3];
                    }
                }
            }
        }
        __syncthreads();
        if (MODE <= 1) {
            for (int l = tid; l < 64 * 32; l += 256) {
                int rl = l >> 5, cq = (l & 31) * 4;
                int p = n0 + pass * 64 + rl;
                if (p >= P) continue;
                float4 v = *(float4*)&sD[rl * KSTR + cq];
                float4 bb = *(const float4*)(bias + m0 + cq);
                v.x += bb.x; v.y += bb.y; v.z += bb.z; v.w += bb.w;
                size_t off = (size_t)p * M + m0 + cq;
                if (MODE == 1) {
                    float4 rr = *(const float4*)(resb + off);
                    v.x += rr.x; v.y += rr.y; v.z += rr.z; v.w += rr.w;
                }
                *(float4*)(outb + off) = v;
            }
        } else {
            for (int l = tid; l < 64 * 32; l += 256) {
                int rl = l >> 5, cq = (l & 31) * 4;
                int m = m0 + pass * 64 + rl;
                int p = n0 + cq;
                if (p >= P) continue;
                float scale = bng[m] * rsqrtf(bnv[m] + EPSf);
                float shift = bnb[m] - bnm[m] * scale + bias[m] * scale;
                float4 v = *(float4*)&sD[rl * KSTR + cq];
                v.x = v.x * scale + shift; v.y = v.y * scale + shift;
                v.z = v.z * scale + shift; v.w = v.w * scale + shift;
                if (MODE == 2) { v.x = gelu_f(v.x); v.y = gelu_f(v.y); v.z = gelu_f(v.z); v.w = gelu_f(v.w); }
                size_t off = (size_t)m * P + p;
                if (MODE == 3) {
                    float4 rr = *(const float4*)(resb + off);
                    v.x += rr.x; v.y += rr.y; v.z += rr.z; v.w += rr.w;
                }
                *(float4*)(outb + off) = v;
            }
        }
    }
}

// ---------------- generic tiled transpose ----------------
__global__ void k_transp(const float* __restrict__ in, float* __restrict__ out,
                         int R, int C) {
    __shared__ float t[32][33];
    size_t boff = (size_t)blockIdx.z * R * C;
    in  += boff;
    out += boff;
    int c0 = blockIdx.x * 32, r0 = blockIdx.y * 32;
#pragma unroll
    for (int q = 0; q < 32; q += 8) {
        int r = r0 + threadIdx.y + q, c = c0 + threadIdx.x;
        if (r < R && c < C) t[threadIdx.y + q][threadIdx.x] = in[(size_t)r * C + c];
    }
    __syncthreads();
#pragma unroll
    for (int q = 0; q < 32; q += 8) {
        int c = c0 + threadIdx.y + q, r = r0 + threadIdx.x;
        if (r < R && c < C) out[(size_t)c * R + r] = t[threadIdx.x][threadIdx.y + q];
    }
}

// ---- merged 4x 256x256 transpose (wq, wk, wv, wo) ----
__global__ void k_transp4(const float* __restrict__ p0, const float* __restrict__ p1,
                          const float* __restrict__ p2, const float* __restrict__ p3,
                          float* __restrict__ o0, float* __restrict__ o1,
                          float* __restrict__ o2, float* __restrict__ o3) {
    __shared__ float t[32][33];
    const float* in  = (blockIdx.z == 0) ? p0 : (blockIdx.z == 1) ? p1 : (blockIdx.z == 2) ? p2 : p3;
    float*       out = (blockIdx.z == 0) ? o0 : (blockIdx.z == 1) ? o1 : (blockIdx.z == 2) ? o2 : o3;
    int c0 = blockIdx.x * 32, r0 = blockIdx.y * 32;
#pragma unroll
    for (int q = 0; q < 32; q += 8)
        t[threadIdx.y + q][threadIdx.x] = in[(size_t)(r0 + threadIdx.y + q) * Cn + c0 + threadIdx.x];
    __syncthreads();
#pragma unroll
    for (int q = 0; q < 32; q += 8)
        out[(size_t)(c0 + threadIdx.y + q) * Cn + r0 + threadIdx.x] = t[threadIdx.x][threadIdx.y + q];
}

// ---------------- depthwise 3x3 pad1, padded-smem plane ----------------
template <int MODE>
__global__ void __launch_bounds__(256) k_dwplane(
    const float* __restrict__ X, const float* __restrict__ w,
    const float* __restrict__ bias,
    const float* __restrict__ bng, const float* __restrict__ bnb,
    const float* __restrict__ bnm, const float* __restrict__ bnv,
    float* __restrict__ out, int CH) {
    __shared__ float sp[30 * 30];
    int bc = blockIdx.x;
    int c  = bc % CH;
    const float* xin = X + (size_t)bc * Pn;
    for (int i = threadIdx.x; i < 900; i += 256) sp[i] = 0.f;
    float wc[9];
#pragma unroll
    for (int i = 0; i < 9; i++) wc[i] = w[c * 9 + i];
    float bsv = bias[c];
    float scale = 0.f, shift = 0.f;
    if (MODE == 1) {
        scale = bng[c] * rsqrtf(bnv[c] + EPSf);
        shift = bnb[c] - bnm[c] * scale;
    }
    __syncthreads();
    for (int i = threadIdx.x; i < Pn; i += 256) {
        int py = i / Wn, px = i - py * Wn;
        sp[(py + 1) * 30 + px + 1] = xin[i];
    }
    __syncthreads();
    for (int p = threadIdx.x; p < Pn; p += 256) {
        int py = p / Wn, px = p - py * Wn;
        const float* s0 = sp + py * 30 + px;
        float acc = bsv;
        acc += wc[0] * s0[0]  + wc[1] * s0[1]  + wc[2] * s0[2];
        acc += wc[3] * s0[30] + wc[4] * s0[31] + wc[5] * s0[32];
        acc += wc[6] * s0[60] + wc[7] * s0[61] + wc[8] * s0[62];
        float y;
        if (MODE == 0) y = acc + s0[31];
        else           y = gelu_f(acc * scale + shift);
        out[(size_t)bc * Pn + p] = y;
    }
}

// ---------------- LN stats ----------------
__global__ void k_stats_part(const float* __restrict__ src, float2* __restrict__ part) {
    int b = blockIdx.x, ch = blockIdx.y;
    const float4* s = (const float4*)(src + (size_t)b * Cn * Pn + (size_t)ch * (Cn * Pn / 8));
    const int nv = (Cn * Pn / 8) / 4;
    float sum = 0.f, sq = 0.f;
    for (int i = threadIdx.x; i < nv; i += 256) {
        float4 v = s[i];
        sum += v.x + v.y + v.z + v.w;
        sq  += v.x * v.x + v.y * v.y + v.z * v.z + v.w * v.w;
    }
    __shared__ float r1[256], r2[256];
    r1[threadIdx.x] = sum; r2[threadIdx.x] = sq;
    __syncthreads();
    for (int st = 128; st > 0; st >>= 1) {
        if (threadIdx.x < st) {
            r1[threadIdx.x] += r1[threadIdx.x + st];
            r2[threadIdx.x] += r2[threadIdx.x + st];
        }
        __syncthreads();
    }
    if (threadIdx.x == 0) part[b * 8 + ch] = make_float2(r1[0], r2[0]);
}

__global__ void k_stats_fin(const float2* __restrict__ part, float2* __restrict__ mr) {
    int t = threadIdx.x;
    float2 p = part[t];
#pragma unroll
    for (int o = 4; o >= 1; o >>= 1) {
        p.x += __shfl_down_sync(0xffffffffu, p.x, o, 8);
        p.y += __shfl_down_sync(0xffffffffu, p.y, o, 8);
    }
    if ((t & 7) == 0) {
        const float n = (float)(Cn * Pn);
        float m  = p.x / n;
        float vv = p.y / n - m * m;
        mr[t >> 3] = make_float2(m, rsqrtf(vv + EPSf));
    }
}

// ---------------- KV downsample: depthwise 2x2 stride2 ----------------
__global__ void k_kvconv(const float* __restrict__ x, const float* __restrict__ w,
                         const float* __restrict__ bias, float* __restrict__ out) {
    int idx = blockIdx.x * blockDim.x + threadIdx.x;
    if (idx >= Bn * Cn * NKn) return;
    int p  = idx % NKn;
    int bc = idx / NKn;
    int c  = bc % Cn;
    int oy = p / HKn, ox = p % HKn;
    const float* xin = x + (size_t)bc * Pn;
    const float* wc  = w + c * 4;
    float acc = bias[c];
    acc += wc[0] * xin[(2 * oy) * Wn + 2 * ox];
    acc += wc[1] * xin[(2 * oy) * Wn + 2 * ox + 1];
    acc += wc[2] * xin[(2 * oy + 1) * Wn + 2 * ox];
    acc += wc[3] * xin[(2 * oy + 1) * Wn + 2 * ox + 1];
    out[idx] = acc;
}

// ================= fp16 mma attention =================
// Block = (qtile 112, head, batch); 7 warps; warp owns one m16 q-row tile.
// S = Q K^T (keys padded to 208), softmax w/ pos bias in registers, O = P V.
// outT channel-major [b][d][p].
#define KP_STR 20   // Kp half2 row stride (conflict-free: 20*gid+tq bijective)
#define VP_STR 40   // Vp half2 row stride (conflict-free: 8*tq+gid bijective)

__global__ void __launch_bounds__(224, 1) k_attn_mma(
    const float* __restrict__ q, const float* __restrict__ k,
    const float* __restrict__ v, const float* __restrict__ pos,
    float* __restrict__ outT) {
    __shared__ __half2 Kp[208 * KP_STR];   // [key][d-pair]
    __shared__ __half2 Vp[104 * VP_STR];   // [key-pair][dv]
    const int tid = threadIdx.x;
    const int warp = tid >> 5, lane = tid & 31;
    const int gid = lane >> 2, tq = lane & 3;
    const int qt = blockIdx.x;
    const int h  = blockIdx.y;
    const int b  = blockIdx.z;
    const int hoff = h * DKn;

    // stage K (d-paired) and V (key-paired) as fp16
    for (int idx = tid; idx < 208 * 16; idx += 224) {
        int key = idx >> 4, e = idx & 15;
        __half2 val = __floats2half2_rn(0.f, 0.f);
        if (key < NKn) {
            float2 f = *(const float2*)(k + ((size_t)(b * NKn + key)) * Cn + hoff + 2 * e);
            val = __floats2half2_rn(f.x, f.y);
        }
        Kp[key * KP_STR + e] = val;
    }
    for (int idx = tid; idx < 104 * 32; idx += 224) {
        int kp = idx >> 5, dv = idx & 31;
        int k0 = 2 * kp, k1 = 2 * kp + 1;
        float f0 = (k0 < NKn) ? v[((size_t)(b * NKn + k0)) * Cn + hoff + dv] : 0.f;
        float f1 = (k1 < NKn) ? v[((size_t)(b * NKn + k1)) * Cn + hoff + dv] : 0.f;
        Vp[kp * VP_STR + dv] = __floats2half2_rn(f0, f1);
    }
    __syncthreads();

    const int iA = qt * 112 + warp * 16 + gid;   // query row A (rowB = iA+8)

    // Q fragments for the two k16 steps (d = 0..31)
    uint32_t aq[2][4];
    {
        const float* q0 = q + ((size_t)(b * Pn + iA)) * Cn + hoff;
        const float* q1 = q0 + 8 * Cn;
#pragma unroll
        for (int kt = 0; kt < 2; kt++) {
            float2 f;
            f = *(const float2*)(q0 + 16 * kt + 2 * tq);     aq[kt][0] = packh2(f.x, f.y);
            f = *(const float2*)(q1 + 16 * kt + 2 * tq);     aq[kt][1] = packh2(f.x, f.y);
            f = *(const float2*)(q0 + 16 * kt + 8 + 2 * tq); aq[kt][2] = packh2(f.x, f.y);
            f = *(const float2*)(q1 + 16 * kt + 8 + 2 * tq); aq[kt][3] = packh2(f.x, f.y);
        }
    }

    // S = Q K^T  (26 n8 key-tiles)
    float accS[26][4];
#pragma unroll
    for (int jt = 0; jt < 26; jt++)
#pragma unroll
        for (int r = 0; r < 4; r++) accS[jt][r] = 0.f;
#pragma unroll
    for (int jt = 0; jt < 26; jt++) {
#pragma unroll
        for (int kt = 0; kt < 2; kt++) {
            uint32_t bf[2];
            bf[0] = *(uint32_t*)&Kp[(8 * jt + gid) * KP_STR + 8 * kt + tq];
            bf[1] = *(uint32_t*)&Kp[(8 * jt + gid) * KP_STR + 8 * kt + 4 + tq];
            mma_f16(accS[jt], aq[kt], bf);
        }
    }

    // scale + pos bias + softmax (rows iA, iA+8)
    const float scale = 0.17677669529663687f;
    const float* posA = pos + ((size_t)(h * Pn + iA)) * NKn;
    const float* posB = posA + 8 * NKn;
    float mA = -1e30f, mB = -1e30f;
#pragma unroll
    for (int jt = 0; jt < 26; jt++) {
        int col = 8 * jt + 2 * tq;
        if (col < NKn) {
            float2 pA = *(const float2*)(posA + col);
            float2 pB = *(const float2*)(posB + col);
            accS[jt][0] = accS[jt][0] * scale + pA.x;
            accS[jt][1] = accS[jt][1] * scale + pA.y;
            accS[jt][2] = accS[jt][2] * scale + pB.x;
            accS[jt][3] = accS[jt][3] * scale + pB.y;
            mA = fmaxf(mA, fmaxf(accS[jt][0], accS[jt][1]));
            mB = fmaxf(mB, fmaxf(accS[jt][2], accS[jt][3]));
        } else {
            accS[jt][0] = -1e30f; accS[jt][1] = -1e30f;
            accS[jt][2] = -1e30f; accS[jt][3] = -1e30f;
        }
    }
    mA = fmaxf(mA, __shfl_xor_sync(0xffffffffu, mA, 1));
    mA = fmaxf(mA, __shfl_xor_sync(0xffffffffu, mA, 2));
    mB = fmaxf(mB, __shfl_xor_sync(0xffffffffu, mB, 1));
    mB = fmaxf(mB, __shfl_xor_sync(0xffffffffu, mB, 2));
    float lA = 0.f, lB = 0.f;
#pragma unroll
    for (int jt = 0; jt < 26; jt++) {
        accS[jt][0] = __expf(accS[jt][0] - mA);
        accS[jt][1] = __expf(accS[jt][1] - mA);
        accS[jt][2] = __expf(accS[jt][2] - mB);
        accS[jt][3] = __expf(accS[jt][3] - mB);
        lA += accS[jt][0] + accS[jt][1];
        lB += accS[jt][2] + accS[jt][3];
    }
    lA += __shfl_xor_sync(0xffffffffu, lA, 1);
    lA += __shfl_xor_sync(0xffffffffu, lA, 2);
    lB += __shfl_xor_sync(0xffffffffu, lB, 1);
    lB += __shfl_xor_sync(0xffffffffu, lB, 2);

    // O = P V  (S c-frag layout == P a-frag layout)
    float accO[4][4];
#pragma unroll
    for (int nt = 0; nt < 4; nt++)
#pragma unroll
        for (int r = 0; r < 4; r++) accO[nt][r] = 0.f;
#pragma unroll
    for (int kt = 0; kt < 13; kt++) {
        uint32_t pa[4];
        pa[0] = packh2(accS[2 * kt][0],     accS[2 * kt][1]);
        pa[1] = packh2(accS[2 * kt][2],     accS[2 * kt][3]);
        pa[2] = packh2(accS[2 * kt + 1][0], accS[2 * kt + 1][1]);
        pa[3] = packh2(accS[2 * kt + 1][2], accS[2 * kt + 1][3]);
#pragma unroll
        for (int nt = 0; nt < 4; nt++) {
            uint32_t bf[2];
            bf[0] = *(uint32_t*)&Vp[(8 * kt + tq) * VP_STR + 8 * nt + gid];
            bf[1] = *(uint32_t*)&Vp[(8 * kt + 4 + tq) * VP_STR + 8 * nt + gid];
            mma_f16(accO[nt], pa, bf);
        }
    }
    float invA = 1.f / lA, invB = 1.f / lB;
    float* ob = outT + ((size_t)(b * Cn + hoff)) * Pn;
#pragma unroll
    for (int nt = 0; nt < 4; nt++) {
        int dv = 8 * nt + 2 * tq;
        ob[(size_t)dv * Pn + iA]           = accO[nt][0] * invA;
        ob[(size_t)(dv + 1) * Pn + iA]     = accO[nt][1] * invA;
        ob[(size_t)dv * Pn + iA + 8]       = accO[nt][2] * invB;
        ob[(size_t)(dv + 1) * Pn + iA + 8] = accO[nt][3] * invB;
    }
}

// ---------------- host launch ----------------
static void* sym_addr(const void* symbol) {
    void* p = nullptr;
    cudaGetSymbolAddress(&p, symbol);
    return p;
}

extern "C" void kernel_launch(void* const* d_in, const int* in_sizes, int n_in,
                              void* d_out, int out_size) {
    const float* x     = (const float*)d_in[0];
    const float* lpu_w = (const float*)d_in[1];
    const float* lpu_b = (const float*)d_in[2];
    const float* dw_w  = (const float*)d_in[3];
    const float* dw_b  = (const float*)d_in[4];
    const float* wq    = (const float*)d_in[5];
    const float* bq    = (const float*)d_in[6];
    const float* wk    = (const float*)d_in[7];
    const float* bk    = (const float*)d_in[8];
    const float* wv    = (const float*)d_in[9];
    const float* bv    = (const float*)d_in[10];
    const float* wo    = (const float*)d_in[11];
    const float* bo    = (const float*)d_in[12];
    const float* pos_b = (const float*)d_in[13];
    const float* c1_w  = (const float*)d_in[14];
    const float* c1_b  = (const float*)d_in[15];
    const float* bn1_g = (const float*)d_in[16];
    const float* bn1_b = (const float*)d_in[17];
    const float* bn1_m = (const float*)d_in[18];
    const float* bn1_v = (const float*)d_in[19];
    const float* dw2_w = (const float*)d_in[20];
    const float* dw2_b = (const float*)d_in[21];
    const float* bn2_g = (const float*)d_in[22];
    const float* bn2_b = (const float*)d_in[23];
    const float* bn2_m = (const float*)d_in[24];
    const float* bn2_v = (const float*)d_in[25];
    const float* c2_w  = (const float*)d_in[26];
    const float* c2_b  = (const float*)d_in[27];
    const float* bn3_g = (const float*)d_in[28];
    const float* bn3_b = (const float*)d_in[29];
    const float* bn3_m = (const float*)d_in[30];
    const float* bn3_v = (const float*)d_in[31];
    float* out = (float*)d_out;

    float*  x1   = (float*)sym_addr(g_x1);
    float*  qb   = (float*)sym_addr(g_q);
    float*  kvb  = (float*)sym_addr(g_kv);
    float*  kb   = (float*)sym_addr(g_k);
    float*  vb   = (float*)sym_addr(g_v);
    float*  attT = (float*)sym_addr(g_attT);
    float*  x2   = (float*)sym_addr(g_x2);
    float*  t1   = (float*)sym_addr(g_t1);
    float*  t2   = (float*)sym_addr(g_t2);
    float*  wqT  = (float*)sym_addr(g_wqT);
    float*  wkT  = (float*)sym_addr(g_wkT);
    float*  wvT  = (float*)sym_addr(g_wvT);
    float*  woT  = (float*)sym_addr(g_woT);
    float*  c1T  = (float*)sym_addr(g_c1T);
    float*  c2T  = (float*)sym_addr(g_c2T);
    float2* part = (float2*)sym_addr(g_part);
    float2* mr   = (float2*)sym_addr(g_mr);

    dim3 tb(32, 8);
    // weight transposes -> [k][m] layout
    k_transp4<<<dim3(8, 8, 4), tb>>>(wq, wk, wv, wo, wqT, wkT, wvT, woT);
    k_transp<<<dim3(8, 32, 1), tb>>>(c1_w, c1T, CMn, Cn);
    k_transp<<<dim3(32, 8, 1), tb>>>(c2_w, c2T, Cn, CMn);

    // 1. LPU -> x1 (channel-major)
    k_dwplane<0><<<Bn * Cn, 256>>>(x, lpu_w, lpu_b, nullptr, nullptr, nullptr, nullptr, x1, Cn);
    // 2. LN1 stats
    k_stats_part<<<dim3(Bn, 8), 256>>>(x1, part);
    k_stats_fin<<<1, 256>>>(part, mr);
    // 3. KV downsample (pre-LN x1)
    k_kvconv<<<(Bn * Cn * NKn + 255) / 256, 256>>>(x1, dw_w, dw_b, kvb);
    // 4. Q projection (LN fused in B-load) -> q row-major
    k_mma<0, true><<<dim3(7, 2, Bn), 256, SMEM_MMA>>>(
        wqT, x1, bq, nullptr, nullptr, nullptr, nullptr, mr, nullptr, qb, Cn, Cn, Pn);
    // 5. K, V projections
    k_mma<0, false><<<dim3(2, 2, Bn), 256, SMEM_MMA>>>(
        wkT, kvb, bk, nullptr, nullptr, nullptr, nullptr, nullptr, nullptr, kb, Cn, Cn, NKn);
    k_mma<0, false><<<dim3(2, 2, Bn), 256, SMEM_MMA>>>(
        wvT, kvb, bv, nullptr, nullptr, nullptr, nullptr, nullptr, nullptr, vb, Cn, Cn, NKn);
    // 6. fp16 mma attention -> channel-major attT
    k_attn_mma<<<dim3(7, NH, Bn), 224>>>(qb, kb, vb, pos_b, attT);
    // 7. O projection + flat residual -> x2
    k_mma<1, false><<<dim3(7, 2, Bn), 256, SMEM_MMA>>>(
        woT, attT, bo, nullptr, nullptr, nullptr, nullptr, nullptr, x1, x2, Cn, Cn, Pn);
    // 8. LN2 stats
    k_stats_part<<<dim3(Bn, 8), 256>>>(x2, part);
    k_stats_fin<<<1, 256>>>(part, mr);
    // 9. c1 + BN1 + GELU (LN fused in B-load) -> t1 channel-major
    k_mma<2, true><<<dim3(7, 8, Bn), 256, SMEM_MMA>>>(
        c1T, x2, c1_b, bn1_g, bn1_b, bn1_m, bn1_v, mr, nullptr, t1, CMn, Cn, Pn);
    // 10. dw2 + BN2 + GELU -> t2 channel-major
    k_dwplane<1><<<Bn * CMn, 256>>>(t1, dw2_w, dw2_b, bn2_g, bn2_b, bn2_m, bn2_v, t2, CMn);
    // 11. c2 + BN3 + channel-major residual -> d_out
    k_mma<3, false><<<dim3(7, 2, Bn), 256, SMEM_MMA>>>(
        c2T, t2, c2_b, bn3_g, bn3_b, bn3_m, bn3_v, nullptr, x2, out, Cn, CMn, Pn);
}

// round 8
// speedup vs baseline: 4.3184x; 1.1777x over previous
#include <cuda_runtime.h>
#include <cuda_fp16.h>
#include <math.h>
#include <stdint.h>

// ---------------- problem constants ----------------
#define Bn   32
#define Cn   256
#define Hn   28
#define Wn   28
#define Pn   784          // H*W
#define NKn  196          // (H/2)*(W/2)
#define HKn  14
#define CMn  1024         // C * R
#define NH   8
#define DKn  32
#define EPSf 1e-5f

// ---------------- scratch (device globals; padded for unguarded tile loads) ----------------
__device__ float   g_x1 [Bn*Cn*Pn + 256];      // after LPU (channel-major)
__device__ float   g_kv [Bn*Cn*NKn + 256];     // stride-2 dw conv out [c][196]
__device__ float   g_x2 [Bn*Cn*Pn + 256];      // after attn residual (flat)
__device__ float   g_t1 [Bn*CMn*Pn];           // IRFFN expand fp32 (channel-major)
__device__ __half  g_qh [Bn*Pn*Cn];            // Q fp16 row-major [p][oc]
__device__ __half  g_kh [Bn*NKn*Cn];           // K fp16 [nk][256]
__device__ __half  g_vh [Bn*NKn*Cn];           // V fp16 [nk][256]
__device__ __half2 g_attTh[Bn*(Cn/2)*Pn + 256];  // attn out, channel-PAIR-major [d/2][p]
__device__ __half2 g_t2h  [Bn*(CMn/2)*Pn + 256]; // dw2 out, channel-PAIR-major
__device__ __half2 g_wqh[(Cn/2)*Cn];           // weights k-paired [k/2][m]
__device__ __half2 g_wkh[(Cn/2)*Cn];
__device__ __half2 g_wvh[(Cn/2)*Cn];
__device__ __half2 g_woh[(Cn/2)*Cn];
__device__ __half2 g_c1h[(Cn/2)*CMn];
__device__ __half2 g_c2h[(CMn/2)*Cn];
__device__ float2  g_part[Bn*8];
__device__ float2  g_mr  [Bn];

__device__ __forceinline__ float gelu_f(float v) {
    return 0.5f * v * (1.0f + erff(v * 0.7071067811865475f));
}
__device__ __forceinline__ void mma_f16(float* c, const uint32_t* a, const uint32_t* b) {
    asm volatile(
        "mma.sync.aligned.m16n8k16.row.col.f32.f16.f16.f32 "
        "{%0,%1,%2,%3}, {%4,%5,%6,%7}, {%8,%9}, {%0,%1,%2,%3};"
        : "+f"(c[0]), "+f"(c[1]), "+f"(c[2]), "+f"(c[3])
        : "r"(a[0]), "r"(a[1]), "r"(a[2]), "r"(a[3]), "r"(b[0]), "r"(b[1]));
}
__device__ __forceinline__ uint32_t packh2(float lo, float hi) {
    __half2 h = __floats2half2_rn(lo, hi);
    return *(uint32_t*)&h;
}

// ====================== fp16 mma.sync GEMM ======================
// D[m][p] = sum_k W[m][k] * X[k][p]  per batch.
// A (weights): __half2 k-paired [k/2][M], loaded raw.
// B: BH ? __half2 k-paired [k/2][P] raw : fp32 channel-major [k][P] (+optional LN), packed on the fly.
// MODE 0: half out[p*M+m] = D + bias
// MODE 1: f32  out[p*M+m] = D + bias + res (flat residual)
// MODE 2: f32  out[m*P+p] = gelu(BN(D + bias))
// MODE 3: f32  out[m*P+p] = BN(D + bias) + res
#define H2STR 136
#define KSTR  132
#define SMEM_MMA (64*KSTR*4)

template <int MODE, bool LNB, bool BH>
__global__ void __launch_bounds__(256, 2) k_mma(
    const __half2* __restrict__ Wh, const void* __restrict__ Xv,
    const float* __restrict__ bias,
    const float* __restrict__ bng, const float* __restrict__ bnb,
    const float* __restrict__ bnm, const float* __restrict__ bnv,
    const float2* __restrict__ mr, const float* __restrict__ res,
    void* __restrict__ outv, int M, int K, int P) {
    extern __shared__ float sm[];
    __half2* As2 = (__half2*)sm;             // [16][H2STR]
    __half2* Bs2 = As2 + 16 * H2STR;
    const int tid  = threadIdx.x;
    const int warp = tid >> 5, lane = tid & 31;
    const int gid = lane >> 2, tq = lane & 3;
    const int wm = (warp & 1) * 64;
    const int wn = (warp >> 1) * 32;
    const int b  = blockIdx.z;
    const int m0 = blockIdx.y * 128;
    const int n0 = blockIdx.x * 128;
    const float*   Xf  = BH ? nullptr : (const float*)Xv + (size_t)b * K * P;
    const __half2* Xh2 = BH ? (const __half2*)Xv + (size_t)b * (K >> 1) * P : nullptr;
    float mean = 0.f, rstd = 1.f;
    if (LNB) { float2 v = mr[b]; mean = v.x; rstd = v.y; }

    float acc[4][4][4];
#pragma unroll
    for (int i = 0; i < 4; i++)
#pragma unroll
        for (int j = 0; j < 4; j++)
#pragma unroll
            for (int r = 0; r < 4; r++) acc[i][j][r] = 0.f;

    const int kk = tid >> 4;         // 0..15 k-pair row
    const int mq = (tid & 15) * 8;   // column start
    uint4 pa0, pa1, pb0, pb1;
    const int T = K >> 5;

    auto load_chunk = [&](int kc0) {
        const uint4* wr = (const uint4*)(Wh + (size_t)((kc0 >> 1) + kk) * M + m0 + mq);
        pa0 = wr[0]; pa1 = wr[1];
        if (BH) {
            const uint4* xr = (const uint4*)(Xh2 + (size_t)((kc0 >> 1) + kk) * P + n0 + mq);
            pb0 = xr[0]; pb1 = xr[1];
        } else {
            const float* xr0 = Xf + (size_t)(kc0 + 2 * kk) * P + n0 + mq;
            const float* xr1 = xr0 + P;
            float4 b0 = *(const float4*)xr0;
            float4 b1 = *(const float4*)(xr0 + 4);
            float4 b2 = *(const float4*)xr1;
            float4 b3 = *(const float4*)(xr1 + 4);
            if (LNB) {
                b0.x=(b0.x-mean)*rstd; b0.y=(b0.y-mean)*rstd; b0.z=(b0.z-mean)*rstd; b0.w=(b0.w-mean)*rstd;
                b1.x=(b1.x-mean)*rstd; b1.y=(b1.y-mean)*rstd; b1.z=(b1.z-mean)*rstd; b1.w=(b1.w-mean)*rstd;
                b2.x=(b2.x-mean)*rstd; b2.y=(b2.y-mean)*rstd; b2.z=(b2.z-mean)*rstd; b2.w=(b2.w-mean)*rstd;
                b3.x=(b3.x-mean)*rstd; b3.y=(b3.y-mean)*rstd; b3.z=(b3.z-mean)*rstd; b3.w=(b3.w-mean)*rstd;
            }
            pb0 = make_uint4(packh2(b0.x, b2.x), packh2(b0.y, b2.y),
                             packh2(b0.z, b2.z), packh2(b0.w, b2.w));
            pb1 = make_uint4(packh2(b1.x, b3.x), packh2(b1.y, b3.y),
                             packh2(b1.z, b3.z), packh2(b1.w, b3.w));
        }
    };
    auto store_chunk = [&]() {
        *(uint4*)&As2[kk * H2STR + mq]     = pa0;
        *(uint4*)&As2[kk * H2STR + mq + 4] = pa1;
        *(uint4*)&Bs2[kk * H2STR + mq]     = pb0;
        *(uint4*)&Bs2[kk * H2STR + mq + 4] = pb1;
    };

    load_chunk(0);
    store_chunk();
    __syncthreads();

    for (int t = 0; t < T; t++) {
        if (t + 1 < T) load_chunk((t + 1) << 5);
#pragma unroll
        for (int ks = 0; ks < 2; ks++) {
            const int r0 = ks * 8;
            uint32_t af[4][4], bf[4][2];
#pragma unroll
            for (int i = 0; i < 4; i++) {
                int m = wm + i * 16 + gid;
                af[i][0] = *(uint32_t*)&As2[(r0 + tq) * H2STR + m];
                af[i][1] = *(uint32_t*)&As2[(r0 + tq) * H2STR + m + 8];
                af[i][2] = *(uint32_t*)&As2[(r0 + tq + 4) * H2STR + m];
                af[i][3] = *(uint32_t*)&As2[(r0 + tq + 4) * H2STR + m + 8];
            }
#pragma unroll
            for (int j = 0; j < 4; j++) {
                int p = wn + j * 8 + gid;
                bf[j][0] = *(uint32_t*)&Bs2[(r0 + tq) * H2STR + p];
                bf[j][1] = *(uint32_t*)&Bs2[(r0 + tq + 4) * H2STR + p];
            }
#pragma unroll
            for (int i = 0; i < 4; i++)
#pragma unroll
                for (int j = 0; j < 4; j++) mma_f16(acc[i][j], af[i], bf[j]);
        }
        if (t + 1 < T) {
            __syncthreads();
            store_chunk();
            __syncthreads();
        }
    }

    // ---- epilogue: two 64-row passes staged through smem ----
    float* sD = sm;
    float*  outf = (MODE >= 1) ? (float*)outv + (size_t)b * (size_t)M * P : nullptr;
    __half* outh = (MODE == 0) ? (__half*)outv + (size_t)b * (size_t)M * P : nullptr;
    const float* resb = (MODE == 1 || MODE == 3) ? res + (size_t)b * (size_t)M * P : nullptr;

#pragma unroll
    for (int pass = 0; pass < 2; pass++) {
        __syncthreads();
        if (MODE <= 1) {
            if ((wn >> 6) == pass) {
#pragma unroll
                for (int i = 0; i < 4; i++) {
                    int mrow = wm + i * 16 + gid;
#pragma unroll
                    for (int j = 0; j < 4; j++) {
                        int pc = (wn & 63) + j * 8 + 2 * tq;
                        sD[pc * KSTR + mrow]           = acc[i][j][0];
                        sD[(pc + 1) * KSTR + mrow]     = acc[i][j][1];
                        sD[pc * KSTR + mrow + 8]       = acc[i][j][2];
                        sD[(pc + 1) * KSTR + mrow + 8] = acc[i][j][3];
                    }
                }
            }
        } else {
            if ((wm >> 6) == pass) {
#pragma unroll
                for (int i = 0; i < 4; i++) {
                    int ml = (wm & 63) + i * 16 + gid;
#pragma unroll
                    for (int j = 0; j < 4; j++) {
                        int pc = wn + j * 8 + 2 * tq;
                        sD[ml * KSTR + pc]           = acc[i][j][0];
                        sD[ml * KSTR + pc + 1]       = acc[i][j][1];
                        sD[(ml + 8) * KSTR + pc]     = acc[i][j][2];
                        sD[(ml + 8) * KSTR + pc + 1] = acc[i][j][3];
                    }
                }
            }
        }
        __syncthreads();
        if (MODE <= 1) {
            for (int l = tid; l < 64 * 32; l += 256) {
                int rl = l >> 5, cq = (l & 31) * 4;
                int p = n0 + pass * 64 + rl;
                if (p >= P) continue;
                float4 v = *(float4*)&sD[rl * KSTR + cq];
                float4 bb = *(const float4*)(bias + m0 + cq);
                v.x += bb.x; v.y += bb.y; v.z += bb.z; v.w += bb.w;
                size_t off = (size_t)p * M + m0 + cq;
                if (MODE == 0) {
                    __half2 h01 = __floats2half2_rn(v.x, v.y);
                    __half2 h23 = __floats2half2_rn(v.z, v.w);
                    uint2 u = make_uint2(*(uint32_t*)&h01, *(uint32_t*)&h23);
                    *(uint2*)(outh + off) = u;
                } else {
                    float4 rr = *(const float4*)(resb + off);
                    v.x += rr.x; v.y += rr.y; v.z += rr.z; v.w += rr.w;
                    *(float4*)(outf + off) = v;
                }
            }
        } else {
            for (int l = tid; l < 64 * 32; l += 256) {
                int rl = l >> 5, cq = (l & 31) * 4;
                int m = m0 + pass * 64 + rl;
                int p = n0 + cq;
                if (p >= P) continue;
                float scale = bng[m] * rsqrtf(bnv[m] + EPSf);
                float shift = bnb[m] - bnm[m] * scale + bias[m] * scale;
                float4 v = *(float4*)&sD[rl * KSTR + cq];
                v.x = v.x * scale + shift; v.y = v.y * scale + shift;
                v.z = v.z * scale + shift; v.w = v.w * scale + shift;
                if (MODE == 2) { v.x = gelu_f(v.x); v.y = gelu_f(v.y); v.z = gelu_f(v.z); v.w = gelu_f(v.w); }
                size_t off = (size_t)m * P + p;
                if (MODE == 3) {
                    float4 rr = *(const float4*)(resb + off);
                    v.x += rr.x; v.y += rr.y; v.z += rr.z; v.w += rr.w;
                }
                *(float4*)(outf + off) = v;
            }
        }
    }
}

// ---------------- weight pack: w [M][K] f32 -> wh half2 k-paired [K/2][M] ----------------
__global__ void k_wpack(const float* __restrict__ w, __half2* __restrict__ wh, int M, int K) {
    __shared__ float t[32][33];
    int m0 = blockIdx.x * 32, k0 = blockIdx.y * 32;
    int tx = threadIdx.x, ty = threadIdx.y;
#pragma unroll
    for (int q = 0; q < 32; q += 8)
        t[ty + q][tx] = w[(size_t)(m0 + ty + q) * K + k0 + tx];
    __syncthreads();
#pragma unroll
    for (int q = 0; q < 2; q++) {
        int kp = ty + q * 8;
        __half2 val = __floats2half2_rn(t[tx][2 * kp], t[tx][2 * kp + 1]);
        wh[(size_t)((k0 >> 1) + kp) * M + m0 + tx] = val;
    }
}

__global__ void k_wpack4(const float* __restrict__ p0, const float* __restrict__ p1,
                         const float* __restrict__ p2, const float* __restrict__ p3,
                         __half2* __restrict__ o0, __half2* __restrict__ o1,
                         __half2* __restrict__ o2, __half2* __restrict__ o3) {
    __shared__ float t[32][33];
    const float* in = (blockIdx.z == 0) ? p0 : (blockIdx.z == 1) ? p1 : (blockIdx.z == 2) ? p2 : p3;
    __half2*    out = (blockIdx.z == 0) ? o0 : (blockIdx.z == 1) ? o1 : (blockIdx.z == 2) ? o2 : o3;
    int m0 = blockIdx.x * 32, k0 = blockIdx.y * 32;
    int tx = threadIdx.x, ty = threadIdx.y;
#pragma unroll
    for (int q = 0; q < 32; q += 8)
        t[ty + q][tx] = in[(size_t)(m0 + ty + q) * Cn + k0 + tx];
    __syncthreads();
#pragma unroll
    for (int q = 0; q < 2; q++) {
        int kp = ty + q * 8;
        __half2 val = __floats2half2_rn(t[tx][2 * kp], t[tx][2 * kp + 1]);
        out[(size_t)((k0 >> 1) + kp) * Cn + m0 + tx] = val;
    }
}

// ---------------- LPU: depthwise 3x3 + bias + residual, 4-px vertical strips ----------------
__global__ void __launch_bounds__(224) k_lpu(
    const float* __restrict__ X, const float* __restrict__ w,
    const float* __restrict__ bias, float* __restrict__ out) {
    __shared__ float sp[900];
    int bc = blockIdx.x;
    int c  = bc & (Cn - 1);
    const float* xin = X + (size_t)bc * Pn;
    int tid = threadIdx.x;
    for (int i = tid; i < 900; i += 224) sp[i] = 0.f;
    float wc[9];
#pragma unroll
    for (int i = 0; i < 9; i++) wc[i] = w[c * 9 + i];
    float bsv = bias[c];
    __syncthreads();
    for (int i = tid; i < Pn; i += 224) sp[(i / 28 + 1) * 30 + (i % 28) + 1] = xin[i];
    __syncthreads();
    if (tid < 196) {
        int px = tid % 28, sy = (tid / 28) * 4;
        float a[6][3];
#pragma unroll
        for (int dr = 0; dr < 6; dr++) {
            const float* r = sp + (sy + dr) * 30 + px;
            a[dr][0] = r[0]; a[dr][1] = r[1]; a[dr][2] = r[2];
        }
        float* ob = out + (size_t)bc * Pn;
#pragma unroll
        for (int i = 0; i < 4; i++) {
            float acc = bsv
                + wc[0] * a[i][0]     + wc[1] * a[i][1]     + wc[2] * a[i][2]
                + wc[3] * a[i + 1][0] + wc[4] * a[i + 1][1] + wc[5] * a[i + 1][2]
                + wc[6] * a[i + 2][0] + wc[7] * a[i + 2][1] + wc[8] * a[i + 2][2];
            ob[(sy + i) * 28 + px] = acc + a[i + 1][1];
        }
    }
}

// ---------------- dw2: channel-pair, BN+GELU, half2-paired output ----------------
__global__ void __launch_bounds__(224) k_dw2pair(
    const float* __restrict__ X, const float* __restrict__ w,
    const float* __restrict__ bias,
    const float* __restrict__ bng, const float* __restrict__ bnb,
    const float* __restrict__ bnm, const float* __restrict__ bnv,
    __half2* __restrict__ out2) {
    __shared__ float sp0[900], sp1[900];
    int bc = blockIdx.x;
    int b  = bc >> 9;            // CMn/2 = 512
    int mp = bc & 511;
    int c0 = 2 * mp;
    const float* x0 = X + ((size_t)b * CMn + c0) * Pn;
    int tid = threadIdx.x;
    for (int i = tid; i < 900; i += 224) { sp0[i] = 0.f; sp1[i] = 0.f; }
    float wa[9], wb[9];
#pragma unroll
    for (int i = 0; i < 9; i++) { wa[i] = w[c0 * 9 + i]; wb[i] = w[(c0 + 1) * 9 + i]; }
    float bs0 = bias[c0], bs1 = bias[c0 + 1];
    float sc0 = bng[c0] * rsqrtf(bnv[c0] + EPSf);
    float sh0 = bnb[c0] - bnm[c0] * sc0;
    float sc1 = bng[c0 + 1] * rsqrtf(bnv[c0 + 1] + EPSf);
    float sh1 = bnb[c0 + 1] - bnm[c0 + 1] * sc1;
    __syncthreads();
    for (int i = tid; i < Pn; i += 224) {
        int o = (i / 28 + 1) * 30 + (i % 28) + 1;
        sp0[o] = x0[i];
        sp1[o] = x0[Pn + i];
    }
    __syncthreads();
    if (tid < 196) {
        int px = tid % 28, sy = (tid / 28) * 4;
        float a0[6][3], a1[6][3];
#pragma unroll
        for (int dr = 0; dr < 6; dr++) {
            int base = (sy + dr) * 30 + px;
            a0[dr][0] = sp0[base]; a0[dr][1] = sp0[base + 1]; a0[dr][2] = sp0[base + 2];
            a1[dr][0] = sp1[base]; a1[dr][1] = sp1[base + 1]; a1[dr][2] = sp1[base + 2];
        }
        __half2* ob = out2 + ((size_t)b * (CMn / 2) + mp) * Pn;
#pragma unroll
        for (int i = 0; i < 4; i++) {
            float acc0 = bs0
                + wa[0] * a0[i][0]     + wa[1] * a0[i][1]     + wa[2] * a0[i][2]
                + wa[3] * a0[i + 1][0] + wa[4] * a0[i + 1][1] + wa[5] * a0[i + 1][2]
                + wa[6] * a0[i + 2][0] + wa[7] * a0[i + 2][1] + wa[8] * a0[i + 2][2];
            float acc1 = bs1
                + wb[0] * a1[i][0]     + wb[1] * a1[i][1]     + wb[2] * a1[i][2]
                + wb[3] * a1[i + 1][0] + wb[4] * a1[i + 1][1] + wb[5] * a1[i + 1][2]
                + wb[6] * a1[i + 2][0] + wb[7] * a1[i + 2][1] + wb[8] * a1[i + 2][2];
            float y0 = gelu_f(acc0 * sc0 + sh0);
            float y1 = gelu_f(acc1 * sc1 + sh1);
            ob[(sy + i) * 28 + px] = __floats2half2_rn(y0, y1);
        }
    }
}

// ---------------- LN stats ----------------
__global__ void k_stats_part(const float* __restrict__ src, float2* __restrict__ part) {
    int b = blockIdx.x, ch = blockIdx.y;
    const float4* s = (const float4*)(src + (size_t)b * Cn * Pn + (size_t)ch * (Cn * Pn / 8));
    const int nv = (Cn * Pn / 8) / 4;
    float sum = 0.f, sq = 0.f;
    for (int i = threadIdx.x; i < nv; i += 256) {
        float4 v = s[i];
        sum += v.x + v.y + v.z + v.w;
        sq  += v.x * v.x + v.y * v.y + v.z * v.z + v.w * v.w;
    }
    __shared__ float r1[256], r2[256];
    r1[threadIdx.x] = sum; r2[threadIdx.x] = sq;
    __syncthreads();
    for (int st = 128; st > 0; st >>= 1) {
        if (threadIdx.x < st) {
            r1[threadIdx.x] += r1[threadIdx.x + st];
            r2[threadIdx.x] += r2[threadIdx.x + st];
        }
        __syncthreads();
    }
    if (threadIdx.x == 0) part[b * 8 + ch] = make_float2(r1[0], r2[0]);
}

__global__ void k_stats_fin(const float2* __restrict__ part, float2* __restrict__ mr) {
    int t = threadIdx.x;
    float2 p = part[t];
#pragma unroll
    for (int o = 4; o >= 1; o >>= 1) {
        p.x += __shfl_down_sync(0xffffffffu, p.x, o, 8);
        p.y += __shfl_down_sync(0xffffffffu, p.y, o, 8);
    }
    if ((t & 7) == 0) {
        const float n = (float)(Cn * Pn);
        float m  = p.x / n;
        float vv = p.y / n - m * m;
        mr[t >> 3] = make_float2(m, rsqrtf(vv + EPSf));
    }
}

// ---------------- KV downsample: depthwise 2x2 stride2 ----------------
__global__ void k_kvconv(const float* __restrict__ x, const float* __restrict__ w,
                         const float* __restrict__ bias, float* __restrict__ out) {
    int idx = blockIdx.x * blockDim.x + threadIdx.x;
    if (idx >= Bn * Cn * NKn) return;
    int p  = idx % NKn;
    int bc = idx / NKn;
    int c  = bc % Cn;
    int oy = p / HKn, ox = p % HKn;
    const float* xin = x + (size_t)bc * Pn;
    const float* wc  = w + c * 4;
    float acc = bias[c];
    acc += wc[0] * xin[(2 * oy) * Wn + 2 * ox];
    acc += wc[1] * xin[(2 * oy) * Wn + 2 * ox + 1];
    acc += wc[2] * xin[(2 * oy + 1) * Wn + 2 * ox];
    acc += wc[3] * xin[(2 * oy + 1) * Wn + 2 * ox + 1];
    out[idx] = acc;
}

// ================= fp16 mma attention (fp16 inputs, half2-paired output) =================
#define KP_STR 20
#define VP_STR 40

__global__ void __launch_bounds__(224, 1) k_attn_mma(
    const __half* __restrict__ q, const __half* __restrict__ k,
    const __half* __restrict__ v, const float* __restrict__ pos,
    __half2* __restrict__ outT2) {
    __shared__ __half2 Kp[208 * KP_STR];   // [key][d-pair]
    __shared__ __half2 Vp[104 * VP_STR];   // [key-pair][dv]
    const int tid = threadIdx.x;
    const int warp = tid >> 5, lane = tid & 31;
    const int gid = lane >> 2, tq = lane & 3;
    const int qt = blockIdx.x;
    const int h  = blockIdx.y;
    const int b  = blockIdx.z;
    const int hoff = h * DKn;

    for (int idx = tid; idx < 208 * 16; idx += 224) {
        int key = idx >> 4, e = idx & 15;
        __half2 val = __floats2half2_rn(0.f, 0.f);
        if (key < NKn)
            val = *(const __half2*)(k + ((size_t)(b * NKn + key)) * Cn + hoff + 2 * e);
        Kp[key * KP_STR + e] = val;
    }
    for (int idx = tid; idx < 104 * 32; idx += 224) {
        int kp = idx >> 5, dv = idx & 31;
        int k0 = 2 * kp, k1 = 2 * kp + 1;
        __half f0 = (k0 < NKn) ? v[((size_t)(b * NKn + k0)) * Cn + hoff + dv] : __float2half(0.f);
        __half f1 = (k1 < NKn) ? v[((size_t)(b * NKn + k1)) * Cn + hoff + dv] : __float2half(0.f);
        Vp[kp * VP_STR + dv] = __halves2half2(f0, f1);
    }
    __syncthreads();

    const int iA = qt * 112 + warp * 16 + gid;

    uint32_t aq[2][4];
    {
        const __half* q0 = q + ((size_t)(b * Pn + iA)) * Cn + hoff;
        const __half* q1 = q0 + 8 * Cn;
#pragma unroll
        for (int kt = 0; kt < 2; kt++) {
            aq[kt][0] = *(const uint32_t*)(q0 + 16 * kt + 2 * tq);
            aq[kt][1] = *(const uint32_t*)(q1 + 16 * kt + 2 * tq);
            aq[kt][2] = *(const uint32_t*)(q0 + 16 * kt + 8 + 2 * tq);
            aq[kt][3] = *(const uint32_t*)(q1 + 16 * kt + 8 + 2 * tq);
        }
    }

    float accS[26][4];
#pragma unroll
    for (int jt = 0; jt < 26; jt++)
#pragma unroll
        for (int r = 0; r < 4; r++) accS[jt][r] = 0.f;
#pragma unroll
    for (int jt = 0; jt < 26; jt++) {
#pragma unroll
        for (int kt = 0; kt < 2; kt++) {
            uint32_t bf[2];
            bf[0] = *(uint32_t*)&Kp[(8 * jt + gid) * KP_STR + 8 * kt + tq];
            bf[1] = *(uint32_t*)&Kp[(8 * jt + gid) * KP_STR + 8 * kt + 4 + tq];
            mma_f16(accS[jt], aq[kt], bf);
        }
    }

    const float scale = 0.17677669529663687f;
    const float* posA = pos + ((size_t)(h * Pn + iA)) * NKn;
    const float* posB = posA + 8 * NKn;
    float mA = -1e30f, mB = -1e30f;
#pragma unroll
    for (int jt = 0; jt < 26; jt++) {
        int col = 8 * jt + 2 * tq;
        if (col < NKn) {
            float2 pA = *(const float2*)(posA + col);
            float2 pB = *(const float2*)(posB + col);
            accS[jt][0] = accS[jt][0] * scale + pA.x;
            accS[jt][1] = accS[jt][1] * scale + pA.y;
            accS[jt][2] = accS[jt][2] * scale + pB.x;
            accS[jt][3] = accS[jt][3] * scale + pB.y;
            mA = fmaxf(mA, fmaxf(accS[jt][0], accS[jt][1]));
            mB = fmaxf(mB, fmaxf(accS[jt][2], accS[jt][3]));
        } else {
            accS[jt][0] = -1e30f; accS[jt][1] = -1e30f;
            accS[jt][2] = -1e30f; accS[jt][3] = -1e30f;
        }
    }
    mA = fmaxf(mA, __shfl_xor_sync(0xffffffffu, mA, 1));
    mA = fmaxf(mA, __shfl_xor_sync(0xffffffffu, mA, 2));
    mB = fmaxf(mB, __shfl_xor_sync(0xffffffffu, mB, 1));
    mB = fmaxf(mB, __shfl_xor_sync(0xffffffffu, mB, 2));
    float lA = 0.f, lB = 0.f;
#pragma unroll
    for (int jt = 0; jt < 26; jt++) {
        accS[jt][0] = __expf(accS[jt][0] - mA);
        accS[jt][1] = __expf(accS[jt][1] - mA);
        accS[jt][2] = __expf(accS[jt][2] - mB);
        accS[jt][3] = __expf(accS[jt][3] - mB);
        lA += accS[jt][0] + accS[jt][1];
        lB += accS[jt][2] + accS[jt][3];
    }
    lA += __shfl_xor_sync(0xffffffffu, lA, 1);
    lA += __shfl_xor_sync(0xffffffffu, lA, 2);
    lB += __shfl_xor_sync(0xffffffffu, lB, 1);
    lB += __shfl_xor_sync(0xffffffffu, lB, 2);

    float accO[4][4];
#pragma unroll
    for (int nt = 0; nt < 4; nt++)
#pragma unroll
        for (int r = 0; r < 4; r++) accO[nt][r] = 0.f;
#pragma unroll
    for (int kt = 0; kt < 13; kt++) {
        uint32_t pa[4];
        pa[0] = packh2(accS[2 * kt][0],     accS[2 * kt][1]);
        pa[1] = packh2(accS[2 * kt][2],     accS[2 * kt][3]);
        pa[2] = packh2(accS[2 * kt + 1][0], accS[2 * kt + 1][1]);
        pa[3] = packh2(accS[2 * kt + 1][2], accS[2 * kt + 1][3]);
#pragma unroll
        for (int nt = 0; nt < 4; nt++) {
            uint32_t bf[2];
            bf[0] = *(uint32_t*)&Vp[(8 * kt + tq) * VP_STR + 8 * nt + gid];
            bf[1] = *(uint32_t*)&Vp[(8 * kt + 4 + tq) * VP_STR + 8 * nt + gid];
            mma_f16(accO[nt], pa, bf);
        }
    }
    float invA = 1.f / lA, invB = 1.f / lB;
    __half2* ob = outT2 + ((size_t)(b * (Cn / 2) + (hoff >> 1))) * Pn;
#pragma unroll
    for (int nt = 0; nt < 4; nt++) {
        int dvp = 4 * nt + tq;   // (dv)/2 within head
        ob[(size_t)dvp * Pn + iA]     = __floats2half2_rn(accO[nt][0] * invA, accO[nt][1] * invA);
        ob[(size_t)dvp * Pn + iA + 8] = __floats2half2_rn(accO[nt][2] * invB, accO[nt][3] * invB);
    }
}

// ---------------- host launch ----------------
static void* sym_addr(const void* symbol) {
    void* p = nullptr;
    cudaGetSymbolAddress(&p, symbol);
    return p;
}

extern "C" void kernel_launch(void* const* d_in, const int* in_sizes, int n_in,
                              void* d_out, int out_size) {
    const float* x     = (const float*)d_in[0];
    const float* lpu_w = (const float*)d_in[1];
    const float* lpu_b = (const float*)d_in[2];
    const float* dw_w  = (const float*)d_in[3];
    const float* dw_b  = (const float*)d_in[4];
    const float* wq    = (const float*)d_in[5];
    const float* bq    = (const float*)d_in[6];
    const float* wk    = (const float*)d_in[7];
    const float* bk    = (const float*)d_in[8];
    const float* wv    = (const float*)d_in[9];
    const float* bv    = (const float*)d_in[10];
    const float* wo    = (const float*)d_in[11];
    const float* bo    = (const float*)d_in[12];
    const float* pos_b = (const float*)d_in[13];
    const float* c1_w  = (const float*)d_in[14];
    const float* c1_b  = (const float*)d_in[15];
    const float* bn1_g = (const float*)d_in[16];
    const float* bn1_b = (const float*)d_in[17];
    const float* bn1_m = (const float*)d_in[18];
    const float* bn1_v = (const float*)d_in[19];
    const float* dw2_w = (const float*)d_in[20];
    const float* dw2_b = (const float*)d_in[21];
    const float* bn2_g = (const float*)d_in[22];
    const float* bn2_b = (const float*)d_in[23];
    const float* bn2_m = (const float*)d_in[24];
    const float* bn2_v = (const float*)d_in[25];
    const float* c2_w  = (const float*)d_in[26];
    const float* c2_b  = (const float*)d_in[27];
    const float* bn3_g = (const float*)d_in[28];
    const float* bn3_b = (const float*)d_in[29];
    const float* bn3_m = (const float*)d_in[30];
    const float* bn3_v = (const float*)d_in[31];
    float* out = (float*)d_out;

    float*   x1    = (float*)sym_addr(g_x1);
    float*   kvb   = (float*)sym_addr(g_kv);
    float*   x2    = (float*)sym_addr(g_x2);
    float*   t1    = (float*)sym_addr(g_t1);
    __half*  qh    = (__half*)sym_addr(g_qh);
    __half*  kh    = (__half*)sym_addr(g_kh);
    __half*  vh    = (__half*)sym_addr(g_vh);
    __half2* attTh = (__half2*)sym_addr(g_attTh);
    __half2* t2h   = (__half2*)sym_addr(g_t2h);
    __half2* wqh   = (__half2*)sym_addr(g_wqh);
    __half2* wkh   = (__half2*)sym_addr(g_wkh);
    __half2* wvh   = (__half2*)sym_addr(g_wvh);
    __half2* woh   = (__half2*)sym_addr(g_woh);
    __half2* c1h   = (__half2*)sym_addr(g_c1h);
    __half2* c2h   = (__half2*)sym_addr(g_c2h);
    float2*  part  = (float2*)sym_addr(g_part);
    float2*  mr    = (float2*)sym_addr(g_mr);

    dim3 tb(32, 8);
    // weight packs -> fp16 k-paired [k/2][m]
    k_wpack4<<<dim3(8, 8, 4), tb>>>(wq, wk, wv, wo, wqh, wkh, wvh, woh);
    k_wpack<<<dim3(CMn / 32, Cn / 32), tb>>>(c1_w, c1h, CMn, Cn);
    k_wpack<<<dim3(Cn / 32, CMn / 32), tb>>>(c2_w, c2h, Cn, CMn);

    // 1. LPU -> x1 (channel-major, fp32)
    k_lpu<<<Bn * Cn, 224>>>(x, lpu_w, lpu_b, x1);
    // 2. LN1 stats
    k_stats_part<<<dim3(Bn, 8), 256>>>(x1, part);
    k_stats_fin<<<1, 256>>>(part, mr);
    // 3. KV downsample
    k_kvconv<<<(Bn * Cn * NKn + 255) / 256, 256>>>(x1, dw_w, dw_b, kvb);
    // 4. Q projection (LN fused) -> qh fp16 row-major
    k_mma<0, true, false><<<dim3(7, 2, Bn), 256, SMEM_MMA>>>(
        wqh, x1, bq, nullptr, nullptr, nullptr, nullptr, mr, nullptr, qh, Cn, Cn, Pn);
    // 5. K, V projections -> kh, vh fp16
    k_mma<0, false, false><<<dim3(2, 2, Bn), 256, SMEM_MMA>>>(
        wkh, kvb, bk, nullptr, nullptr, nullptr, nullptr, nullptr, nullptr, kh, Cn, Cn, NKn);
    k_mma<0, false, false><<<dim3(2, 2, Bn), 256, SMEM_MMA>>>(
        wvh, kvb, bv, nullptr, nullptr, nullptr, nullptr, nullptr, nullptr, vh, Cn, Cn, NKn);
    // 6. attention -> attTh half2-paired channel-major
    k_attn_mma<<<dim3(7, NH, Bn), 224>>>(qh, kh, vh, pos_b, attTh);
    // 7. O projection + flat residual -> x2 fp32
    k_mma<1, false, true><<<dim3(7, 2, Bn), 256, SMEM_MMA>>>(
        woh, attTh, bo, nullptr, nullptr, nullptr, nullptr, nullptr, x1, x2, Cn, Cn, Pn);
    // 8. LN2 stats
    k_stats_part<<<dim3(Bn, 8), 256>>>(x2, part);
    k_stats_fin<<<1, 256>>>(part, mr);
    // 9. c1 + BN1 + GELU (LN fused) -> t1 fp32 channel-major
    k_mma<2, true, false><<<dim3(7, 8, Bn), 256, SMEM_MMA>>>(
        c1h, x2, c1_b, bn1_g, bn1_b, bn1_m, bn1_v, mr, nullptr, t1, CMn, Cn, Pn);
    // 10. dw2 + BN2 + GELU -> t2h half2-paired
    k_dw2pair<<<Bn * (CMn / 2), 224>>>(t1, dw2_w, dw2_b, bn2_g, bn2_b, bn2_m, bn2_v, t2h);
    // 11. c2 + BN3 + channel-major residual -> d_out fp32
    k_mma<3, false, true><<<dim3(7, 2, Bn), 256, SMEM_MMA>>>(
        c2h, t2h, c2_b, bn3_g, bn3_b, bn3_m, bn3_v, nullptr, x2, out, Cn, CMn, Pn);
}

// round 9
// speedup vs baseline: 4.6045x; 1.0663x over previous
#include <cuda_runtime.h>
#include <cuda_fp16.h>
#include <math.h>
#include <stdint.h>

// ---------------- problem constants ----------------
#define Bn   32
#define Cn   256
#define Hn   28
#define Wn   28
#define Pn   784          // H*W
#define NKn  196          // (H/2)*(W/2)
#define HKn  14
#define CMn  1024         // C * R
#define NH   8
#define DKn  32
#define EPSf 1e-5f

// ---------------- scratch (device globals; padded for unguarded tile loads) ----------------
__device__ float   g_x1 [Bn*Cn*Pn + 256];        // after LPU (channel-major)
__device__ float   g_kv [Bn*Cn*NKn + 256];       // stride-2 dw conv out [c][196]
__device__ float   g_x2 [Bn*Cn*Pn + 256];        // after attn residual (flat)
__device__ __half  g_qh [Bn*Pn*Cn];              // Q fp16 row-major [p][oc]
__device__ __half  g_kh [Bn*NKn*Cn];             // K fp16 [nk][256]
__device__ __half  g_vh [Bn*NKn*Cn];             // V fp16 [nk][256]
__device__ __half2 g_attTh[Bn*(Cn/2)*Pn + 256];  // attn out, channel-PAIR-major
__device__ __half2 g_t1h  [Bn*(CMn/2)*Pn + 256]; // c1 out, channel-PAIR-major fp16
__device__ __half2 g_t2h  [Bn*(CMn/2)*Pn + 256]; // dw2 out, channel-PAIR-major
__device__ __half2 g_wqh[(Cn/2)*Cn];             // weights k-paired [k/2][m]
__device__ __half2 g_wkh[(Cn/2)*Cn];
__device__ __half2 g_wvh[(Cn/2)*Cn];
__device__ __half2 g_woh[(Cn/2)*Cn];
__device__ __half2 g_c1h[(Cn/2)*CMn];
__device__ __half2 g_c2h[(CMn/2)*Cn];
__device__ float2  g_partl[Bn*Cn];               // LPU per-plane LN1 partials
__device__ float2  g_parto[Bn*14];               // O-proj per-block LN2 partials
__device__ float2  g_mr  [Bn];

__device__ __forceinline__ float gelu_f(float v) {
    return 0.5f * v * (1.0f + erff(v * 0.7071067811865475f));
}
__device__ __forceinline__ void mma_f16(float* c, const uint32_t* a, const uint32_t* b) {
    asm volatile(
        "mma.sync.aligned.m16n8k16.row.col.f32.f16.f16.f32 "
        "{%0,%1,%2,%3}, {%4,%5,%6,%7}, {%8,%9}, {%0,%1,%2,%3};"
        : "+f"(c[0]), "+f"(c[1]), "+f"(c[2]), "+f"(c[3])
        : "r"(a[0]), "r"(a[1]), "r"(a[2]), "r"(a[3]), "r"(b[0]), "r"(b[1]));
}
__device__ __forceinline__ uint32_t packh2(float lo, float hi) {
    __half2 h = __floats2half2_rn(lo, hi);
    return *(uint32_t*)&h;
}

// ====================== fp16 mma.sync GEMM ======================
// D[m][p] = sum_k W[m][k] * X[k][p]  per batch.
// MODE 0: half out[p*M+m] = D + bias
// MODE 1: f32  out[p*M+m] = D + bias + res; block LN partials -> pstat
// MODE 2: half2 out[(m/2)*P+p] pair = gelu(BN(D + bias))
// MODE 3: f32  out[m*P+p] = BN(D + bias) + res
#define H2STR 136
#define KSTR  132
#define SMEM_MMA (64*KSTR*4)

template <int MODE, bool LNB, bool BH>
__global__ void __launch_bounds__(256, 2) k_mma(
    const __half2* __restrict__ Wh, const void* __restrict__ Xv,
    const float* __restrict__ bias,
    const float* __restrict__ bng, const float* __restrict__ bnb,
    const float* __restrict__ bnm, const float* __restrict__ bnv,
    const float2* __restrict__ mr, const float* __restrict__ res,
    float2* __restrict__ pstat,
    void* __restrict__ outv, int M, int K, int P) {
    extern __shared__ float sm[];
    __half2* As2 = (__half2*)sm;             // [16][H2STR]
    __half2* Bs2 = As2 + 16 * H2STR;
    const int tid  = threadIdx.x;
    const int warp = tid >> 5, lane = tid & 31;
    const int gid = lane >> 2, tq = lane & 3;
    const int wm = (warp & 1) * 64;
    const int wn = (warp >> 1) * 32;
    const int b  = blockIdx.z;
    const int m0 = blockIdx.y * 128;
    const int n0 = blockIdx.x * 128;
    const float*   Xf  = BH ? nullptr : (const float*)Xv + (size_t)b * K * P;
    const __half2* Xh2 = BH ? (const __half2*)Xv + (size_t)b * (K >> 1) * P : nullptr;
    float mean = 0.f, rstd = 1.f;
    if (LNB) { float2 v = mr[b]; mean = v.x; rstd = v.y; }

    float acc[4][4][4];
#pragma unroll
    for (int i = 0; i < 4; i++)
#pragma unroll
        for (int j = 0; j < 4; j++)
#pragma unroll
            for (int r = 0; r < 4; r++) acc[i][j][r] = 0.f;

    const int kk = tid >> 4;
    const int mq = (tid & 15) * 8;
    uint4 pa0, pa1, pb0, pb1;
    const int T = K >> 5;

    auto load_chunk = [&](int kc0) {
        const uint4* wr = (const uint4*)(Wh + (size_t)((kc0 >> 1) + kk) * M + m0 + mq);
        pa0 = wr[0]; pa1 = wr[1];
        if (BH) {
            const uint4* xr = (const uint4*)(Xh2 + (size_t)((kc0 >> 1) + kk) * P + n0 + mq);
            pb0 = xr[0]; pb1 = xr[1];
        } else {
            const float* xr0 = Xf + (size_t)(kc0 + 2 * kk) * P + n0 + mq;
            const float* xr1 = xr0 + P;
            float4 b0 = *(const float4*)xr0;
            float4 b1 = *(const float4*)(xr0 + 4);
            float4 b2 = *(const float4*)xr1;
            float4 b3 = *(const float4*)(xr1 + 4);
            if (LNB) {
                b0.x=(b0.x-mean)*rstd; b0.y=(b0.y-mean)*rstd; b0.z=(b0.z-mean)*rstd; b0.w=(b0.w-mean)*rstd;
                b1.x=(b1.x-mean)*rstd; b1.y=(b1.y-mean)*rstd; b1.z=(b1.z-mean)*rstd; b1.w=(b1.w-mean)*rstd;
                b2.x=(b2.x-mean)*rstd; b2.y=(b2.y-mean)*rstd; b2.z=(b2.z-mean)*rstd; b2.w=(b2.w-mean)*rstd;
                b3.x=(b3.x-mean)*rstd; b3.y=(b3.y-mean)*rstd; b3.z=(b3.z-mean)*rstd; b3.w=(b3.w-mean)*rstd;
            }
            pb0 = make_uint4(packh2(b0.x, b2.x), packh2(b0.y, b2.y),
                             packh2(b0.z, b2.z), packh2(b0.w, b2.w));
            pb1 = make_uint4(packh2(b1.x, b3.x), packh2(b1.y, b3.y),
                             packh2(b1.z, b3.z), packh2(b1.w, b3.w));
        }
    };
    auto store_chunk = [&]() {
        *(uint4*)&As2[kk * H2STR + mq]     = pa0;
        *(uint4*)&As2[kk * H2STR + mq + 4] = pa1;
        *(uint4*)&Bs2[kk * H2STR + mq]     = pb0;
        *(uint4*)&Bs2[kk * H2STR + mq + 4] = pb1;
    };

    load_chunk(0);
    store_chunk();
    __syncthreads();

    for (int t = 0; t < T; t++) {
        if (t + 1 < T) load_chunk((t + 1) << 5);
#pragma unroll
        for (int ks = 0; ks < 2; ks++) {
            const int r0 = ks * 8;
            uint32_t af[4][4], bf[4][2];
#pragma unroll
            for (int i = 0; i < 4; i++) {
                int m = wm + i * 16 + gid;
                af[i][0] = *(uint32_t*)&As2[(r0 + tq) * H2STR + m];
                af[i][1] = *(uint32_t*)&As2[(r0 + tq) * H2STR + m + 8];
                af[i][2] = *(uint32_t*)&As2[(r0 + tq + 4) * H2STR + m];
                af[i][3] = *(uint32_t*)&As2[(r0 + tq + 4) * H2STR + m + 8];
            }
#pragma unroll
            for (int j = 0; j < 4; j++) {
                int p = wn + j * 8 + gid;
                bf[j][0] = *(uint32_t*)&Bs2[(r0 + tq) * H2STR + p];
                bf[j][1] = *(uint32_t*)&Bs2[(r0 + tq + 4) * H2STR + p];
            }
#pragma unroll
            for (int i = 0; i < 4; i++)
#pragma unroll
                for (int j = 0; j < 4; j++) mma_f16(acc[i][j], af[i], bf[j]);
        }
        if (t + 1 < T) {
            __syncthreads();
            store_chunk();
            __syncthreads();
        }
    }

    // ---- epilogue: two 64-row passes staged through smem ----
    float* sD = sm;
    float*   outf  = (MODE == 1 || MODE == 3) ? (float*)outv + (size_t)b * (size_t)M * P : nullptr;
    __half*  outh  = (MODE == 0) ? (__half*)outv + (size_t)b * (size_t)M * P : nullptr;
    __half2* outh2 = (MODE == 2) ? (__half2*)outv + (size_t)b * (size_t)(M >> 1) * P : nullptr;
    const float* resb = (MODE == 1 || MODE == 3) ? res + (size_t)b * (size_t)M * P : nullptr;
    float osum = 0.f, osq = 0.f;

#pragma unroll
    for (int pass = 0; pass < 2; pass++) {
        __syncthreads();
        if (MODE <= 1) {
            if ((wn >> 6) == pass) {
#pragma unroll
                for (int i = 0; i < 4; i++) {
                    int mrow = wm + i * 16 + gid;
#pragma unroll
                    for (int j = 0; j < 4; j++) {
                        int pc = (wn & 63) + j * 8 + 2 * tq;
                        sD[pc * KSTR + mrow]           = acc[i][j][0];
                        sD[(pc + 1) * KSTR + mrow]     = acc[i][j][1];
                        sD[pc * KSTR + mrow + 8]       = acc[i][j][2];
                        sD[(pc + 1) * KSTR + mrow + 8] = acc[i][j][3];
                    }
                }
            }
        } else {
            if ((wm >> 6) == pass) {
#pragma unroll
                for (int i = 0; i < 4; i++) {
                    int ml = (wm & 63) + i * 16 + gid;
#pragma unroll
                    for (int j = 0; j < 4; j++) {
                        int pc = wn + j * 8 + 2 * tq;
                        sD[ml * KSTR + pc]           = acc[i][j][0];
                        sD[ml * KSTR + pc + 1]       = acc[i][j][1];
                        sD[(ml + 8) * KSTR + pc]     = acc[i][j][2];
                        sD[(ml + 8) * KSTR + pc + 1] = acc[i][j][3];
                    }
                }
            }
        }
        __syncthreads();
        if (MODE <= 1) {
            for (int l = tid; l < 64 * 32; l += 256) {
                int rl = l >> 5, cq = (l & 31) * 4;
                int p = n0 + pass * 64 + rl;
                if (p >= P) continue;
                float4 v = *(float4*)&sD[rl * KSTR + cq];
                float4 bb = *(const float4*)(bias + m0 + cq);
                v.x += bb.x; v.y += bb.y; v.z += bb.z; v.w += bb.w;
                size_t off = (size_t)p * M + m0 + cq;
                if (MODE == 0) {
                    __half2 h01 = __floats2half2_rn(v.x, v.y);
                    __half2 h23 = __floats2half2_rn(v.z, v.w);
                    uint2 u = make_uint2(*(uint32_t*)&h01, *(uint32_t*)&h23);
                    *(uint2*)(outh + off) = u;
                } else {
                    float4 rr = *(const float4*)(resb + off);
                    v.x += rr.x; v.y += rr.y; v.z += rr.z; v.w += rr.w;
                    *(float4*)(outf + off) = v;
                    osum += v.x + v.y + v.z + v.w;
                    osq  += v.x * v.x + v.y * v.y + v.z * v.z + v.w * v.w;
                }
            }
        } else if (MODE == 2) {
            // half2 channel-pair output: pair rows (2rp, 2rp+1) within pass
            for (int l = tid; l < 32 * 32; l += 256) {
                int rp = l >> 5, cq = (l & 31) * 4;
                int m = m0 + pass * 64 + 2 * rp;
                int p = n0 + cq;
                if (p >= P) continue;
                float sc0 = bng[m] * rsqrtf(bnv[m] + EPSf);
                float sh0 = bnb[m] - bnm[m] * sc0 + bias[m] * sc0;
                float sc1 = bng[m + 1] * rsqrtf(bnv[m + 1] + EPSf);
                float sh1 = bnb[m + 1] - bnm[m + 1] * sc1 + bias[m + 1] * sc1;
                float4 v0 = *(float4*)&sD[(2 * rp) * KSTR + cq];
                float4 v1 = *(float4*)&sD[(2 * rp + 1) * KSTR + cq];
                v0.x = gelu_f(v0.x * sc0 + sh0); v0.y = gelu_f(v0.y * sc0 + sh0);
                v0.z = gelu_f(v0.z * sc0 + sh0); v0.w = gelu_f(v0.w * sc0 + sh0);
                v1.x = gelu_f(v1.x * sc1 + sh1); v1.y = gelu_f(v1.y * sc1 + sh1);
                v1.z = gelu_f(v1.z * sc1 + sh1); v1.w = gelu_f(v1.w * sc1 + sh1);
                uint4 u = make_uint4(packh2(v0.x, v1.x), packh2(v0.y, v1.y),
                                     packh2(v0.z, v1.z), packh2(v0.w, v1.w));
                *(uint4*)(outh2 + (size_t)(m >> 1) * P + p) = u;
            }
        } else {
            for (int l = tid; l < 64 * 32; l += 256) {
                int rl = l >> 5, cq = (l & 31) * 4;
                int m = m0 + pass * 64 + rl;
                int p = n0 + cq;
                if (p >= P) continue;
                float scale = bng[m] * rsqrtf(bnv[m] + EPSf);
                float shift = bnb[m] - bnm[m] * scale + bias[m] * scale;
                float4 v = *(float4*)&sD[rl * KSTR + cq];
                v.x = v.x * scale + shift; v.y = v.y * scale + shift;
                v.z = v.z * scale + shift; v.w = v.w * scale + shift;
                size_t off = (size_t)m * P + p;
                float4 rr = *(const float4*)(resb + off);
                v.x += rr.x; v.y += rr.y; v.z += rr.z; v.w += rr.w;
                *(float4*)(outf + off) = v;
            }
        }
    }

    if (MODE == 1) {
        // LN2 block partials (deterministic: fixed tree)
        __syncthreads();
        float* r1 = sm;
        float* r2 = sm + 256;
        r1[tid] = osum; r2[tid] = osq;
        __syncthreads();
        for (int st = 128; st > 0; st >>= 1) {
            if (tid < st) { r1[tid] += r1[tid + st]; r2[tid] += r2[tid + st]; }
            __syncthreads();
        }
        if (tid == 0)
            pstat[b * 14 + blockIdx.y * gridDim.x + blockIdx.x] = make_float2(r1[0], r2[0]);
    }
}

// ---------------- weight pack: w [M][K] f32 -> wh half2 k-paired [K/2][M] ----------------
__global__ void k_wpack(const float* __restrict__ w, __half2* __restrict__ wh, int M, int K) {
    __shared__ float t[32][33];
    int m0 = blockIdx.x * 32, k0 = blockIdx.y * 32;
    int tx = threadIdx.x, ty = threadIdx.y;
#pragma unroll
    for (int q = 0; q < 32; q += 8)
        t[ty + q][tx] = w[(size_t)(m0 + ty + q) * K + k0 + tx];
    __syncthreads();
#pragma unroll
    for (int q = 0; q < 2; q++) {
        int kp = ty + q * 8;
        __half2 val = __floats2half2_rn(t[tx][2 * kp], t[tx][2 * kp + 1]);
        wh[(size_t)((k0 >> 1) + kp) * M + m0 + tx] = val;
    }
}

__global__ void k_wpack4(const float* __restrict__ p0, const float* __restrict__ p1,
                         const float* __restrict__ p2, const float* __restrict__ p3,
                         __half2* __restrict__ o0, __half2* __restrict__ o1,
                         __half2* __restrict__ o2, __half2* __restrict__ o3) {
    __shared__ float t[32][33];
    const float* in = (blockIdx.z == 0) ? p0 : (blockIdx.z == 1) ? p1 : (blockIdx.z == 2) ? p2 : p3;
    __half2*    out = (blockIdx.z == 0) ? o0 : (blockIdx.z == 1) ? o1 : (blockIdx.z == 2) ? o2 : o3;
    int m0 = blockIdx.x * 32, k0 = blockIdx.y * 32;
    int tx = threadIdx.x, ty = threadIdx.y;
#pragma unroll
    for (int q = 0; q < 32; q += 8)
        t[ty + q][tx] = in[(size_t)(m0 + ty + q) * Cn + k0 + tx];
    __syncthreads();
#pragma unroll
    for (int q = 0; q < 2; q++) {
        int kp = ty + q * 8;
        __half2 val = __floats2half2_rn(t[tx][2 * kp], t[tx][2 * kp + 1]);
        out[(size_t)((k0 >> 1) + kp) * Cn + m0 + tx] = val;
    }
}

// ------- fused LPU: dw3x3+bias+residual -> x1, plus KV downsample + LN1 partials -------
__global__ void __launch_bounds__(224) k_lpu_fused(
    const float* __restrict__ X, const float* __restrict__ w,
    const float* __restrict__ bias,
    const float* __restrict__ wkv, const float* __restrict__ bkv,
    float* __restrict__ x1, float* __restrict__ kv, float2* __restrict__ partl) {
    __shared__ float sp[900];
    __shared__ float so[784];
    __shared__ float r1[224], r2[224];
    int bc = blockIdx.x;
    int c  = bc & (Cn - 1);
    const float* xin = X + (size_t)bc * Pn;
    int tid = threadIdx.x;
    for (int i = tid; i < 900; i += 224) sp[i] = 0.f;
    float wc[9];
#pragma unroll
    for (int i = 0; i < 9; i++) wc[i] = w[c * 9 + i];
    float bsv = bias[c];
    __syncthreads();
    for (int i = tid; i < Pn; i += 224) sp[(i / 28 + 1) * 30 + (i % 28) + 1] = xin[i];
    __syncthreads();
    float lsum = 0.f, lsq = 0.f;
    if (tid < 196) {
        int px = tid % 28, sy = (tid / 28) * 4;
        float a[6][3];
#pragma unroll
        for (int dr = 0; dr < 6; dr++) {
            const float* r = sp + (sy + dr) * 30 + px;
            a[dr][0] = r[0]; a[dr][1] = r[1]; a[dr][2] = r[2];
        }
        float* ob = x1 + (size_t)bc * Pn;
#pragma unroll
        for (int i = 0; i < 4; i++) {
            float acc = bsv
                + wc[0] * a[i][0]     + wc[1] * a[i][1]     + wc[2] * a[i][2]
                + wc[3] * a[i + 1][0] + wc[4] * a[i + 1][1] + wc[5] * a[i + 1][2]
                + wc[6] * a[i + 2][0] + wc[7] * a[i + 2][1] + wc[8] * a[i + 2][2];
            float y = acc + a[i + 1][1];
            so[(sy + i) * 28 + px] = y;
            ob[(sy + i) * 28 + px] = y;
            lsum += y; lsq += y * y;
        }
    }
    r1[tid] = lsum; r2[tid] = lsq;
    __syncthreads();
    for (int st = 112; st >= 7; st >>= 1) {
        if (tid < st) { r1[tid] += r1[tid + st]; r2[tid] += r2[tid + st]; }
        __syncthreads();
    }
    if (tid == 0) {
        float s = 0.f, qv = 0.f;
#pragma unroll
        for (int i = 0; i < 7; i++) { s += r1[i]; qv += r2[i]; }
        partl[bc] = make_float2(s, qv);
    }
    // KV downsample from LPU output in smem
    if (tid < 196) {
        int oy = tid / HKn, ox = tid % HKn;
        float acc = bkv[c]
            + wkv[c * 4 + 0] * so[(2 * oy) * 28 + 2 * ox]
            + wkv[c * 4 + 1] * so[(2 * oy) * 28 + 2 * ox + 1]
            + wkv[c * 4 + 2] * so[(2 * oy + 1) * 28 + 2 * ox]
            + wkv[c * 4 + 3] * so[(2 * oy + 1) * 28 + 2 * ox + 1];
        kv[(size_t)bc * NKn + tid] = acc;
    }
}

// ---------------- LN finishers ----------------
__global__ void k_stats_fin_l(const float2* __restrict__ partl, float2* __restrict__ mr) {
    int b = blockIdx.x, t = threadIdx.x;
    __shared__ float r1[256], r2[256];
    float2 p = partl[b * Cn + t];
    r1[t] = p.x; r2[t] = p.y;
    __syncthreads();
    for (int st = 128; st > 0; st >>= 1) {
        if (t < st) { r1[t] += r1[t + st]; r2[t] += r2[t + st]; }
        __syncthreads();
    }
    if (t == 0) {
        const float n = (float)(Cn * Pn);
        float m  = r1[0] / n;
        float vv = r2[0] / n - m * m;
        mr[b] = make_float2(m, rsqrtf(vv + EPSf));
    }
}

__global__ void k_stats_fin_o(const float2* __restrict__ parto, float2* __restrict__ mr) {
    int b = blockIdx.x, t = threadIdx.x;  // 32 threads
    float2 p = (t < 14) ? parto[b * 14 + t] : make_float2(0.f, 0.f);
#pragma unroll
    for (int o = 16; o >= 1; o >>= 1) {
        p.x += __shfl_down_sync(0xffffffffu, p.x, o);
        p.y += __shfl_down_sync(0xffffffffu, p.y, o);
    }
    if (t == 0) {
        const float n = (float)(Cn * Pn);
        float m  = p.x / n;
        float vv = p.y / n - m * m;
        mr[b] = make_float2(m, rsqrtf(vv + EPSf));
    }
}

// ---------------- dw2: channel-pair fp16 in, BN+GELU, half2-paired output ----------------
__global__ void __launch_bounds__(224) k_dw2pair(
    const __half2* __restrict__ X2, const float* __restrict__ w,
    const float* __restrict__ bias,
    const float* __restrict__ bng, const float* __restrict__ bnb,
    const float* __restrict__ bnm, const float* __restrict__ bnv,
    __half2* __restrict__ out2) {
    __shared__ float sp0[900], sp1[900];
    int bc = blockIdx.x;
    int b  = bc >> 9;            // CMn/2 = 512
    int mp = bc & 511;
    int c0 = 2 * mp;
    const __half2* x0 = X2 + ((size_t)b * (CMn / 2) + mp) * Pn;
    int tid = threadIdx.x;
    for (int i = tid; i < 900; i += 224) { sp0[i] = 0.f; sp1[i] = 0.f; }
    float wa[9], wb[9];
#pragma unroll
    for (int i = 0; i < 9; i++) { wa[i] = w[c0 * 9 + i]; wb[i] = w[(c0 + 1) * 9 + i]; }
    float bs0 = bias[c0], bs1 = bias[c0 + 1];
    float sc0 = bng[c0] * rsqrtf(bnv[c0] + EPSf);
    float sh0 = bnb[c0] - bnm[c0] * sc0;
    float sc1 = bng[c0 + 1] * rsqrtf(bnv[c0 + 1] + EPSf);
    float sh1 = bnb[c0 + 1] - bnm[c0 + 1] * sc1;
    __syncthreads();
    for (int i = tid; i < Pn; i += 224) {
        int o = (i / 28 + 1) * 30 + (i % 28) + 1;
        float2 f = __half22float2(x0[i]);
        sp0[o] = f.x;
        sp1[o] = f.y;
    }
    __syncthreads();
    if (tid < 196) {
        int px = tid % 28, sy = (tid / 28) * 4;
        float a0[6][3], a1[6][3];
#pragma unroll
        for (int dr = 0; dr < 6; dr++) {
            int base = (sy + dr) * 30 + px;
            a0[dr][0] = sp0[base]; a0[dr][1] = sp0[base + 1]; a0[dr][2] = sp0[base + 2];
            a1[dr][0] = sp1[base]; a1[dr][1] = sp1[base + 1]; a1[dr][2] = sp1[base + 2];
        }
        __half2* ob = out2 + ((size_t)b * (CMn / 2) + mp) * Pn;
#pragma unroll
        for (int i = 0; i < 4; i++) {
            float acc0 = bs0
                + wa[0] * a0[i][0]     + wa[1] * a0[i][1]     + wa[2] * a0[i][2]
                + wa[3] * a0[i + 1][0] + wa[4] * a0[i + 1][1] + wa[5] * a0[i + 1][2]
                + wa[6] * a0[i + 2][0] + wa[7] * a0[i + 2][1] + wa[8] * a0[i + 2][2];
            float acc1 = bs1
                + wb[0] * a1[i][0]     + wb[1] * a1[i][1]     + wb[2] * a1[i][2]
                + wb[3] * a1[i + 1][0] + wb[4] * a1[i + 1][1] + wb[5] * a1[i + 1][2]
                + wb[6] * a1[i + 2][0] + wb[7] * a1[i + 2][1] + wb[8] * a1[i + 2][2];
            float y0 = gelu_f(acc0 * sc0 + sh0);
            float y1 = gelu_f(acc1 * sc1 + sh1);
            ob[(sy + i) * 28 + px] = __floats2half2_rn(y0, y1);
        }
    }
}

// ================= fp16 mma attention =================
#define KP_STR 20
#define VP_STR 40

__global__ void __launch_bounds__(224, 1) k_attn_mma(
    const __half* __restrict__ q, const __half* __restrict__ k,
    const __half* __restrict__ v, const float* __restrict__ pos,
    __half2* __restrict__ outT2) {
    __shared__ __half2 Kp[208 * KP_STR];
    __shared__ __half2 Vp[104 * VP_STR];
    const int tid = threadIdx.x;
    const int warp = tid >> 5, lane = tid & 31;
    const int gid = lane >> 2, tq = lane & 3;
    const int qt = blockIdx.x;
    const int h  = blockIdx.y;
    const int b  = blockIdx.z;
    const int hoff = h * DKn;

    for (int idx = tid; idx < 208 * 16; idx += 224) {
        int key = idx >> 4, e = idx & 15;
        __half2 val = __floats2half2_rn(0.f, 0.f);
        if (key < NKn)
            val = *(const __half2*)(k + ((size_t)(b * NKn + key)) * Cn + hoff + 2 * e);
        Kp[key * KP_STR + e] = val;
    }
    for (int idx = tid; idx < 104 * 32; idx += 224) {
        int kp = idx >> 5, dv = idx & 31;
        int k0 = 2 * kp, k1 = 2 * kp + 1;
        __half f0 = (k0 < NKn) ? v[((size_t)(b * NKn + k0)) * Cn + hoff + dv] : __float2half(0.f);
        __half f1 = (k1 < NKn) ? v[((size_t)(b * NKn + k1)) * Cn + hoff + dv] : __float2half(0.f);
        Vp[kp * VP_STR + dv] = __halves2half2(f0, f1);
    }
    __syncthreads();

    const int iA = qt * 112 + warp * 16 + gid;

    uint32_t aq[2][4];
    {
        const __half* q0 = q + ((size_t)(b * Pn + iA)) * Cn + hoff;
        const __half* q1 = q0 + 8 * Cn;
#pragma unroll
        for (int kt = 0; kt < 2; kt++) {
            aq[kt][0] = *(const uint32_t*)(q0 + 16 * kt + 2 * tq);
            aq[kt][1] = *(const uint32_t*)(q1 + 16 * kt + 2 * tq);
            aq[kt][2] = *(const uint32_t*)(q0 + 16 * kt + 8 + 2 * tq);
            aq[kt][3] = *(const uint32_t*)(q1 + 16 * kt + 8 + 2 * tq);
        }
    }

    float accS[26][4];
#pragma unroll
    for (int jt = 0; jt < 26; jt++)
#pragma unroll
        for (int r = 0; r < 4; r++) accS[jt][r] = 0.f;
#pragma unroll
    for (int jt = 0; jt < 26; jt++) {
#pragma unroll
        for (int kt = 0; kt < 2; kt++) {
            uint32_t bf[2];
            bf[0] = *(uint32_t*)&Kp[(8 * jt + gid) * KP_STR + 8 * kt + tq];
            bf[1] = *(uint32_t*)&Kp[(8 * jt + gid) * KP_STR + 8 * kt + 4 + tq];
            mma_f16(accS[jt], aq[kt], bf);
        }
    }

    const float scale = 0.17677669529663687f;
    const float* posA = pos + ((size_t)(h * Pn + iA)) * NKn;
    const float* posB = posA + 8 * NKn;
    float mA = -1e30f, mB = -1e30f;
#pragma unroll
    for (int jt = 0; jt < 26; jt++) {
        int col = 8 * jt + 2 * tq;
        if (col < NKn) {
            float2 pA = *(const float2*)(posA + col);
            float2 pB = *(const float2*)(posB + col);
            accS[jt][0] = accS[jt][0] * scale + pA.x;
            accS[jt][1] = accS[jt][1] * scale + pA.y;
            accS[jt][2] = accS[jt][2] * scale + pB.x;
            accS[jt][3] = accS[jt][3] * scale + pB.y;
            mA = fmaxf(mA, fmaxf(accS[jt][0], accS[jt][1]));
            mB = fmaxf(mB, fmaxf(accS[jt][2], accS[jt][3]));
        } else {
            accS[jt][0] = -1e30f; accS[jt][1] = -1e30f;
            accS[jt][2] = -1e30f; accS[jt][3] = -1e30f;
        }
    }
    mA = fmaxf(mA, __shfl_xor_sync(0xffffffffu, mA, 1));
    mA = fmaxf(mA, __shfl_xor_sync(0xffffffffu, mA, 2));
    mB = fmaxf(mB, __shfl_xor_sync(0xffffffffu, mB, 1));
    mB = fmaxf(mB, __shfl_xor_sync(0xffffffffu, mB, 2));
    float lA = 0.f, lB = 0.f;
#pragma unroll
    for (int jt = 0; jt < 26; jt++) {
        accS[jt][0] = __expf(accS[jt][0] - mA);
        accS[jt][1] = __expf(accS[jt][1] - mA);
        accS[jt][2] = __expf(accS[jt][2] - mB);
        accS[jt][3] = __expf(accS[jt][3] - mB);
        lA += accS[jt][0] + accS[jt][1];
        lB += accS[jt][2] + accS[jt][3];
    }
    lA += __shfl_xor_sync(0xffffffffu, lA, 1);
    lA += __shfl_xor_sync(0xffffffffu, lA, 2);
    lB += __shfl_xor_sync(0xffffffffu, lB, 1);
    lB += __shfl_xor_sync(0xffffffffu, lB, 2);

    float accO[4][4];
#pragma unroll
    for (int nt = 0; nt < 4; nt++)
#pragma unroll
        for (int r = 0; r < 4; r++) accO[nt][r] = 0.f;
#pragma unroll
    for (int kt = 0; kt < 13; kt++) {
        uint32_t pa[4];
        pa[0] = packh2(accS[2 * kt][0],     accS[2 * kt][1]);
        pa[1] = packh2(accS[2 * kt][2],     accS[2 * kt][3]);
        pa[2] = packh2(accS[2 * kt + 1][0], accS[2 * kt + 1][1]);
        pa[3] = packh2(accS[2 * kt + 1][2], accS[2 * kt + 1][3]);
#pragma unroll
        for (int nt = 0; nt < 4; nt++) {
            uint32_t bf[2];
            bf[0] = *(uint32_t*)&Vp[(8 * kt + tq) * VP_STR + 8 * nt + gid];
            bf[1] = *(uint32_t*)&Vp[(8 * kt + 4 + tq) * VP_STR + 8 * nt + gid];
            mma_f16(accO[nt], pa, bf);
        }
    }
    float invA = 1.f / lA, invB = 1.f / lB;
    __half2* ob = outT2 + ((size_t)(b * (Cn / 2) + (hoff >> 1))) * Pn;
#pragma unroll
    for (int nt = 0; nt < 4; nt++) {
        int dvp = 4 * nt + tq;
        ob[(size_t)dvp * Pn + iA]     = __floats2half2_rn(accO[nt][0] * invA, accO[nt][1] * invA);
        ob[(size_t)dvp * Pn + iA + 8] = __floats2half2_rn(accO[nt][2] * invB, accO[nt][3] * invB);
    }
}

// ---------------- host launch ----------------
static void* sym_addr(const void* symbol) {
    void* p = nullptr;
    cudaGetSymbolAddress(&p, symbol);
    return p;
}

extern "C" void kernel_launch(void* const* d_in, const int* in_sizes, int n_in,
                              void* d_out, int out_size) {
    const float* x     = (const float*)d_in[0];
    const float* lpu_w = (const float*)d_in[1];
    const float* lpu_b = (const float*)d_in[2];
    const float* dw_w  = (const float*)d_in[3];
    const float* dw_b  = (const float*)d_in[4];
    const float* wq    = (const float*)d_in[5];
    const float* bq    = (const float*)d_in[6];
    const float* wk    = (const float*)d_in[7];
    const float* bk    = (const float*)d_in[8];
    const float* wv    = (const float*)d_in[9];
    const float* bv    = (const float*)d_in[10];
    const float* wo    = (const float*)d_in[11];
    const float* bo    = (const float*)d_in[12];
    const float* pos_b = (const float*)d_in[13];
    const float* c1_w  = (const float*)d_in[14];
    const float* c1_b  = (const float*)d_in[15];
    const float* bn1_g = (const float*)d_in[16];
    const float* bn1_b = (const float*)d_in[17];
    const float* bn1_m = (const float*)d_in[18];
    const float* bn1_v = (const float*)d_in[19];
    const float* dw2_w = (const float*)d_in[20];
    const float* dw2_b = (const float*)d_in[21];
    const float* bn2_g = (const float*)d_in[22];
    const float* bn2_b = (const float*)d_in[23];
    const float* bn2_m = (const float*)d_in[24];
    const float* bn2_v = (const float*)d_in[25];
    const float* c2_w  = (const float*)d_in[26];
    const float* c2_b  = (const float*)d_in[27];
    const float* bn3_g = (const float*)d_in[28];
    const float* bn3_b = (const float*)d_in[29];
    const float* bn3_m = (const float*)d_in[30];
    const float* bn3_v = (const float*)d_in[31];
    float* out = (float*)d_out;

    float*   x1    = (float*)sym_addr(g_x1);
    float*   kvb   = (float*)sym_addr(g_kv);
    float*   x2    = (float*)sym_addr(g_x2);
    __half*  qh    = (__half*)sym_addr(g_qh);
    __half*  kh    = (__half*)sym_addr(g_kh);
    __half*  vh    = (__half*)sym_addr(g_vh);
    __half2* attTh = (__half2*)sym_addr(g_attTh);
    __half2* t1h   = (__half2*)sym_addr(g_t1h);
    __half2* t2h   = (__half2*)sym_addr(g_t2h);
    __half2* wqh   = (__half2*)sym_addr(g_wqh);
    __half2* wkh   = (__half2*)sym_addr(g_wkh);
    __half2* wvh   = (__half2*)sym_addr(g_wvh);
    __half2* woh   = (__half2*)sym_addr(g_woh);
    __half2* c1h   = (__half2*)sym_addr(g_c1h);
    __half2* c2h   = (__half2*)sym_addr(g_c2h);
    float2*  partl = (float2*)sym_addr(g_partl);
    float2*  parto = (float2*)sym_addr(g_parto);
    float2*  mr    = (float2*)sym_addr(g_mr);

    dim3 tb(32, 8);
    // weight packs -> fp16 k-paired [k/2][m]
    k_wpack4<<<dim3(8, 8, 4), tb>>>(wq, wk, wv, wo, wqh, wkh, wvh, woh);
    k_wpack<<<dim3(CMn / 32, Cn / 32), tb>>>(c1_w, c1h, CMn, Cn);
    k_wpack<<<dim3(Cn / 32, CMn / 32), tb>>>(c2_w, c2h, Cn, CMn);

    // 1. fused LPU (+KV downsample +LN1 partials)
    k_lpu_fused<<<Bn * Cn, 224>>>(x, lpu_w, lpu_b, dw_w, dw_b, x1, kvb, partl);
    k_stats_fin_l<<<Bn, 256>>>(partl, mr);
    // 2. Q projection (LN fused) -> qh fp16
    k_mma<0, true, false><<<dim3(7, 2, Bn), 256, SMEM_MMA>>>(
        wqh, x1, bq, nullptr, nullptr, nullptr, nullptr, mr, nullptr, nullptr, qh, Cn, Cn, Pn);
    // 3. K, V projections -> kh, vh fp16
    k_mma<0, false, false><<<dim3(2, 2, Bn), 256, SMEM_MMA>>>(
        wkh, kvb, bk, nullptr, nullptr, nullptr, nullptr, nullptr, nullptr, nullptr, kh, Cn, Cn, NKn);
    k_mma<0, false, false><<<dim3(2, 2, Bn), 256, SMEM_MMA>>>(
        wvh, kvb, bv, nullptr, nullptr, nullptr, nullptr, nullptr, nullptr, nullptr, vh, Cn, Cn, NKn);
    // 4. attention -> attTh
    k_attn_mma<<<dim3(7, NH, Bn), 224>>>(qh, kh, vh, pos_b, attTh);
    // 5. O projection + flat residual -> x2 (+LN2 partials)
    k_mma<1, false, true><<<dim3(7, 2, Bn), 256, SMEM_MMA>>>(
        woh, attTh, bo, nullptr, nullptr, nullptr, nullptr, nullptr, x1, parto, x2, Cn, Cn, Pn);
    k_stats_fin_o<<<Bn, 32>>>(parto, mr);
    // 6. c1 + BN1 + GELU (LN fused) -> t1h fp16 channel-paired
    k_mma<2, true, false><<<dim3(7, 8, Bn), 256, SMEM_MMA>>>(
        c1h, x2, c1_b, bn1_g, bn1_b, bn1_m, bn1_v, mr, nullptr, nullptr, t1h, CMn, Cn, Pn);
    // 7. dw2 + BN2 + GELU -> t2h
    k_dw2pair<<<Bn * (CMn / 2), 224>>>(t1h, dw2_w, dw2_b, bn2_g, bn2_b, bn2_m, bn2_v, t2h);
    // 8. c2 + BN3 + channel-major residual -> d_out
    k_mma<3, false, true><<<dim3(7, 2, Bn), 256, SMEM_MMA>>>(
        c2h, t2h, c2_b, bn3_g, bn3_b, bn3_m, bn3_v, nullptr, x2, nullptr, out, Cn, CMn, Pn);
}

// round 10
// speedup vs baseline: 4.7071x; 1.0223x over previous
#include <cuda_runtime.h>
#include <cuda_fp16.h>
#include <math.h>
#include <stdint.h>

// ---------------- problem constants ----------------
#define Bn   32
#define Cn   256
#define Hn   28
#define Wn   28
#define Pn   784          // H*W
#define NKn  196          // (H/2)*(W/2)
#define HKn  14
#define CMn  1024         // C * R
#define NH   8
#define DKn  32
#define EPSf 1e-5f

// ---------------- scratch (device globals; padded for unguarded tile loads) ----------------
__device__ float   g_x1 [Bn*Cn*Pn + 256];        // after LPU (channel-major)
__device__ float   g_kv [Bn*Cn*NKn + 256];       // stride-2 dw conv out [c][196]
__device__ float   g_x2 [Bn*Cn*Pn + 256];        // after attn residual (flat)
__device__ __half  g_qh [Bn*Pn*Cn];              // Q fp16 row-major [p][oc]
__device__ __half  g_kh [Bn*NKn*Cn + 256];       // K fp16 [nk][256]
__device__ __half  g_vh [Bn*NKn*Cn + 256];       // V fp16 [nk][256]
__device__ __half2 g_attTh[Bn*(Cn/2)*Pn + 256];  // attn out, channel-PAIR-major
__device__ __half2 g_t1h  [Bn*(CMn/2)*Pn + 256]; // c1 out, channel-PAIR-major fp16
__device__ __half2 g_t2h  [Bn*(CMn/2)*Pn + 256]; // dw2 out, channel-PAIR-major
__device__ __half2 g_wqh[(Cn/2)*Cn];             // weights k-paired [k/2][m]
__device__ __half2 g_wkh[(Cn/2)*Cn];
__device__ __half2 g_wvh[(Cn/2)*Cn];
__device__ __half2 g_woh[(Cn/2)*Cn];
__device__ __half2 g_c1h[(Cn/2)*CMn];
__device__ __half2 g_c2h[(CMn/2)*Cn];
__device__ float2  g_partl[Bn*Cn];               // LPU per-plane LN1 partials
__device__ float2  g_parto[Bn*14];               // O-proj per-block LN2 partials
__device__ float2  g_mr  [Bn];

__device__ __forceinline__ float gelu_f(float v) {
    return 0.5f * v * (1.0f + erff(v * 0.7071067811865475f));
}
__device__ __forceinline__ void mma_f16(float* c, const uint32_t* a, const uint32_t* b) {
    asm volatile(
        "mma.sync.aligned.m16n8k16.row.col.f32.f16.f16.f32 "
        "{%0,%1,%2,%3}, {%4,%5,%6,%7}, {%8,%9}, {%0,%1,%2,%3};"
        : "+f"(c[0]), "+f"(c[1]), "+f"(c[2]), "+f"(c[3])
        : "r"(a[0]), "r"(a[1]), "r"(a[2]), "r"(a[3]), "r"(b[0]), "r"(b[1]));
}
__device__ __forceinline__ uint32_t packh2(float lo, float hi) {
    __half2 h = __floats2half2_rn(lo, hi);
    return *(uint32_t*)&h;
}

#define H2STR 136
#define KSTR  132
#define STAGE (32*H2STR)              // half2 per stage (As 16*H2STR + Bs 16*H2STR)
#define SMEM_MMA (2*STAGE*4)          // 34816 B >= epilogue 64*132*4

// ====================== fp16 mma.sync GEMM (double-buffer, 1 sync/chunk) ======================
// MODE 1: f32 out[p*M+m] = D + bias + res; block LN partials -> pstat
// MODE 2: half2 out[(m/2)*P+p] = gelu(BN(D + bias))
// MODE 3: f32 out[m*P+p] = BN(D + bias) + res
template <int MODE, bool LNB, bool BH>
__global__ void __launch_bounds__(256, 2) k_mma(
    const __half2* __restrict__ Wh, const void* __restrict__ Xv,
    const float* __restrict__ bias,
    const float* __restrict__ bng, const float* __restrict__ bnb,
    const float* __restrict__ bnm, const float* __restrict__ bnv,
    const float2* __restrict__ mr, const float* __restrict__ res,
    float2* __restrict__ pstat,
    void* __restrict__ outv, int M, int K, int P) {
    extern __shared__ float sm[];
    const int tid  = threadIdx.x;
    const int warp = tid >> 5, lane = tid & 31;
    const int gid = lane >> 2, tq = lane & 3;
    const int wm = (warp & 1) * 64;
    const int wn = (warp >> 1) * 32;
    const int b  = blockIdx.z;
    const int m0 = blockIdx.y * 128;
    const int n0 = blockIdx.x * 128;
    const float*   Xf  = BH ? nullptr : (const float*)Xv + (size_t)b * K * P;
    const __half2* Xh2 = BH ? (const __half2*)Xv + (size_t)b * (K >> 1) * P : nullptr;
    float mean = 0.f, rstd = 1.f;
    if (LNB) { float2 v = mr[b]; mean = v.x; rstd = v.y; }

    float acc[4][4][4];
#pragma unroll
    for (int i = 0; i < 4; i++)
#pragma unroll
        for (int j = 0; j < 4; j++)
#pragma unroll
            for (int r = 0; r < 4; r++) acc[i][j][r] = 0.f;

    const int kk = tid >> 4;
    const int mq = (tid & 15) * 8;
    uint4 pa0, pa1, pb0, pb1;
    const int T = K >> 5;

    auto load_chunk = [&](int kc0) {
        const uint4* wr = (const uint4*)(Wh + (size_t)((kc0 >> 1) + kk) * M + m0 + mq);
        pa0 = wr[0]; pa1 = wr[1];
        if (BH) {
            const uint4* xr = (const uint4*)(Xh2 + (size_t)((kc0 >> 1) + kk) * P + n0 + mq);
            pb0 = xr[0]; pb1 = xr[1];
        } else {
            const float* xr0 = Xf + (size_t)(kc0 + 2 * kk) * P + n0 + mq;
            const float* xr1 = xr0 + P;
            float4 b0 = *(const float4*)xr0;
            float4 b1 = *(const float4*)(xr0 + 4);
            float4 b2 = *(const float4*)xr1;
            float4 b3 = *(const float4*)(xr1 + 4);
            if (LNB) {
                b0.x=(b0.x-mean)*rstd; b0.y=(b0.y-mean)*rstd; b0.z=(b0.z-mean)*rstd; b0.w=(b0.w-mean)*rstd;
                b1.x=(b1.x-mean)*rstd; b1.y=(b1.y-mean)*rstd; b1.z=(b1.z-mean)*rstd; b1.w=(b1.w-mean)*rstd;
                b2.x=(b2.x-mean)*rstd; b2.y=(b2.y-mean)*rstd; b2.z=(b2.z-mean)*rstd; b2.w=(b2.w-mean)*rstd;
                b3.x=(b3.x-mean)*rstd; b3.y=(b3.y-mean)*rstd; b3.z=(b3.z-mean)*rstd; b3.w=(b3.w-mean)*rstd;
            }
            pb0 = make_uint4(packh2(b0.x, b2.x), packh2(b0.y, b2.y),
                             packh2(b0.z, b2.z), packh2(b0.w, b2.w));
            pb1 = make_uint4(packh2(b1.x, b3.x), packh2(b1.y, b3.y),
                             packh2(b1.z, b3.z), packh2(b1.w, b3.w));
        }
    };
    auto store_chunk = [&](int s) {
        __half2* As2 = (__half2*)sm + s * STAGE;
        __half2* Bs2 = As2 + 16 * H2STR;
        *(uint4*)&As2[kk * H2STR + mq]     = pa0;
        *(uint4*)&As2[kk * H2STR + mq + 4] = pa1;
        *(uint4*)&Bs2[kk * H2STR + mq]     = pb0;
        *(uint4*)&Bs2[kk * H2STR + mq + 4] = pb1;
    };

    load_chunk(0);
    store_chunk(0);
    __syncthreads();

    for (int t = 0; t < T; t++) {
        if (t + 1 < T) load_chunk((t + 1) << 5);
        const __half2* As2 = (const __half2*)sm + (t & 1) * STAGE;
        const __half2* Bs2 = As2 + 16 * H2STR;
#pragma unroll
        for (int ks = 0; ks < 2; ks++) {
            const int r0 = ks * 8;
            uint32_t af[4][4], bf[4][2];
#pragma unroll
            for (int i = 0; i < 4; i++) {
                int m = wm + i * 16 + gid;
                af[i][0] = *(uint32_t*)&As2[(r0 + tq) * H2STR + m];
                af[i][1] = *(uint32_t*)&As2[(r0 + tq) * H2STR + m + 8];
                af[i][2] = *(uint32_t*)&As2[(r0 + tq + 4) * H2STR + m];
                af[i][3] = *(uint32_t*)&As2[(r0 + tq + 4) * H2STR + m + 8];
            }
#pragma unroll
            for (int j = 0; j < 4; j++) {
                int p = wn + j * 8 + gid;
                bf[j][0] = *(uint32_t*)&Bs2[(r0 + tq) * H2STR + p];
                bf[j][1] = *(uint32_t*)&Bs2[(r0 + tq + 4) * H2STR + p];
            }
#pragma unroll
            for (int i = 0; i < 4; i++)
#pragma unroll
                for (int j = 0; j < 4; j++) mma_f16(acc[i][j], af[i], bf[j]);
        }
        if (t + 1 < T) {
            store_chunk((t + 1) & 1);
            __syncthreads();
        }
    }

    // ---- epilogue: two 64-row passes staged through smem ----
    float* sD = sm;
    float*   outf  = (MODE == 1 || MODE == 3) ? (float*)outv + (size_t)b * (size_t)M * P : nullptr;
    __half2* outh2 = (MODE == 2) ? (__half2*)outv + (size_t)b * (size_t)(M >> 1) * P : nullptr;
    const float* resb = (MODE == 1 || MODE == 3) ? res + (size_t)b * (size_t)M * P : nullptr;
    float osum = 0.f, osq = 0.f;

#pragma unroll
    for (int pass = 0; pass < 2; pass++) {
        __syncthreads();
        if (MODE == 1) {
            if ((wn >> 6) == pass) {
#pragma unroll
                for (int i = 0; i < 4; i++) {
                    int mrow = wm + i * 16 + gid;
#pragma unroll
                    for (int j = 0; j < 4; j++) {
                        int pc = (wn & 63) + j * 8 + 2 * tq;
                        sD[pc * KSTR + mrow]           = acc[i][j][0];
                        sD[(pc + 1) * KSTR + mrow]     = acc[i][j][1];
                        sD[pc * KSTR + mrow + 8]       = acc[i][j][2];
                        sD[(pc + 1) * KSTR + mrow + 8] = acc[i][j][3];
                    }
                }
            }
        } else {
            if ((wm >> 6) == pass) {
#pragma unroll
                for (int i = 0; i < 4; i++) {
                    int ml = (wm & 63) + i * 16 + gid;
#pragma unroll
                    for (int j = 0; j < 4; j++) {
                        int pc = wn + j * 8 + 2 * tq;
                        sD[ml * KSTR + pc]           = acc[i][j][0];
                        sD[ml * KSTR + pc + 1]       = acc[i][j][1];
                        sD[(ml + 8) * KSTR + pc]     = acc[i][j][2];
                        sD[(ml + 8) * KSTR + pc + 1] = acc[i][j][3];
                    }
                }
            }
        }
        __syncthreads();
        if (MODE == 1) {
            for (int l = tid; l < 64 * 32; l += 256) {
                int rl = l >> 5, cq = (l & 31) * 4;
                int p = n0 + pass * 64 + rl;
                if (p >= P) continue;
                float4 v = *(float4*)&sD[rl * KSTR + cq];
                float4 bb = *(const float4*)(bias + m0 + cq);
                v.x += bb.x; v.y += bb.y; v.z += bb.z; v.w += bb.w;
                size_t off = (size_t)p * M + m0 + cq;
                float4 rr = *(const float4*)(resb + off);
                v.x += rr.x; v.y += rr.y; v.z += rr.z; v.w += rr.w;
                *(float4*)(outf + off) = v;
                osum += v.x + v.y + v.z + v.w;
                osq  += v.x * v.x + v.y * v.y + v.z * v.z + v.w * v.w;
            }
        } else if (MODE == 2) {
            for (int l = tid; l < 32 * 32; l += 256) {
                int rp = l >> 5, cq = (l & 31) * 4;
                int m = m0 + pass * 64 + 2 * rp;
                int p = n0 + cq;
                if (p >= P) continue;
                float sc0 = bng[m] * rsqrtf(bnv[m] + EPSf);
                float sh0 = bnb[m] - bnm[m] * sc0 + bias[m] * sc0;
                float sc1 = bng[m + 1] * rsqrtf(bnv[m + 1] + EPSf);
                float sh1 = bnb[m + 1] - bnm[m + 1] * sc1 + bias[m + 1] * sc1;
                float4 v0 = *(float4*)&sD[(2 * rp) * KSTR + cq];
                float4 v1 = *(float4*)&sD[(2 * rp + 1) * KSTR + cq];
                v0.x = gelu_f(v0.x * sc0 + sh0); v0.y = gelu_f(v0.y * sc0 + sh0);
                v0.z = gelu_f(v0.z * sc0 + sh0); v0.w = gelu_f(v0.w * sc0 + sh0);
                v1.x = gelu_f(v1.x * sc1 + sh1); v1.y = gelu_f(v1.y * sc1 + sh1);
                v1.z = gelu_f(v1.z * sc1 + sh1); v1.w = gelu_f(v1.w * sc1 + sh1);
                uint4 u = make_uint4(packh2(v0.x, v1.x), packh2(v0.y, v1.y),
                                     packh2(v0.z, v1.z), packh2(v0.w, v1.w));
                *(uint4*)(outh2 + (size_t)(m >> 1) * P + p) = u;
            }
        } else {
            for (int l = tid; l < 64 * 32; l += 256) {
                int rl = l >> 5, cq = (l & 31) * 4;
                int m = m0 + pass * 64 + rl;
                int p = n0 + cq;
                if (p >= P) continue;
                float scale = bng[m] * rsqrtf(bnv[m] + EPSf);
                float shift = bnb[m] - bnm[m] * scale + bias[m] * scale;
                float4 v = *(float4*)&sD[rl * KSTR + cq];
                v.x = v.x * scale + shift; v.y = v.y * scale + shift;
                v.z = v.z * scale + shift; v.w = v.w * scale + shift;
                size_t off = (size_t)m * P + p;
                float4 rr = *(const float4*)(resb + off);
                v.x += rr.x; v.y += rr.y; v.z += rr.z; v.w += rr.w;
                *(float4*)(outf + off) = v;
            }
        }
    }

    if (MODE == 1) {
        __syncthreads();
        float* r1 = sm;
        float* r2 = sm + 256;
        r1[tid] = osum; r2[tid] = osq;
        __syncthreads();
        for (int st = 128; st > 0; st >>= 1) {
            if (tid < st) { r1[tid] += r1[tid + st]; r2[tid] += r2[tid + st]; }
            __syncthreads();
        }
        if (tid == 0)
            pstat[b * 14 + blockIdx.y * gridDim.x + blockIdx.x] = make_float2(r1[0], r2[0]);
    }
}

// ====================== merged QKV projection (fp32 B, fp16 out) ======================
__global__ void __launch_bounds__(256, 2) k_qkv(
    const __half2* __restrict__ wqh, const __half2* __restrict__ wkh,
    const __half2* __restrict__ wvh,
    const float* __restrict__ x1, const float* __restrict__ kvb,
    const float* __restrict__ bq, const float* __restrict__ bk,
    const float* __restrict__ bv, const float2* __restrict__ mr,
    __half* __restrict__ qh, __half* __restrict__ kh, __half* __restrict__ vh) {
    extern __shared__ float sm[];
    const int tid  = threadIdx.x;
    const int warp = tid >> 5, lane = tid & 31;
    const int gid = lane >> 2, tq = lane & 3;
    const int wm = (warp & 1) * 64;
    const int wn = (warp >> 1) * 32;
    const int b  = blockIdx.z;
    const int id = blockIdx.x;  // 0..21

    const __half2* Wh;
    const float* Xf;
    const float* bias;
    __half* outp;
    int P, m0, n0;
    bool ln = false;
    if (id < 14) {
        Wh = wqh; Xf = x1 + (size_t)b * Cn * Pn; bias = bq; outp = qh + (size_t)b * Pn * Cn;
        P = Pn; ln = true; m0 = (id / 7) * 128; n0 = (id % 7) * 128;
    } else if (id < 18) {
        int t = id - 14;
        Wh = wkh; Xf = kvb + (size_t)b * Cn * NKn; bias = bk; outp = kh + (size_t)b * NKn * Cn;
        P = NKn; m0 = (t >> 1) * 128; n0 = (t & 1) * 128;
    } else {
        int t = id - 18;
        Wh = wvh; Xf = kvb + (size_t)b * Cn * NKn; bias = bv; outp = vh + (size_t)b * NKn * Cn;
        P = NKn; m0 = (t >> 1) * 128; n0 = (t & 1) * 128;
    }
    float mean = 0.f, rstd = 1.f;
    if (ln) { float2 v = mr[b]; mean = v.x; rstd = v.y; }

    float acc[4][4][4];
#pragma unroll
    for (int i = 0; i < 4; i++)
#pragma unroll
        for (int j = 0; j < 4; j++)
#pragma unroll
            for (int r = 0; r < 4; r++) acc[i][j][r] = 0.f;

    const int kk = tid >> 4;
    const int mq = (tid & 15) * 8;
    uint4 pa0, pa1, pb0, pb1;
    const int T = Cn >> 5;  // 8

    auto load_chunk = [&](int kc0) {
        const uint4* wr = (const uint4*)(Wh + (size_t)((kc0 >> 1) + kk) * Cn + m0 + mq);
        pa0 = wr[0]; pa1 = wr[1];
        const float* xr0 = Xf + (size_t)(kc0 + 2 * kk) * P + n0 + mq;
        const float* xr1 = xr0 + P;
        float4 b0 = *(const float4*)xr0;
        float4 b1 = *(const float4*)(xr0 + 4);
        float4 b2 = *(const float4*)xr1;
        float4 b3 = *(const float4*)(xr1 + 4);
        if (ln) {
            b0.x=(b0.x-mean)*rstd; b0.y=(b0.y-mean)*rstd; b0.z=(b0.z-mean)*rstd; b0.w=(b0.w-mean)*rstd;
            b1.x=(b1.x-mean)*rstd; b1.y=(b1.y-mean)*rstd; b1.z=(b1.z-mean)*rstd; b1.w=(b1.w-mean)*rstd;
            b2.x=(b2.x-mean)*rstd; b2.y=(b2.y-mean)*rstd; b2.z=(b2.z-mean)*rstd; b2.w=(b2.w-mean)*rstd;
            b3.x=(b3.x-mean)*rstd; b3.y=(b3.y-mean)*rstd; b3.z=(b3.z-mean)*rstd; b3.w=(b3.w-mean)*rstd;
        }
        pb0 = make_uint4(packh2(b0.x, b2.x), packh2(b0.y, b2.y),
                         packh2(b0.z, b2.z), packh2(b0.w, b2.w));
        pb1 = make_uint4(packh2(b1.x, b3.x), packh2(b1.y, b3.y),
                         packh2(b1.z, b3.z), packh2(b1.w, b3.w));
    };
    auto store_chunk = [&](int s) {
        __half2* As2 = (__half2*)sm + s * STAGE;
        __half2* Bs2 = As2 + 16 * H2STR;
        *(uint4*)&As2[kk * H2STR + mq]     = pa0;
        *(uint4*)&As2[kk * H2STR + mq + 4] = pa1;
        *(uint4*)&Bs2[kk * H2STR + mq]     = pb0;
        *(uint4*)&Bs2[kk * H2STR + mq + 4] = pb1;
    };

    load_chunk(0);
    store_chunk(0);
    __syncthreads();

    for (int t = 0; t < T; t++) {
        if (t + 1 < T) load_chunk((t + 1) << 5);
        const __half2* As2 = (const __half2*)sm + (t & 1) * STAGE;
        const __half2* Bs2 = As2 + 16 * H2STR;
#pragma unroll
        for (int ks = 0; ks < 2; ks++) {
            const int r0 = ks * 8;
            uint32_t af[4][4], bf[4][2];
#pragma unroll
            for (int i = 0; i < 4; i++) {
                int m = wm + i * 16 + gid;
                af[i][0] = *(uint32_t*)&As2[(r0 + tq) * H2STR + m];
                af[i][1] = *(uint32_t*)&As2[(r0 + tq) * H2STR + m + 8];
                af[i][2] = *(uint32_t*)&As2[(r0 + tq + 4) * H2STR + m];
                af[i][3] = *(uint32_t*)&As2[(r0 + tq + 4) * H2STR + m + 8];
            }
#pragma unroll
            for (int j = 0; j < 4; j++) {
                int p = wn + j * 8 + gid;
                bf[j][0] = *(uint32_t*)&Bs2[(r0 + tq) * H2STR + p];
                bf[j][1] = *(uint32_t*)&Bs2[(r0 + tq + 4) * H2STR + p];
            }
#pragma unroll
            for (int i = 0; i < 4; i++)
#pragma unroll
                for (int j = 0; j < 4; j++) mma_f16(acc[i][j], af[i], bf[j]);
        }
        if (t + 1 < T) {
            store_chunk((t + 1) & 1);
            __syncthreads();
        }
    }

    // epilogue (MODE 0 style): half out[p*Cn + m]
    float* sD = sm;
#pragma unroll
    for (int pass = 0; pass < 2; pass++) {
        __syncthreads();
        if ((wn >> 6) == pass) {
#pragma unroll
            for (int i = 0; i < 4; i++) {
                int mrow = wm + i * 16 + gid;
#pragma unroll
                for (int j = 0; j < 4; j++) {
                    int pc = (wn & 63) + j * 8 + 2 * tq;
                    sD[pc * KSTR + mrow]           = acc[i][j][0];
                    sD[(pc + 1) * KSTR + mrow]     = acc[i][j][1];
                    sD[pc * KSTR + mrow + 8]       = acc[i][j][2];
                    sD[(pc + 1) * KSTR + mrow + 8] = acc[i][j][3];
                }
            }
        }
        __syncthreads();
        for (int l = tid; l < 64 * 32; l += 256) {
            int rl = l >> 5, cq = (l & 31) * 4;
            int p = n0 + pass * 64 + rl;
            if (p >= P) continue;
            float4 v = *(float4*)&sD[rl * KSTR + cq];
            float4 bb = *(const float4*)(bias + m0 + cq);
            v.x += bb.x; v.y += bb.y; v.z += bb.z; v.w += bb.w;
            __half2 h01 = __floats2half2_rn(v.x, v.y);
            __half2 h23 = __floats2half2_rn(v.z, v.w);
            uint2 u = make_uint2(*(uint32_t*)&h01, *(uint32_t*)&h23);
            *(uint2*)(outp + (size_t)p * Cn + m0 + cq) = u;
        }
    }
}

// ---------------- merged weight pack: all 6 weights -> fp16 k-paired ----------------
__global__ void k_wpack_all(
    const float* __restrict__ wq, const float* __restrict__ wk,
    const float* __restrict__ wv, const float* __restrict__ wo,
    const float* __restrict__ c1w, const float* __restrict__ c2w,
    __half2* __restrict__ oq, __half2* __restrict__ ok,
    __half2* __restrict__ ov, __half2* __restrict__ oo,
    __half2* __restrict__ oc1, __half2* __restrict__ oc2) {
    __shared__ float t[32][33];
    int id = blockIdx.x;
    const float* in;
    __half2* out;
    int M, K, tile;
    if (id < 256) {        // qkvo: 4 matrices x 64 tiles (256x256)
        int w = id >> 6; tile = id & 63;
        in  = (w == 0) ? wq : (w == 1) ? wk : (w == 2) ? wv : wo;
        out = (w == 0) ? oq : (w == 1) ? ok : (w == 2) ? ov : oo;
        M = Cn; K = Cn;
    } else if (id < 512) { // c1: 1024x256 -> 32x8 tiles
        tile = id - 256;
        in = c1w; out = oc1; M = CMn; K = Cn;
    } else {               // c2: 256x1024 -> 8x32 tiles
        tile = id - 512;
        in = c2w; out = oc2; M = Cn; K = CMn;
    }
    int ktiles = K >> 5;
    int m0 = (tile / ktiles) * 32, k0 = (tile % ktiles) * 32;
    int tx = threadIdx.x, ty = threadIdx.y;
#pragma unroll
    for (int q = 0; q < 32; q += 8)
        t[ty + q][tx] = in[(size_t)(m0 + ty + q) * K + k0 + tx];
    __syncthreads();
#pragma unroll
    for (int q = 0; q < 2; q++) {
        int kp = ty + q * 8;
        __half2 val = __floats2half2_rn(t[tx][2 * kp], t[tx][2 * kp + 1]);
        out[(size_t)((k0 >> 1) + kp) * M + m0 + tx] = val;
    }
}

// ------- fused LPU: dw3x3+bias+residual -> x1, plus KV downsample + LN1 partials -------
__global__ void __launch_bounds__(224) k_lpu_fused(
    const float* __restrict__ X, const float* __restrict__ w,
    const float* __restrict__ bias,
    const float* __restrict__ wkv, const float* __restrict__ bkv,
    float* __restrict__ x1, float* __restrict__ kv, float2* __restrict__ partl) {
    __shared__ float sp[900];
    __shared__ float so[784];
    __shared__ float r1[224], r2[224];
    int bc = blockIdx.x;
    int c  = bc & (Cn - 1);
    const float* xin = X + (size_t)bc * Pn;
    int tid = threadIdx.x;
    for (int i = tid; i < 900; i += 224) sp[i] = 0.f;
    float wc[9];
#pragma unroll
    for (int i = 0; i < 9; i++) wc[i] = w[c * 9 + i];
    float bsv = bias[c];
    __syncthreads();
    for (int i = tid; i < Pn; i += 224) sp[(i / 28 + 1) * 30 + (i % 28) + 1] = xin[i];
    __syncthreads();
    float lsum = 0.f, lsq = 0.f;
    if (tid < 196) {
        int px = tid % 28, sy = (tid / 28) * 4;
        float a[6][3];
#pragma unroll
        for (int dr = 0; dr < 6; dr++) {
            const float* r = sp + (sy + dr) * 30 + px;
            a[dr][0] = r[0]; a[dr][1] = r[1]; a[dr][2] = r[2];
        }
        float* ob = x1 + (size_t)bc * Pn;
#pragma unroll
        for (int i = 0; i < 4; i++) {
            float acc = bsv
                + wc[0] * a[i][0]     + wc[1] * a[i][1]     + wc[2] * a[i][2]
                + wc[3] * a[i + 1][0] + wc[4] * a[i + 1][1] + wc[5] * a[i + 1][2]
                + wc[6] * a[i + 2][0] + wc[7] * a[i + 2][1] + wc[8] * a[i + 2][2];
            float y = acc + a[i + 1][1];
            so[(sy + i) * 28 + px] = y;
            ob[(sy + i) * 28 + px] = y;
            lsum += y; lsq += y * y;
        }
    }
    r1[tid] = lsum; r2[tid] = lsq;
    __syncthreads();
    for (int st = 112; st >= 7; st >>= 1) {
        if (tid < st) { r1[tid] += r1[tid + st]; r2[tid] += r2[tid + st]; }
        __syncthreads();
    }
    if (tid == 0) {
        float s = 0.f, qv = 0.f;
#pragma unroll
        for (int i = 0; i < 7; i++) { s += r1[i]; qv += r2[i]; }
        partl[bc] = make_float2(s, qv);
    }
    if (tid < 196) {
        int oy = tid / HKn, ox = tid % HKn;
        float acc = bkv[c]
            + wkv[c * 4 + 0] * so[(2 * oy) * 28 + 2 * ox]
            + wkv[c * 4 + 1] * so[(2 * oy) * 28 + 2 * ox + 1]
            + wkv[c * 4 + 2] * so[(2 * oy + 1) * 28 + 2 * ox]
            + wkv[c * 4 + 3] * so[(2 * oy + 1) * 28 + 2 * ox + 1];
        kv[(size_t)bc * NKn + tid] = acc;
    }
}

// ---------------- LN finishers ----------------
__global__ void k_stats_fin_l(const float2* __restrict__ partl, float2* __restrict__ mr) {
    int b = blockIdx.x, t = threadIdx.x;
    __shared__ float r1[256], r2[256];
    float2 p = partl[b * Cn + t];
    r1[t] = p.x; r2[t] = p.y;
    __syncthreads();
    for (int st = 128; st > 0; st >>= 1) {
        if (t < st) { r1[t] += r1[t + st]; r2[t] += r2[t + st]; }
        __syncthreads();
    }
    if (t == 0) {
        const float n = (float)(Cn * Pn);
        float m  = r1[0] / n;
        float vv = r2[0] / n - m * m;
        mr[b] = make_float2(m, rsqrtf(vv + EPSf));
    }
}

__global__ void k_stats_fin_o(const float2* __restrict__ parto, float2* __restrict__ mr) {
    int b = blockIdx.x, t = threadIdx.x;  // 32 threads
    float2 p = (t < 14) ? parto[b * 14 + t] : make_float2(0.f, 0.f);
#pragma unroll
    for (int o = 16; o >= 1; o >>= 1) {
        p.x += __shfl_down_sync(0xffffffffu, p.x, o);
        p.y += __shfl_down_sync(0xffffffffu, p.y, o);
    }
    if (t == 0) {
        const float n = (float)(Cn * Pn);
        float m  = p.x / n;
        float vv = p.y / n - m * m;
        mr[b] = make_float2(m, rsqrtf(vv + EPSf));
    }
}

// ---------------- dw2: channel-pair fp16 in, BN+GELU, half2-paired output ----------------
__global__ void __launch_bounds__(224) k_dw2pair(
    const __half2* __restrict__ X2, const float* __restrict__ w,
    const float* __restrict__ bias,
    const float* __restrict__ bng, const float* __restrict__ bnb,
    const float* __restrict__ bnm, const float* __restrict__ bnv,
    __half2* __restrict__ out2) {
    __shared__ float sp0[900], sp1[900];
    int bc = blockIdx.x;
    int b  = bc >> 9;
    int mp = bc & 511;
    int c0 = 2 * mp;
    const __half2* x0 = X2 + ((size_t)b * (CMn / 2) + mp) * Pn;
    int tid = threadIdx.x;
    for (int i = tid; i < 900; i += 224) { sp0[i] = 0.f; sp1[i] = 0.f; }
    float wa[9], wb[9];
#pragma unroll
    for (int i = 0; i < 9; i++) { wa[i] = w[c0 * 9 + i]; wb[i] = w[(c0 + 1) * 9 + i]; }
    float bs0 = bias[c0], bs1 = bias[c0 + 1];
    float sc0 = bng[c0] * rsqrtf(bnv[c0] + EPSf);
    float sh0 = bnb[c0] - bnm[c0] * sc0;
    float sc1 = bng[c0 + 1] * rsqrtf(bnv[c0 + 1] + EPSf);
    float sh1 = bnb[c0 + 1] - bnm[c0 + 1] * sc1;
    __syncthreads();
    for (int i = tid; i < Pn; i += 224) {
        int o = (i / 28 + 1) * 30 + (i % 28) + 1;
        float2 f = __half22float2(x0[i]);
        sp0[o] = f.x;
        sp1[o] = f.y;
    }
    __syncthreads();
    if (tid < 196) {
        int px = tid % 28, sy = (tid / 28) * 4;
        float a0[6][3], a1[6][3];
#pragma unroll
        for (int dr = 0; dr < 6; dr++) {
            int base = (sy + dr) * 30 + px;
            a0[dr][0] = sp0[base]; a0[dr][1] = sp0[base + 1]; a0[dr][2] = sp0[base + 2];
            a1[dr][0] = sp1[base]; a1[dr][1] = sp1[base + 1]; a1[dr][2] = sp1[base + 2];
        }
        __half2* ob = out2 + ((size_t)b * (CMn / 2) + mp) * Pn;
#pragma unroll
        for (int i = 0; i < 4; i++) {
            float acc0 = bs0
                + wa[0] * a0[i][0]     + wa[1] * a0[i][1]     + wa[2] * a0[i][2]
                + wa[3] * a0[i + 1][0] + wa[4] * a0[i + 1][1] + wa[5] * a0[i + 1][2]
                + wa[6] * a0[i + 2][0] + wa[7] * a0[i + 2][1] + wa[8] * a0[i + 2][2];
            float acc1 = bs1
                + wb[0] * a1[i][0]     + wb[1] * a1[i][1]     + wb[2] * a1[i][2]
                + wb[3] * a1[i + 1][0] + wb[4] * a1[i + 1][1] + wb[5] * a1[i + 1][2]
                + wb[6] * a1[i + 2][0] + wb[7] * a1[i + 2][1] + wb[8] * a1[i + 2][2];
            float y0 = gelu_f(acc0 * sc0 + sh0);
            float y1 = gelu_f(acc1 * sc1 + sh1);
            ob[(sy + i) * 28 + px] = __floats2half2_rn(y0, y1);
        }
    }
}

// ================= fp16 mma attention =================
#define KP_STR 20
#define VP_STR 40

__global__ void __launch_bounds__(224, 1) k_attn_mma(
    const __half* __restrict__ q, const __half* __restrict__ k,
    const __half* __restrict__ v, const float* __restrict__ pos,
    __half2* __restrict__ outT2) {
    __shared__ __half2 Kp[208 * KP_STR];
    __shared__ __half2 Vp[104 * VP_STR];
    const int tid = threadIdx.x;
    const int warp = tid >> 5, lane = tid & 31;
    const int gid = lane >> 2, tq = lane & 3;
    const int qt = blockIdx.x;
    const int h  = blockIdx.y;
    const int b  = blockIdx.z;
    const int hoff = h * DKn;

    for (int idx = tid; idx < 208 * 16; idx += 224) {
        int key = idx >> 4, e = idx & 15;
        __half2 val = __floats2half2_rn(0.f, 0.f);
        if (key < NKn)
            val = *(const __half2*)(k + ((size_t)(b * NKn + key)) * Cn + hoff + 2 * e);
        Kp[key * KP_STR + e] = val;
    }
    for (int idx = tid; idx < 104 * 32; idx += 224) {
        int kp = idx >> 5, dv = idx & 31;
        int k0 = 2 * kp, k1 = 2 * kp + 1;
        __half f0 = (k0 < NKn) ? v[((size_t)(b * NKn + k0)) * Cn + hoff + dv] : __float2half(0.f);
        __half f1 = (k1 < NKn) ? v[((size_t)(b * NKn + k1)) * Cn + hoff + dv] : __float2half(0.f);
        Vp[kp * VP_STR + dv] = __halves2half2(f0, f1);
    }
    __syncthreads();

    const int iA = qt * 112 + warp * 16 + gid;

    uint32_t aq[2][4];
    {
        const __half* q0 = q + ((size_t)(b * Pn + iA)) * Cn + hoff;
        const __half* q1 = q0 + 8 * Cn;
#pragma unroll
        for (int kt = 0; kt < 2; kt++) {
            aq[kt][0] = *(const uint32_t*)(q0 + 16 * kt + 2 * tq);
            aq[kt][1] = *(const uint32_t*)(q1 + 16 * kt + 2 * tq);
            aq[kt][2] = *(const uint32_t*)(q0 + 16 * kt + 8 + 2 * tq);
            aq[kt][3] = *(const uint32_t*)(q1 + 16 * kt + 8 + 2 * tq);
        }
    }

    float accS[26][4];
#pragma unroll
    for (int jt = 0; jt < 26; jt++)
#pragma unroll
        for (int r = 0; r < 4; r++) accS[jt][r] = 0.f;
#pragma unroll
    for (int jt = 0; jt < 26; jt++) {
#pragma unroll
        for (int kt = 0; kt < 2; kt++) {
            uint32_t bf[2];
            bf[0] = *(uint32_t*)&Kp[(8 * jt + gid) * KP_STR + 8 * kt + tq];
            bf[1] = *(uint32_t*)&Kp[(8 * jt + gid) * KP_STR + 8 * kt + 4 + tq];
            mma_f16(accS[jt], aq[kt], bf);
        }
    }

    const float scale = 0.17677669529663687f;
    const float* posA = pos + ((size_t)(h * Pn + iA)) * NKn;
    const float* posB = posA + 8 * NKn;
    float mA = -1e30f, mB = -1e30f;
#pragma unroll
    for (int jt = 0; jt < 26; jt++) {
        int col = 8 * jt + 2 * tq;
        if (col < NKn) {
            float2 pA = *(const float2*)(posA + col);
            float2 pB = *(const float2*)(posB + col);
            accS[jt][0] = accS[jt][0] * scale + pA.x;
            accS[jt][1] = accS[jt][1] * scale + pA.y;
            accS[jt][2] = accS[jt][2] * scale + pB.x;
            accS[jt][3] = accS[jt][3] * scale + pB.y;
            mA = fmaxf(mA, fmaxf(accS[jt][0], accS[jt][1]));
            mB = fmaxf(mB, fmaxf(accS[jt][2], accS[jt][3]));
        } else {
            accS[jt][0] = -1e30f; accS[jt][1] = -1e30f;
            accS[jt][2] = -1e30f; accS[jt][3] = -1e30f;
        }
    }
    mA = fmaxf(mA, __shfl_xor_sync(0xffffffffu, mA, 1));
    mA = fmaxf(mA, __shfl_xor_sync(0xffffffffu, mA, 2));
    mB = fmaxf(mB, __shfl_xor_sync(0xffffffffu, mB, 1));
    mB = fmaxf(mB, __shfl_xor_sync(0xffffffffu, mB, 2));
    float lA = 0.f, lB = 0.f;
#pragma unroll
    for (int jt = 0; jt < 26; jt++) {
        accS[jt][0] = __expf(accS[jt][0] - mA);
        accS[jt][1] = __expf(accS[jt][1] - mA);
        accS[jt][2] = __expf(accS[jt][2] - mB);
        accS[jt][3] = __expf(accS[jt][3] - mB);
        lA += accS[jt][0] + accS[jt][1];
        lB += accS[jt][2] + accS[jt][3];
    }
    lA += __shfl_xor_sync(0xffffffffu, lA, 1);
    lA += __shfl_xor_sync(0xffffffffu, lA, 2);
    lB += __shfl_xor_sync(0xffffffffu, lB, 1);
    lB += __shfl_xor_sync(0xffffffffu, lB, 2);

    float accO[4][4];
#pragma unroll
    for (int nt = 0; nt < 4; nt++)
#pragma unroll
        for (int r = 0; r < 4; r++) accO[nt][r] = 0.f;
#pragma unroll
    for (int kt = 0; kt < 13; kt++) {
        uint32_t pa[4];
        pa[0] = packh2(accS[2 * kt][0],     accS[2 * kt][1]);
        pa[1] = packh2(accS[2 * kt][2],     accS[2 * kt][3]);
        pa[2] = packh2(accS[2 * kt + 1][0], accS[2 * kt + 1][1]);
        pa[3] = packh2(accS[2 * kt + 1][2], accS[2 * kt + 1][3]);
#pragma unroll
        for (int nt = 0; nt < 4; nt++) {
            uint32_t bf[2];
            bf[0] = *(uint32_t*)&Vp[(8 * kt + tq) * VP_STR + 8 * nt + gid];
            bf[1] = *(uint32_t*)&Vp[(8 * kt + 4 + tq) * VP_STR + 8 * nt + gid];
            mma_f16(accO[nt], pa, bf);
        }
    }
    float invA = 1.f / lA, invB = 1.f / lB;
    __half2* ob = outT2 + ((size_t)(b * (Cn / 2) + (hoff >> 1))) * Pn;
#pragma unroll
    for (int nt = 0; nt < 4; nt++) {
        int dvp = 4 * nt + tq;
        ob[(size_t)dvp * Pn + iA]     = __floats2half2_rn(accO[nt][0] * invA, accO[nt][1] * invA);
        ob[(size_t)dvp * Pn + iA + 8] = __floats2half2_rn(accO[nt][2] * invB, accO[nt][3] * invB);
    }
}

// ---------------- host launch ----------------
static void* sym_addr(const void* symbol) {
    void* p = nullptr;
    cudaGetSymbolAddress(&p, symbol);
    return p;
}

extern "C" void kernel_launch(void* const* d_in, const int* in_sizes, int n_in,
                              void* d_out, int out_size) {
    const float* x     = (const float*)d_in[0];
    const float* lpu_w = (const float*)d_in[1];
    const float* lpu_b = (const float*)d_in[2];
    const float* dw_w  = (const float*)d_in[3];
    const float* dw_b  = (const float*)d_in[4];
    const float* wq    = (const float*)d_in[5];
    const float* bq    = (const float*)d_in[6];
    const float* wk    = (const float*)d_in[7];
    const float* bk    = (const float*)d_in[8];
    const float* wv    = (const float*)d_in[9];
    const float* bv    = (const float*)d_in[10];
    const float* wo    = (const float*)d_in[11];
    const float* bo    = (const float*)d_in[12];
    const float* pos_b = (const float*)d_in[13];
    const float* c1_w  = (const float*)d_in[14];
    const float* c1_b  = (const float*)d_in[15];
    const float* bn1_g = (const float*)d_in[16];
    const float* bn1_b = (const float*)d_in[17];
    const float* bn1_m = (const float*)d_in[18];
    const float* bn1_v = (const float*)d_in[19];
    const float* dw2_w = (const float*)d_in[20];
    const float* dw2_b = (const float*)d_in[21];
    const float* bn2_g = (const float*)d_in[22];
    const float* bn2_b = (const float*)d_in[23];
    const float* bn2_m = (const float*)d_in[24];
    const float* bn2_v = (const float*)d_in[25];
    const float* c2_w  = (const float*)d_in[26];
    const float* c2_b  = (const float*)d_in[27];
    const float* bn3_g = (const float*)d_in[28];
    const float* bn3_b = (const float*)d_in[29];
    const float* bn3_m = (const float*)d_in[30];
    const float* bn3_v = (const float*)d_in[31];
    float* out = (float*)d_out;

    float*   x1    = (float*)sym_addr(g_x1);
    float*   kvb   = (float*)sym_addr(g_kv);
    float*   x2    = (float*)sym_addr(g_x2);
    __half*  qh    = (__half*)sym_addr(g_qh);
    __half*  kh    = (__half*)sym_addr(g_kh);
    __half*  vh    = (__half*)sym_addr(g_vh);
    __half2* attTh = (__half2*)sym_addr(g_attTh);
    __half2* t1h   = (__half2*)sym_addr(g_t1h);
    __half2* t2h   = (__half2*)sym_addr(g_t2h);
    __half2* wqh   = (__half2*)sym_addr(g_wqh);
    __half2* wkh   = (__half2*)sym_addr(g_wkh);
    __half2* wvh   = (__half2*)sym_addr(g_wvh);
    __half2* woh   = (__half2*)sym_addr(g_woh);
    __half2* c1h   = (__half2*)sym_addr(g_c1h);
    __half2* c2h   = (__half2*)sym_addr(g_c2h);
    float2*  partl = (float2*)sym_addr(g_partl);
    float2*  parto = (float2*)sym_addr(g_parto);
    float2*  mr    = (float2*)sym_addr(g_mr);

    dim3 tb(32, 8);
    // 1. all weight packs in one launch
    k_wpack_all<<<768, tb>>>(wq, wk, wv, wo, c1_w, c2_w, wqh, wkh, wvh, woh, c1h, c2h);
    // 2. fused LPU (+KV downsample +LN1 partials)
    k_lpu_fused<<<Bn * Cn, 224>>>(x, lpu_w, lpu_b, dw_w, dw_b, x1, kvb, partl);
    k_stats_fin_l<<<Bn, 256>>>(partl, mr);
    // 3. merged Q/K/V projections (one launch, 22 blocks/batch)
    k_qkv<<<dim3(22, 1, Bn), 256, SMEM_MMA>>>(
        wqh, wkh, wvh, x1, kvb, bq, bk, bv, mr, qh, kh, vh);
    // 4. attention -> attTh
    k_attn_mma<<<dim3(7, NH, Bn), 224>>>(qh, kh, vh, pos_b, attTh);
    // 5. O projection + flat residual -> x2 (+LN2 partials)
    k_mma<1, false, true><<<dim3(7, 2, Bn), 256, SMEM_MMA>>>(
        woh, attTh, bo, nullptr, nullptr, nullptr, nullptr, nullptr, x1, parto, x2, Cn, Cn, Pn);
    k_stats_fin_o<<<Bn, 32>>>(parto, mr);
    // 6. c1 + BN1 + GELU (LN fused) -> t1h fp16 channel-paired
    k_mma<2, true, false><<<dim3(7, 8, Bn), 256, SMEM_MMA>>>(
        c1h, x2, c1_b, bn1_g, bn1_b, bn1_m, bn1_v, mr, nullptr, nullptr, t1h, CMn, Cn, Pn);
    // 7. dw2 + BN2 + GELU -> t2h
    k_dw2pair<<<Bn * (CMn / 2), 224>>>(t1h, dw2_w, dw2_b, bn2_g, bn2_b, bn2_m, bn2_v, t2h);
    // 8. c2 + BN3 + channel-major residual -> d_out
    k_mma<3, false, true><<<dim3(7, 2, Bn), 256, SMEM_MMA>>>(
        c2h, t2h, c2_b, bn3_g, bn3_b, bn3_m, bn3_v, nullptr, x2, nullptr, out, Cn, CMn, Pn);
}